// round 9
// baseline (speedup 1.0000x reference)
#include <cuda_runtime.h>
#include <cuda_bf16.h>
#include <cstdint>
#include <cstddef>

#define DI __device__ __forceinline__

// ---------------- problem dims ----------------
constexpr int L_ = 12, D_ = 768, H_ = 12, FF_ = 3072;
constexpr int B_ = 64, NP_ = 196, NT_ = 197, NC_ = 100, T_ = 10;
constexpr int M1 = B_ * NT_;        // 12608 token rows
constexpr int NKMAX = 217;          // 197 + 20 (e-prompt layers)
constexpr int MKMAX = B_ * NKMAX;   // 13888
constexpr int KSTR = 225;           // attention smem row stride (conflict-free)

// ---------------- device scratch (static, no runtime alloc) ----------------
__device__ float g_x   [(size_t)M1 * D_];
__device__ float g_x0  [(size_t)M1 * D_];
__device__ float g_ptmp[(size_t)B_ * NP_ * D_];
__device__ float g_qkvf[(size_t)M1 * 3 * D_];
__device__ float g_qf  [(size_t)M1 * D_];
__device__ float g_kf  [(size_t)MKMAX * D_];
__device__ float g_vf  [(size_t)MKMAX * D_];
__device__ int   g_idx [B_];
// hi/lo activation pairs
__device__ __nv_bfloat16 g_h_hi [(size_t)M1 * D_];
__device__ __nv_bfloat16 g_h_lo [(size_t)M1 * D_];
__device__ __nv_bfloat16 g_at_hi[(size_t)M1 * D_];
__device__ __nv_bfloat16 g_at_lo[(size_t)M1 * D_];
__device__ __nv_bfloat16 g_ff_hi[(size_t)M1 * FF_];
__device__ __nv_bfloat16 g_ff_lo[(size_t)M1 * FF_];
__device__ __nv_bfloat16 g_xk_hi[(size_t)MKMAX * D_];
__device__ __nv_bfloat16 g_xk_lo[(size_t)MKMAX * D_];
__device__ __nv_bfloat16 g_xv_hi[(size_t)MKMAX * D_];
__device__ __nv_bfloat16 g_xv_lo[(size_t)MKMAX * D_];
__device__ __nv_bfloat16 g_p_hi [(size_t)B_ * NP_ * D_];
__device__ __nv_bfloat16 g_p_lo [(size_t)B_ * NP_ * D_];
// hi/lo weight pairs
__device__ __nv_bfloat16 g_wpatch_hi[(size_t)D_ * D_];
__device__ __nv_bfloat16 g_wpatch_lo[(size_t)D_ * D_];
__device__ __nv_bfloat16 g_wqkv_hi  [(size_t)L_ * 3 * D_ * D_];
__device__ __nv_bfloat16 g_wqkv_lo  [(size_t)L_ * 3 * D_ * D_];
__device__ __nv_bfloat16 g_wproj_hi [(size_t)L_ * D_ * D_];
__device__ __nv_bfloat16 g_wproj_lo [(size_t)L_ * D_ * D_];
__device__ __nv_bfloat16 g_wfc1_hi  [(size_t)L_ * FF_ * D_];
__device__ __nv_bfloat16 g_wfc1_lo  [(size_t)L_ * FF_ * D_];
__device__ __nv_bfloat16 g_wfc2_hi  [(size_t)L_ * D_ * FF_];
__device__ __nv_bfloat16 g_wfc2_lo  [(size_t)L_ * D_ * FF_];

// ---------------- PTX helpers ----------------
DI uint32_t sptr(const void* p) { return (uint32_t)__cvta_generic_to_shared(p); }

DI void cp16(void* s, const void* g, bool pred) {
    asm volatile("cp.async.cg.shared.global [%0], [%1], 16, %2;\n"
                 :: "r"(sptr(s)), "l"(g), "r"(pred ? 16 : 0));
}
DI void cpcommit() { asm volatile("cp.async.commit_group;\n" ::); }
DI void cpwait0()  { asm volatile("cp.async.wait_group 0;\n" ::); }

DI void ldm4(uint32_t* r, const void* p) {
    asm volatile("ldmatrix.sync.aligned.m8n8.x4.shared.b16 {%0,%1,%2,%3}, [%4];\n"
                 : "=r"(r[0]), "=r"(r[1]), "=r"(r[2]), "=r"(r[3])
                 : "r"(sptr(p)) : "memory");
}
DI void mma_bf16(float* d, const uint32_t* a, const uint32_t* b) {
    asm volatile("mma.sync.aligned.m16n8k16.row.col.f32.bf16.bf16.f32 "
                 "{%0,%1,%2,%3}, {%4,%5,%6,%7}, {%8,%9}, {%0,%1,%2,%3};\n"
                 : "+f"(d[0]), "+f"(d[1]), "+f"(d[2]), "+f"(d[3])
                 : "r"(a[0]), "r"(a[1]), "r"(a[2]), "r"(a[3]),
                   "r"(b[0]), "r"(b[1]));
}
DI float gelu_f(float v) { return 0.5f * v * (1.f + erff(v * 0.70710678118654752f)); }
DI void split_f(float v, __nv_bfloat16& hi, __nv_bfloat16& lo) {
    hi = __float2bfloat16(v);
    lo = __float2bfloat16(v - __bfloat162float(hi));
}

// ---------------- split-bf16 TN GEMM: C[M,N] = A[M,K] * B[N,K]^T ----------------
// A = Ahi + Alo, B = Bhi + Blo (bf16 pairs, K-contiguous).
// acc = Ahi*Bhi + Ahi*Blo + Alo*Bhi (fp32 accumulate) -> ~fp32 precision.
// EPI 0: Cf = acc + bias                        (fp32 out)
// EPI 1: (Cb_hi,Cb_lo) = split(gelu(acc+bias))  (bf16-pair out)
// EPI 2: Cf += acc + bias                       (fp32 residual accumulate)
constexpr int EPI_F32 = 0, EPI_GELU = 1, EPI_RES = 2;
constexpr int AS = 40;                    // smem row stride (32+8) -> conflict-free LDSM
constexpr int TILE_ELE = 128 * AS;        // 5120 bf16 per tile
constexpr int SMEM3 = 8 * TILE_ELE * 2;   // 81920 bytes

DI void load3(const __nv_bfloat16* __restrict__ Ahi, const __nv_bfloat16* __restrict__ Alo,
              const __nv_bfloat16* __restrict__ Bhi, const __nv_bfloat16* __restrict__ Blo,
              __nv_bfloat16* sAh, __nv_bfloat16* sAl,
              __nv_bfloat16* sBh, __nv_bfloat16* sBl,
              int tid, int m0, int n0, int k0, int M, int K)
{
    #pragma unroll
    for (int i = 0; i < 2; i++) {
        int idx = tid + i * 256;          // 512 chunks: 128 rows x 4 x 16B
        int r = idx >> 2, c = (idx & 3) << 3;
        int gr = m0 + r;
        bool p = gr < M;
        size_t aoff = (size_t)(p ? gr : 0) * K + k0 + c;
        size_t boff = (size_t)(n0 + r) * K + k0 + c;
        cp16(sAh + r * AS + c, Ahi + aoff, p);
        cp16(sAl + r * AS + c, Alo + aoff, p);
        cp16(sBh + r * AS + c, Bhi + boff, true);
        cp16(sBl + r * AS + c, Blo + boff, true);
    }
}

template<int EPI>
__global__ __launch_bounds__(256, 1) void gemm3_k(
    const __nv_bfloat16* __restrict__ Ahi, const __nv_bfloat16* __restrict__ Alo,
    const __nv_bfloat16* __restrict__ Bhi, const __nv_bfloat16* __restrict__ Blo,
    const float* __restrict__ bias, float* __restrict__ Cf,
    __nv_bfloat16* __restrict__ Cb_hi, __nv_bfloat16* __restrict__ Cb_lo,
    int M, int N, int K)
{
    extern __shared__ __nv_bfloat16 smem[];
    __nv_bfloat16* sAh = smem;
    __nv_bfloat16* sAl = smem + 2 * TILE_ELE;
    __nv_bfloat16* sBh = smem + 4 * TILE_ELE;
    __nv_bfloat16* sBl = smem + 6 * TILE_ELE;

    const int tid = threadIdx.x;
    const int m0 = blockIdx.y * 128, n0 = blockIdx.x * 128;
    const int wid = tid >> 5, lane = tid & 31;
    const int wm = wid >> 2, wn = wid & 3;          // 2x4 warps, warp tile 64x32

    float acc[4][4][4];
    #pragma unroll
    for (int a = 0; a < 4; a++)
        #pragma unroll
        for (int b = 0; b < 4; b++)
            #pragma unroll
            for (int c = 0; c < 4; c++) acc[a][b][c] = 0.f;

    const int nIt = K >> 5;

    load3(Ahi, Alo, Bhi, Blo, sAh, sAl, sBh, sBl, tid, m0, n0, 0, M, K);
    cpcommit();
    cpwait0();
    __syncthreads();

    for (int it = 0; it < nIt; ++it) {
        const int buf = it & 1;
        const int nb = buf ^ 1;
        if (it + 1 < nIt) {
            load3(Ahi, Alo, Bhi, Blo,
                  sAh + nb * TILE_ELE, sAl + nb * TILE_ELE,
                  sBh + nb * TILE_ELE, sBl + nb * TILE_ELE,
                  tid, m0, n0, (it + 1) << 5, M, K);
            cpcommit();
        }
        const int bo = buf * TILE_ELE;
        #pragma unroll
        for (int kk = 0; kk < 2; ++kk) {
            const int kcol = kk << 4;
            uint32_t ah[4][4], al[4][4], bh[4][2], bl[4][2];
            #pragma unroll
            for (int mt = 0; mt < 4; ++mt) {
                int row = wm * 64 + mt * 16 + (lane & 15);
                int col = kcol + ((lane >> 4) << 3);
                ldm4(ah[mt], &sAh[bo + row * AS + col]);
                ldm4(al[mt], &sAl[bo + row * AS + col]);
            }
            #pragma unroll
            for (int j = 0; j < 2; ++j) {
                int row = wn * 32 + j * 16 + (lane & 7) + ((lane >> 4) << 3);
                int col = kcol + (((lane >> 3) & 1) << 3);
                uint32_t t[4];
                ldm4(t, &sBh[bo + row * AS + col]);
                bh[2 * j][0] = t[0]; bh[2 * j][1] = t[1];
                bh[2 * j + 1][0] = t[2]; bh[2 * j + 1][1] = t[3];
                ldm4(t, &sBl[bo + row * AS + col]);
                bl[2 * j][0] = t[0]; bl[2 * j][1] = t[1];
                bl[2 * j + 1][0] = t[2]; bl[2 * j + 1][1] = t[3];
            }
            #pragma unroll
            for (int mt = 0; mt < 4; ++mt)
                #pragma unroll
                for (int nt = 0; nt < 4; ++nt) {
                    mma_bf16(acc[mt][nt], ah[mt], bh[nt]);
                    mma_bf16(acc[mt][nt], ah[mt], bl[nt]);
                    mma_bf16(acc[mt][nt], al[mt], bh[nt]);
                }
        }
        if (it + 1 < nIt) cpwait0();
        __syncthreads();
    }

    // epilogue
    const int g = lane >> 2, tg = lane & 3;
    #pragma unroll
    for (int mt = 0; mt < 4; ++mt) {
        #pragma unroll
        for (int nt = 0; nt < 4; ++nt) {
            const int col = n0 + wn * 32 + nt * 8 + tg * 2;
            #pragma unroll
            for (int hh = 0; hh < 2; ++hh) {
                const int r = m0 + wm * 64 + mt * 16 + g + hh * 8;
                if (r < M) {
                    float v0 = acc[mt][nt][2 * hh + 0] + bias[col];
                    float v1 = acc[mt][nt][2 * hh + 1] + bias[col + 1];
                    size_t off = (size_t)r * N + col;
                    if (EPI == EPI_F32) {
                        float2 o; o.x = v0; o.y = v1;
                        *reinterpret_cast<float2*>(Cf + off) = o;
                    } else if (EPI == EPI_GELU) {
                        float g0 = gelu_f(v0), g1 = gelu_f(v1);
                        __nv_bfloat16 h0, l0, h1, l1;
                        split_f(g0, h0, l0); split_f(g1, h1, l1);
                        __nv_bfloat162 oh; oh.x = h0; oh.y = h1;
                        __nv_bfloat162 ol; ol.x = l0; ol.y = l1;
                        *reinterpret_cast<__nv_bfloat162*>(Cb_hi + off) = oh;
                        *reinterpret_cast<__nv_bfloat162*>(Cb_lo + off) = ol;
                    } else {
                        float2 o = *reinterpret_cast<float2*>(Cf + off);
                        o.x += v0; o.y += v1;
                        *reinterpret_cast<float2*>(Cf + off) = o;
                    }
                }
            }
        }
    }
}

// ---------------- attention (fp32 SIMT, block per (b,h)), outputs hi/lo ----------------
__global__ __launch_bounds__(256) void attn_k(
    const float* __restrict__ qp, long long qbs, int qrs,
    const float* __restrict__ kp, long long kbs, int krs,
    const float* __restrict__ vp, long long vbs, int vrs,
    __nv_bfloat16* __restrict__ out_hi, __nv_bfloat16* __restrict__ out_lo, int nk)
{
    extern __shared__ float skvf[];
    float* Ks = skvf;                 // [64][KSTR] transposed
    float* Vs = skvf + 64 * KSTR;
    const int h = blockIdx.x, b = blockIdx.y;
    const int tid = threadIdx.x, lane = tid & 31, w = tid >> 5;

    const float* kb = kp + (long long)b * kbs + h * 64;
    const float* vb = vp + (long long)b * vbs + h * 64;
    for (int i = tid; i < nk * 64; i += 256) {
        int j = i >> 6, d = i & 63;
        Ks[d * KSTR + j] = kb[(long long)j * krs + d];
        Vs[d * KSTR + j] = vb[(long long)j * vrs + d];
    }
    __syncthreads();

    const int cnt = (nk > lane) ? ((nk - lane + 31) >> 5) : 0;   // keys for this lane (<=7)

    for (int qi = w; qi < NT_; qi += 8) {
        const float* qrow = qp + (long long)b * qbs + (long long)qi * qrs + h * 64;
        float qv[64];
        #pragma unroll
        for (int d = 0; d < 64; ++d) qv[d] = qrow[d];

        float s[7];
        #pragma unroll
        for (int jj = 0; jj < 7; ++jj) s[jj] = 0.f;
        #pragma unroll
        for (int d = 0; d < 64; ++d) {
            const float qd = qv[d];
            #pragma unroll
            for (int jj = 0; jj < 7; ++jj)
                if (jj < cnt) s[jj] += qd * Ks[d * KSTR + lane + jj * 32];
        }
        float m = -1e30f;
        #pragma unroll
        for (int jj = 0; jj < 7; ++jj)
            if (jj < cnt) { s[jj] *= 0.125f; m = fmaxf(m, s[jj]); }
        #pragma unroll
        for (int o = 16; o; o >>= 1) m = fmaxf(m, __shfl_xor_sync(0xffffffffu, m, o));
        float sum = 0.f;
        #pragma unroll
        for (int jj = 0; jj < 7; ++jj) {
            s[jj] = (jj < cnt) ? __expf(s[jj] - m) : 0.f;
            sum += s[jj];
        }
        #pragma unroll
        for (int o = 16; o; o >>= 1) sum += __shfl_xor_sync(0xffffffffu, sum, o);
        const float inv = 1.f / sum;
        #pragma unroll
        for (int jj = 0; jj < 7; ++jj) s[jj] *= inv;

        float o0 = 0.f, o1 = 0.f;
        #pragma unroll
        for (int d = 0; d < 64; ++d) {
            float a = 0.f;
            #pragma unroll
            for (int jj = 0; jj < 7; ++jj)
                if (jj < cnt) a += s[jj] * Vs[d * KSTR + lane + jj * 32];
            #pragma unroll
            for (int o = 16; o; o >>= 1) a += __shfl_xor_sync(0xffffffffu, a, o);
            if (lane == (d & 31)) { if (d < 32) o0 = a; else o1 = a; }
        }
        size_t base = ((size_t)(b * NT_ + qi)) * D_ + h * 64;
        __nv_bfloat16 h0, l0, h1, l1;
        split_f(o0, h0, l0); split_f(o1, h1, l1);
        out_hi[base + lane] = h0;      out_lo[base + lane] = l0;
        out_hi[base + lane + 32] = h1; out_lo[base + lane + 32] = l1;
    }
}

// ---------------- layernorm (block per row) -> bf16 hi/lo ----------------
__global__ __launch_bounds__(256) void ln_k(const float* __restrict__ x,
    const float* __restrict__ s, const float* __restrict__ b,
    __nv_bfloat16* __restrict__ out_hi, __nv_bfloat16* __restrict__ out_lo)
{
    const int row = blockIdx.x, tid = threadIdx.x;
    const float* xr = x + (size_t)row * D_;
    float v[3], sum = 0.f, sq = 0.f;
    #pragma unroll
    for (int i = 0; i < 3; i++) { v[i] = xr[tid + i * 256]; sum += v[i]; sq += v[i] * v[i]; }
    __shared__ float rs[8], rq[8];
    #pragma unroll
    for (int o = 16; o; o >>= 1) {
        sum += __shfl_xor_sync(0xffffffffu, sum, o);
        sq  += __shfl_xor_sync(0xffffffffu, sq, o);
    }
    if ((tid & 31) == 0) { rs[tid >> 5] = sum; rq[tid >> 5] = sq; }
    __syncthreads();
    sum = 0.f; sq = 0.f;
    #pragma unroll
    for (int i = 0; i < 8; i++) { sum += rs[i]; sq += rq[i]; }
    const float mu = sum * (1.f / D_);
    const float var = sq * (1.f / D_) - mu * mu;
    const float rstd = rsqrtf(var + 1e-6f);
    #pragma unroll
    for (int i = 0; i < 3; i++) {
        int c = tid + i * 256;
        float y = (v[i] - mu) * rstd * s[c] + b[c];
        __nv_bfloat16 h, l;
        split_f(y, h, l);
        out_hi[(size_t)row * D_ + c] = h;
        out_lo[(size_t)row * D_ + c] = l;
    }
}

// ---------------- small utility kernels ----------------
__global__ void split_arr_k(const float* __restrict__ in,
                            __nv_bfloat16* __restrict__ hi, __nv_bfloat16* __restrict__ lo,
                            size_t n) {
    size_t i = (size_t)blockIdx.x * 256 + threadIdx.x;
    if (i < n) {
        __nv_bfloat16 h, l;
        split_f(in[i], h, l);
        hi[i] = h; lo[i] = l;
    }
}
__global__ void copy_k(const float* __restrict__ in, float* __restrict__ out, size_t n) {
    size_t i = (size_t)blockIdx.x * 256 + threadIdx.x;
    if (i < n) out[i] = in[i];
}
__global__ void patchify_k(const float* __restrict__ in,
                           __nv_bfloat16* __restrict__ hi, __nv_bfloat16* __restrict__ lo) {
    size_t i = (size_t)blockIdx.x * 256 + threadIdx.x;
    if (i >= (size_t)B_ * NP_ * D_) return;
    int d = (int)(i % D_), r = (int)((i / D_) % NP_), b = (int)(i / ((size_t)D_ * NP_));
    int hp = r / 14, wp = r % 14;
    int c = d >> 8, ph = (d >> 4) & 15, pw = d & 15;
    float v = in[(((size_t)b * 3 + c) * 224 + hp * 16 + ph) * 224 + wp * 16 + pw];
    __nv_bfloat16 h, l;
    split_f(v, h, l);
    hi[i] = h; lo[i] = l;
}
__global__ void assemble_k(const float* __restrict__ ptmp, const float* __restrict__ cls,
                           const float* __restrict__ pos, float* __restrict__ x0,
                           float* __restrict__ x) {
    size_t i = (size_t)blockIdx.x * 256 + threadIdx.x;
    if (i >= (size_t)B_ * NT_ * D_) return;
    int d = (int)(i % D_), j = (int)((i / D_) % NT_), b = (int)(i / ((size_t)D_ * NT_));
    float v = (j == 0 ? cls[d] : ptmp[((size_t)b * NP_ + j - 1) * D_ + d]) + pos[(size_t)j * D_ + d];
    x0[i] = v; x[i] = v;
}
// build xk/xv = concat(h, prompt_k/v) per batch (hi/lo pairs)
__global__ void concat_k(const __nv_bfloat16* __restrict__ h_hi, const __nv_bfloat16* __restrict__ h_lo,
                         const float* __restrict__ gp, const float* __restrict__ ep,
                         const int* __restrict__ idx,
                         __nv_bfloat16* __restrict__ xk_hi, __nv_bfloat16* __restrict__ xk_lo,
                         __nv_bfloat16* __restrict__ xv_hi, __nv_bfloat16* __restrict__ xv_lo,
                         int nkl, int plen, int pi, int isE)
{
    size_t i = (size_t)blockIdx.x * 256 + threadIdx.x;
    if (i >= (size_t)B_ * nkl * D_) return;
    int d = (int)(i % D_);
    int row = (int)(i / D_);
    int b = row / nkl, j = row % nkl;
    if (j < NT_) {
        size_t src = ((size_t)(b * NT_ + j)) * D_ + d;
        __nv_bfloat16 wh = h_hi[src], wl = h_lo[src];
        xk_hi[i] = wh; xk_lo[i] = wl;
        xv_hi[i] = wh; xv_lo[i] = wl;
    } else {
        int jj = j - NT_;
        const float* base = isE ? (ep + (size_t)idx[b] * 120 * D_) : gp;
        float vk = base[((size_t)(2 * pi) * plen + jj) * D_ + d];
        float vv = base[((size_t)(2 * pi + 1) * plen + jj) * D_ + d];
        __nv_bfloat16 h, l;
        split_f(vk, h, l); xk_hi[i] = h; xk_lo[i] = l;
        split_f(vv, h, l); xv_hi[i] = h; xv_lo[i] = l;
    }
}
// cosine argmin prompt selection (block per batch)
__global__ __launch_bounds__(256) void select_k(const float* __restrict__ x,
    const float* __restrict__ key, int* __restrict__ idx)
{
    const int b = blockIdx.x, tid = threadIdx.x;
    const float* q = x + (size_t)b * NT_ * D_;
    float pq = 0.f, pd[T_], pk[T_];
    #pragma unroll
    for (int t = 0; t < T_; t++) { pd[t] = 0.f; pk[t] = 0.f; }
    for (int i = 0; i < 3; i++) {
        int d = tid + i * 256;
        float qd = q[d];
        pq += qd * qd;
        #pragma unroll
        for (int t = 0; t < T_; t++) {
            float kv = key[(size_t)t * D_ + d];
            pd[t] += qd * kv; pk[t] += kv * kv;
        }
    }
    __shared__ float red[256];
    __shared__ float tot[21];
    for (int a = 0; a < 21; a++) {
        float v = (a == 0) ? pq : (a <= 10 ? pd[a - 1] : pk[a - 11]);
        red[tid] = v; __syncthreads();
        for (int st = 128; st > 0; st >>= 1) {
            if (tid < st) red[tid] += red[tid + st];
            __syncthreads();
        }
        if (tid == 0) tot[a] = red[0];
        __syncthreads();
    }
    if (tid == 0) {
        float qn = sqrtf(tot[0]) + 1e-8f;
        float best = -2e30f; int bi = 0;
        for (int t = 0; t < T_; t++) {
            float cosv = tot[1 + t] / (qn * (sqrtf(tot[11 + t]) + 1e-8f));
            if (cosv > best) { best = cosv; bi = t; }   // argmin(dist) = first argmax(cos)
        }
        idx[b] = bi;
    }
}
// final LN(row 0) + head + mask (block per batch)
__global__ __launch_bounds__(256) void head_k(const float* __restrict__ x,
    const float* __restrict__ ns, const float* __restrict__ nb,
    const float* __restrict__ hw, const float* __restrict__ hb,
    const float* __restrict__ mp, const int* __restrict__ idx,
    float* __restrict__ out)
{
    const int b = blockIdx.x, tid = threadIdx.x;
    __shared__ float feat[D_];
    __shared__ float rs[8], rq[8];
    const float* xr = x + (size_t)b * NT_ * D_;
    float v[3], sum = 0.f, sq = 0.f;
    #pragma unroll
    for (int i = 0; i < 3; i++) { v[i] = xr[tid + i * 256]; sum += v[i]; sq += v[i] * v[i]; }
    #pragma unroll
    for (int o = 16; o; o >>= 1) {
        sum += __shfl_xor_sync(0xffffffffu, sum, o);
        sq  += __shfl_xor_sync(0xffffffffu, sq, o);
    }
    if ((tid & 31) == 0) { rs[tid >> 5] = sum; rq[tid >> 5] = sq; }
    __syncthreads();
    sum = 0.f; sq = 0.f;
    #pragma unroll
    for (int i = 0; i < 8; i++) { sum += rs[i]; sq += rq[i]; }
    const float mu = sum * (1.f / D_);
    const float var = sq * (1.f / D_) - mu * mu;
    const float rstd = rsqrtf(var + 1e-6f);
    #pragma unroll
    for (int i = 0; i < 3; i++) {
        int c = tid + i * 256;
        feat[c] = (v[i] - mu) * rstd * ns[c] + nb[c];
    }
    __syncthreads();
    if (tid < NC_) {
        float a = hb[tid];
        const float* wr = hw + (size_t)tid * D_;
        for (int d = 0; d < D_; d++) a += feat[d] * wr[d];
        float m = mp[(size_t)idx[b] * NC_ + tid];
        out[b * NC_ + tid] = a * 2.f / (1.f + expf(-m));
    }
}

// ---------------- host side ----------------
static inline void launch_gemm(int epi,
                               const __nv_bfloat16* Ahi, const __nv_bfloat16* Alo,
                               const __nv_bfloat16* Bhi, const __nv_bfloat16* Blo,
                               const float* bias, float* Cf,
                               __nv_bfloat16* Cb_hi, __nv_bfloat16* Cb_lo,
                               int M, int N, int K)
{
    dim3 grid(N / 128, (M + 127) / 128);
    switch (epi) {
        case 0:  gemm3_k<0><<<grid, 256, SMEM3>>>(Ahi, Alo, Bhi, Blo, bias, Cf, Cb_hi, Cb_lo, M, N, K); break;
        case 1:  gemm3_k<1><<<grid, 256, SMEM3>>>(Ahi, Alo, Bhi, Blo, bias, Cf, Cb_hi, Cb_lo, M, N, K); break;
        default: gemm3_k<2><<<grid, 256, SMEM3>>>(Ahi, Alo, Bhi, Blo, bias, Cf, Cb_hi, Cb_lo, M, N, K); break;
    }
}

extern "C" void kernel_launch(void* const* d_in, const int* in_sizes, int n_in,
                              void* d_out, int out_size)
{
    (void)in_sizes; (void)n_in; (void)out_size;
    const float* inputs     = (const float*)d_in[0];
    const float* patch_w    = (const float*)d_in[1];
    const float* patch_b    = (const float*)d_in[2];
    const float* cls_token  = (const float*)d_in[3];
    const float* pos_embed  = (const float*)d_in[4];
    const float* ln1_s      = (const float*)d_in[5];
    const float* ln1_b      = (const float*)d_in[6];
    const float* qkv_w      = (const float*)d_in[7];
    const float* qkv_b      = (const float*)d_in[8];
    const float* proj_w     = (const float*)d_in[9];
    const float* proj_b     = (const float*)d_in[10];
    const float* ln2_s      = (const float*)d_in[11];
    const float* ln2_b      = (const float*)d_in[12];
    const float* fc1_w      = (const float*)d_in[13];
    const float* fc1_b      = (const float*)d_in[14];
    const float* fc2_w      = (const float*)d_in[15];
    const float* fc2_b      = (const float*)d_in[16];
    const float* norm_s     = (const float*)d_in[17];
    const float* norm_b     = (const float*)d_in[18];
    const float* head_w     = (const float*)d_in[19];
    const float* head_b     = (const float*)d_in[20];
    const float* key_emb    = (const float*)d_in[21];
    const float* mask_param = (const float*)d_in[22];
    const float* g_prompts  = (const float*)d_in[23];
    const float* e_prompts  = (const float*)d_in[24];
    float* out = (float*)d_out;

    void* p;
    cudaGetSymbolAddress(&p, g_x);      float* x      = (float*)p;
    cudaGetSymbolAddress(&p, g_x0);     float* x0     = (float*)p;
    cudaGetSymbolAddress(&p, g_ptmp);   float* ptmp   = (float*)p;
    cudaGetSymbolAddress(&p, g_qkvf);   float* qkvf   = (float*)p;
    cudaGetSymbolAddress(&p, g_qf);     float* qf     = (float*)p;
    cudaGetSymbolAddress(&p, g_kf);     float* kf     = (float*)p;
    cudaGetSymbolAddress(&p, g_vf);     float* vf     = (float*)p;
    cudaGetSymbolAddress(&p, g_idx);    int*   idx    = (int*)p;
    cudaGetSymbolAddress(&p, g_h_hi);   __nv_bfloat16* h_hi  = (__nv_bfloat16*)p;
    cudaGetSymbolAddress(&p, g_h_lo);   __nv_bfloat16* h_lo  = (__nv_bfloat16*)p;
    cudaGetSymbolAddress(&p, g_at_hi);  __nv_bfloat16* at_hi = (__nv_bfloat16*)p;
    cudaGetSymbolAddress(&p, g_at_lo);  __nv_bfloat16* at_lo = (__nv_bfloat16*)p;
    cudaGetSymbolAddress(&p, g_ff_hi);  __nv_bfloat16* ff_hi = (__nv_bfloat16*)p;
    cudaGetSymbolAddress(&p, g_ff_lo);  __nv_bfloat16* ff_lo = (__nv_bfloat16*)p;
    cudaGetSymbolAddress(&p, g_xk_hi);  __nv_bfloat16* xk_hi = (__nv_bfloat16*)p;
    cudaGetSymbolAddress(&p, g_xk_lo);  __nv_bfloat16* xk_lo = (__nv_bfloat16*)p;
    cudaGetSymbolAddress(&p, g_xv_hi);  __nv_bfloat16* xv_hi = (__nv_bfloat16*)p;
    cudaGetSymbolAddress(&p, g_xv_lo);  __nv_bfloat16* xv_lo = (__nv_bfloat16*)p;
    cudaGetSymbolAddress(&p, g_p_hi);   __nv_bfloat16* p_hi  = (__nv_bfloat16*)p;
    cudaGetSymbolAddress(&p, g_p_lo);   __nv_bfloat16* p_lo  = (__nv_bfloat16*)p;
    cudaGetSymbolAddress(&p, g_wpatch_hi); __nv_bfloat16* wpatch_hi = (__nv_bfloat16*)p;
    cudaGetSymbolAddress(&p, g_wpatch_lo); __nv_bfloat16* wpatch_lo = (__nv_bfloat16*)p;
    cudaGetSymbolAddress(&p, g_wqkv_hi);   __nv_bfloat16* wqkv_hi   = (__nv_bfloat16*)p;
    cudaGetSymbolAddress(&p, g_wqkv_lo);   __nv_bfloat16* wqkv_lo   = (__nv_bfloat16*)p;
    cudaGetSymbolAddress(&p, g_wproj_hi);  __nv_bfloat16* wproj_hi  = (__nv_bfloat16*)p;
    cudaGetSymbolAddress(&p, g_wproj_lo);  __nv_bfloat16* wproj_lo  = (__nv_bfloat16*)p;
    cudaGetSymbolAddress(&p, g_wfc1_hi);   __nv_bfloat16* wfc1_hi   = (__nv_bfloat16*)p;
    cudaGetSymbolAddress(&p, g_wfc1_lo);   __nv_bfloat16* wfc1_lo   = (__nv_bfloat16*)p;
    cudaGetSymbolAddress(&p, g_wfc2_hi);   __nv_bfloat16* wfc2_hi   = (__nv_bfloat16*)p;
    cudaGetSymbolAddress(&p, g_wfc2_lo);   __nv_bfloat16* wfc2_lo   = (__nv_bfloat16*)p;

    const int ATT_SMEM = 2 * 64 * KSTR * (int)sizeof(float);   // 115200
    cudaFuncSetAttribute(attn_k, cudaFuncAttributeMaxDynamicSharedMemorySize, ATT_SMEM);
    cudaFuncSetAttribute(gemm3_k<0>, cudaFuncAttributeMaxDynamicSharedMemorySize, SMEM3);
    cudaFuncSetAttribute(gemm3_k<1>, cudaFuncAttributeMaxDynamicSharedMemorySize, SMEM3);
    cudaFuncSetAttribute(gemm3_k<2>, cudaFuncAttributeMaxDynamicSharedMemorySize, SMEM3);

    auto split = [](const float* in, __nv_bfloat16* hi, __nv_bfloat16* lo, size_t n) {
        split_arr_k<<<(unsigned)((n + 255) / 256), 256>>>(in, hi, lo, n);
    };
    // weights -> bf16 hi/lo pairs
    split(patch_w, wpatch_hi, wpatch_lo, (size_t)D_ * D_);
    split(qkv_w,  wqkv_hi,  wqkv_lo,  (size_t)L_ * 3 * D_ * D_);
    split(proj_w, wproj_hi, wproj_lo, (size_t)L_ * D_ * D_);
    split(fc1_w,  wfc1_hi,  wfc1_lo,  (size_t)L_ * FF_ * D_);
    split(fc2_w,  wfc2_hi,  wfc2_lo,  (size_t)L_ * D_ * FF_);

    // patch embed
    {
        size_t n = (size_t)B_ * NP_ * D_;
        patchify_k<<<(unsigned)((n + 255) / 256), 256>>>(inputs, p_hi, p_lo);
        launch_gemm(EPI_F32, p_hi, p_lo, wpatch_hi, wpatch_lo, patch_b,
                    ptmp, nullptr, nullptr, B_ * NP_, D_, D_);
        size_t m = (size_t)B_ * NT_ * D_;
        assemble_k<<<(unsigned)((m + 255) / 256), 256>>>(ptmp, cls_token, pos_embed, x0, x);
    }

    // standard transformer block on x
    auto std_block = [&](int l) {
        ln_k<<<M1, 256>>>(x, ln1_s + (size_t)l * D_, ln1_b + (size_t)l * D_, h_hi, h_lo);
        launch_gemm(EPI_F32, h_hi, h_lo,
                    wqkv_hi + (size_t)l * 3 * D_ * D_, wqkv_lo + (size_t)l * 3 * D_ * D_,
                    qkv_b + (size_t)l * 3 * D_, qkvf, nullptr, nullptr, M1, 3 * D_, D_);
        attn_k<<<dim3(H_, B_), 256, ATT_SMEM>>>(
            qkvf,            (long long)NT_ * 3 * D_, 3 * D_,
            qkvf + D_,       (long long)NT_ * 3 * D_, 3 * D_,
            qkvf + 2 * D_,   (long long)NT_ * 3 * D_, 3 * D_,
            at_hi, at_lo, NT_);
        launch_gemm(EPI_RES, at_hi, at_lo,
                    wproj_hi + (size_t)l * D_ * D_, wproj_lo + (size_t)l * D_ * D_,
                    proj_b + (size_t)l * D_, x, nullptr, nullptr, M1, D_, D_);
        ln_k<<<M1, 256>>>(x, ln2_s + (size_t)l * D_, ln2_b + (size_t)l * D_, h_hi, h_lo);
        launch_gemm(EPI_GELU, h_hi, h_lo,
                    wfc1_hi + (size_t)l * FF_ * D_, wfc1_lo + (size_t)l * FF_ * D_,
                    fc1_b + (size_t)l * FF_, nullptr, ff_hi, ff_lo, M1, FF_, D_);
        launch_gemm(EPI_RES, ff_hi, ff_lo,
                    wfc2_hi + (size_t)l * D_ * FF_, wfc2_lo + (size_t)l * D_ * FF_,
                    fc2_b + (size_t)l * D_, x, nullptr, nullptr, M1, D_, FF_);
    };

    // 1) frozen query pass
    for (int l = 0; l < L_; ++l) std_block(l);
    select_k<<<B_, 256>>>(x, key_emb, idx);

    // 2) reset x = x0 and run prompted pass
    {
        size_t n = (size_t)M1 * D_;
        copy_k<<<(unsigned)((n + 255) / 256), 256>>>(x0, x, n);
    }
    for (int l = 0; l < L_; ++l) {
        const bool isG = (l < 2), isEL = (l >= 2 && l < 5);
        if (!isG && !isEL) { std_block(l); continue; }
        const int plen = isG ? 5 : 20;
        const int pi   = isG ? l : (l - 2);
        const int nkl  = NT_ + plen;
        const int Mk   = B_ * nkl;

        ln_k<<<M1, 256>>>(x, ln1_s + (size_t)l * D_, ln1_b + (size_t)l * D_, h_hi, h_lo);
        {
            size_t n = (size_t)Mk * D_;
            concat_k<<<(unsigned)((n + 255) / 256), 256>>>(
                h_hi, h_lo, g_prompts, e_prompts, idx,
                xk_hi, xk_lo, xv_hi, xv_lo, nkl, plen, pi, isEL ? 1 : 0);
        }
        const size_t wo = (size_t)l * 3 * D_ * D_;
        const float* bl = qkv_b + (size_t)l * 3 * D_;
        launch_gemm(EPI_F32, h_hi, h_lo, wqkv_hi + wo, wqkv_lo + wo,
                    bl, qf, nullptr, nullptr, M1, D_, D_);
        launch_gemm(EPI_F32, xk_hi, xk_lo,
                    wqkv_hi + wo + (size_t)D_ * D_, wqkv_lo + wo + (size_t)D_ * D_,
                    bl + D_, kf, nullptr, nullptr, Mk, D_, D_);
        launch_gemm(EPI_F32, xv_hi, xv_lo,
                    wqkv_hi + wo + (size_t)2 * D_ * D_, wqkv_lo + wo + (size_t)2 * D_ * D_,
                    bl + 2 * D_, vf, nullptr, nullptr, Mk, D_, D_);
        attn_k<<<dim3(H_, B_), 256, ATT_SMEM>>>(
            qf, (long long)NT_ * D_, D_,
            kf, (long long)nkl * D_, D_,
            vf, (long long)nkl * D_, D_,
            at_hi, at_lo, nkl);
        launch_gemm(EPI_RES, at_hi, at_lo,
                    wproj_hi + (size_t)l * D_ * D_, wproj_lo + (size_t)l * D_ * D_,
                    proj_b + (size_t)l * D_, x, nullptr, nullptr, M1, D_, D_);
        ln_k<<<M1, 256>>>(x, ln2_s + (size_t)l * D_, ln2_b + (size_t)l * D_, h_hi, h_lo);
        launch_gemm(EPI_GELU, h_hi, h_lo,
                    wfc1_hi + (size_t)l * FF_ * D_, wfc1_lo + (size_t)l * FF_ * D_,
                    fc1_b + (size_t)l * FF_, nullptr, ff_hi, ff_lo, M1, FF_, D_);
        launch_gemm(EPI_RES, ff_hi, ff_lo,
                    wfc2_hi + (size_t)l * D_ * FF_, wfc2_lo + (size_t)l * D_ * FF_,
                    fc2_b + (size_t)l * D_, x, nullptr, nullptr, M1, D_, FF_);
    }

    // 3) head
    head_k<<<B_, 256>>>(x, norm_s, norm_b, head_w, head_b, mask_param, idx, out);
}

// round 10
// speedup vs baseline: 1.2405x; 1.2405x over previous
#include <cuda_runtime.h>
#include <cuda_bf16.h>
#include <cstdint>
#include <cstddef>

#define DI __device__ __forceinline__

// ---------------- problem dims ----------------
constexpr int L_ = 12, D_ = 768, H_ = 12, FF_ = 3072;
constexpr int B_ = 64, NP_ = 196, NT_ = 197, NC_ = 100, T_ = 10;
constexpr int M1 = B_ * NT_;        // 12608 token rows
constexpr int NKMAX = 217;          // 197 + 20 (e-prompt layers)
constexpr int MKMAX = B_ * NKMAX;   // 13888
constexpr int KSTR = 225;           // attention smem row stride (conflict-free)

// ---------------- device scratch (static, no runtime alloc) ----------------
__device__ float g_x   [(size_t)M1 * D_];
__device__ float g_x0  [(size_t)M1 * D_];
__device__ float g_ptmp[(size_t)B_ * NP_ * D_];
__device__ float g_qkvf[(size_t)M1 * 3 * D_];
__device__ float g_qf  [(size_t)M1 * D_];
__device__ float g_kf  [(size_t)MKMAX * D_];
__device__ float g_vf  [(size_t)MKMAX * D_];
__device__ int   g_idx [B_];
// hi/lo activation pairs
__device__ __nv_bfloat16 g_h_hi [(size_t)M1 * D_];
__device__ __nv_bfloat16 g_h_lo [(size_t)M1 * D_];
__device__ __nv_bfloat16 g_at_hi[(size_t)M1 * D_];
__device__ __nv_bfloat16 g_at_lo[(size_t)M1 * D_];
__device__ __nv_bfloat16 g_ff_hi[(size_t)M1 * FF_];
__device__ __nv_bfloat16 g_ff_lo[(size_t)M1 * FF_];
__device__ __nv_bfloat16 g_xk_hi[(size_t)MKMAX * D_];
__device__ __nv_bfloat16 g_xk_lo[(size_t)MKMAX * D_];
__device__ __nv_bfloat16 g_xv_hi[(size_t)MKMAX * D_];
__device__ __nv_bfloat16 g_xv_lo[(size_t)MKMAX * D_];
__device__ __nv_bfloat16 g_p_hi [(size_t)B_ * NP_ * D_];
__device__ __nv_bfloat16 g_p_lo [(size_t)B_ * NP_ * D_];
// hi/lo weight pairs
__device__ __nv_bfloat16 g_wpatch_hi[(size_t)D_ * D_];
__device__ __nv_bfloat16 g_wpatch_lo[(size_t)D_ * D_];
__device__ __nv_bfloat16 g_wqkv_hi  [(size_t)L_ * 3 * D_ * D_];
__device__ __nv_bfloat16 g_wqkv_lo  [(size_t)L_ * 3 * D_ * D_];
__device__ __nv_bfloat16 g_wproj_hi [(size_t)L_ * D_ * D_];
__device__ __nv_bfloat16 g_wproj_lo [(size_t)L_ * D_ * D_];
__device__ __nv_bfloat16 g_wfc1_hi  [(size_t)L_ * FF_ * D_];
__device__ __nv_bfloat16 g_wfc1_lo  [(size_t)L_ * FF_ * D_];
__device__ __nv_bfloat16 g_wfc2_hi  [(size_t)L_ * D_ * FF_];
__device__ __nv_bfloat16 g_wfc2_lo  [(size_t)L_ * D_ * FF_];

// ---------------- PTX helpers ----------------
DI uint32_t sptr(const void* p) { return (uint32_t)__cvta_generic_to_shared(p); }

DI void cp16(void* s, const void* g, bool pred) {
    asm volatile("cp.async.cg.shared.global [%0], [%1], 16, %2;\n"
                 :: "r"(sptr(s)), "l"(g), "r"(pred ? 16 : 0));
}
DI void cpcommit() { asm volatile("cp.async.commit_group;\n" ::); }
DI void cpwait0()  { asm volatile("cp.async.wait_group 0;\n" ::); }

DI void ldm4(uint32_t* r, const void* p) {
    asm volatile("ldmatrix.sync.aligned.m8n8.x4.shared.b16 {%0,%1,%2,%3}, [%4];\n"
                 : "=r"(r[0]), "=r"(r[1]), "=r"(r[2]), "=r"(r[3])
                 : "r"(sptr(p)) : "memory");
}
DI void mma_bf16(float* d, const uint32_t* a, const uint32_t* b) {
    asm volatile("mma.sync.aligned.m16n8k16.row.col.f32.bf16.bf16.f32 "
                 "{%0,%1,%2,%3}, {%4,%5,%6,%7}, {%8,%9}, {%0,%1,%2,%3};\n"
                 : "+f"(d[0]), "+f"(d[1]), "+f"(d[2]), "+f"(d[3])
                 : "r"(a[0]), "r"(a[1]), "r"(a[2]), "r"(a[3]),
                   "r"(b[0]), "r"(b[1]));
}
DI float gelu_f(float v) { return 0.5f * v * (1.f + erff(v * 0.70710678118654752f)); }
DI void split_f(float v, __nv_bfloat16& hi, __nv_bfloat16& lo) {
    hi = __float2bfloat16(v);
    lo = __float2bfloat16(v - __bfloat162float(hi));
}

constexpr int EPI_F32 = 0, EPI_GELU = 1, EPI_RES = 2;
constexpr int AS = 40;                    // smem row stride (32+8) -> conflict-free LDSM
constexpr int TILE_ELE = 128 * AS;        // 5120 bf16 per tile
constexpr int SMEM3 = 8 * TILE_ELE * 2;   // 81920 bytes (hi/lo A,B double-buffered)
constexpr int SMEM1 = 4 * TILE_ELE * 2;   // 40960 bytes (hi-only A,B double-buffered)

// ---------------- split-bf16 3-product TN GEMM: C = A * B^T (fp32-accurate) ----
DI void load3(const __nv_bfloat16* __restrict__ Ahi, const __nv_bfloat16* __restrict__ Alo,
              const __nv_bfloat16* __restrict__ Bhi, const __nv_bfloat16* __restrict__ Blo,
              __nv_bfloat16* sAh, __nv_bfloat16* sAl,
              __nv_bfloat16* sBh, __nv_bfloat16* sBl,
              int tid, int m0, int n0, int k0, int M, int K)
{
    #pragma unroll
    for (int i = 0; i < 2; i++) {
        int idx = tid + i * 256;          // 512 chunks: 128 rows x 4 x 16B
        int r = idx >> 2, c = (idx & 3) << 3;
        int gr = m0 + r;
        bool p = gr < M;
        size_t aoff = (size_t)(p ? gr : 0) * K + k0 + c;
        size_t boff = (size_t)(n0 + r) * K + k0 + c;
        cp16(sAh + r * AS + c, Ahi + aoff, p);
        cp16(sAl + r * AS + c, Alo + aoff, p);
        cp16(sBh + r * AS + c, Bhi + boff, true);
        cp16(sBl + r * AS + c, Blo + boff, true);
    }
}

template<int EPI>
__global__ __launch_bounds__(256, 1) void gemm3_k(
    const __nv_bfloat16* __restrict__ Ahi, const __nv_bfloat16* __restrict__ Alo,
    const __nv_bfloat16* __restrict__ Bhi, const __nv_bfloat16* __restrict__ Blo,
    const float* __restrict__ bias, float* __restrict__ Cf,
    __nv_bfloat16* __restrict__ Cb_hi, __nv_bfloat16* __restrict__ Cb_lo,
    int M, int N, int K)
{
    extern __shared__ __nv_bfloat16 smem[];
    __nv_bfloat16* sAh = smem;
    __nv_bfloat16* sAl = smem + 2 * TILE_ELE;
    __nv_bfloat16* sBh = smem + 4 * TILE_ELE;
    __nv_bfloat16* sBl = smem + 6 * TILE_ELE;

    const int tid = threadIdx.x;
    const int m0 = blockIdx.y * 128, n0 = blockIdx.x * 128;
    const int wid = tid >> 5, lane = tid & 31;
    const int wm = wid >> 2, wn = wid & 3;          // 2x4 warps, warp tile 64x32

    float acc[4][4][4];
    #pragma unroll
    for (int a = 0; a < 4; a++)
        #pragma unroll
        for (int b = 0; b < 4; b++)
            #pragma unroll
            for (int c = 0; c < 4; c++) acc[a][b][c] = 0.f;

    const int nIt = K >> 5;

    load3(Ahi, Alo, Bhi, Blo, sAh, sAl, sBh, sBl, tid, m0, n0, 0, M, K);
    cpcommit();
    cpwait0();
    __syncthreads();

    for (int it = 0; it < nIt; ++it) {
        const int buf = it & 1;
        const int nb = buf ^ 1;
        if (it + 1 < nIt) {
            load3(Ahi, Alo, Bhi, Blo,
                  sAh + nb * TILE_ELE, sAl + nb * TILE_ELE,
                  sBh + nb * TILE_ELE, sBl + nb * TILE_ELE,
                  tid, m0, n0, (it + 1) << 5, M, K);
            cpcommit();
        }
        const int bo = buf * TILE_ELE;
        #pragma unroll
        for (int kk = 0; kk < 2; ++kk) {
            const int kcol = kk << 4;
            uint32_t ah[4][4], al[4][4], bh[4][2], bl[4][2];
            #pragma unroll
            for (int mt = 0; mt < 4; ++mt) {
                int row = wm * 64 + mt * 16 + (lane & 15);
                int col = kcol + ((lane >> 4) << 3);
                ldm4(ah[mt], &sAh[bo + row * AS + col]);
                ldm4(al[mt], &sAl[bo + row * AS + col]);
            }
            #pragma unroll
            for (int j = 0; j < 2; ++j) {
                int row = wn * 32 + j * 16 + (lane & 7) + ((lane >> 4) << 3);
                int col = kcol + (((lane >> 3) & 1) << 3);
                uint32_t t[4];
                ldm4(t, &sBh[bo + row * AS + col]);
                bh[2 * j][0] = t[0]; bh[2 * j][1] = t[1];
                bh[2 * j + 1][0] = t[2]; bh[2 * j + 1][1] = t[3];
                ldm4(t, &sBl[bo + row * AS + col]);
                bl[2 * j][0] = t[0]; bl[2 * j][1] = t[1];
                bl[2 * j + 1][0] = t[2]; bl[2 * j + 1][1] = t[3];
            }
            #pragma unroll
            for (int mt = 0; mt < 4; ++mt)
                #pragma unroll
                for (int nt = 0; nt < 4; ++nt) {
                    mma_bf16(acc[mt][nt], ah[mt], bh[nt]);
                    mma_bf16(acc[mt][nt], ah[mt], bl[nt]);
                    mma_bf16(acc[mt][nt], al[mt], bh[nt]);
                }
        }
        if (it + 1 < nIt) cpwait0();
        __syncthreads();
    }

    const int g = lane >> 2, tg = lane & 3;
    #pragma unroll
    for (int mt = 0; mt < 4; ++mt) {
        #pragma unroll
        for (int nt = 0; nt < 4; ++nt) {
            const int col = n0 + wn * 32 + nt * 8 + tg * 2;
            #pragma unroll
            for (int hh = 0; hh < 2; ++hh) {
                const int r = m0 + wm * 64 + mt * 16 + g + hh * 8;
                if (r < M) {
                    float v0 = acc[mt][nt][2 * hh + 0] + bias[col];
                    float v1 = acc[mt][nt][2 * hh + 1] + bias[col + 1];
                    size_t off = (size_t)r * N + col;
                    if (EPI == EPI_F32) {
                        float2 o; o.x = v0; o.y = v1;
                        *reinterpret_cast<float2*>(Cf + off) = o;
                    } else if (EPI == EPI_GELU) {
                        float g0 = gelu_f(v0), g1 = gelu_f(v1);
                        __nv_bfloat16 h0, l0, h1, l1;
                        split_f(g0, h0, l0); split_f(g1, h1, l1);
                        __nv_bfloat162 oh; oh.x = h0; oh.y = h1;
                        __nv_bfloat162 ol; ol.x = l0; ol.y = l1;
                        *reinterpret_cast<__nv_bfloat162*>(Cb_hi + off) = oh;
                        *reinterpret_cast<__nv_bfloat162*>(Cb_lo + off) = ol;
                    } else {
                        float2 o = *reinterpret_cast<float2*>(Cf + off);
                        o.x += v0; o.y += v1;
                        *reinterpret_cast<float2*>(Cf + off) = o;
                    }
                }
            }
        }
    }
}

// ---------------- 1-product bf16 TN GEMM (query pass: feeds only idx selection) --
DI void load1(const __nv_bfloat16* __restrict__ A, const __nv_bfloat16* __restrict__ Bw,
              __nv_bfloat16* sA, __nv_bfloat16* sB,
              int tid, int m0, int n0, int k0, int M, int K)
{
    #pragma unroll
    for (int i = 0; i < 2; i++) {
        int idx = tid + i * 256;
        int r = idx >> 2, c = (idx & 3) << 3;
        int gr = m0 + r;
        bool p = gr < M;
        cp16(sA + r * AS + c, A + (size_t)(p ? gr : 0) * K + k0 + c, p);
        cp16(sB + r * AS + c, Bw + (size_t)(n0 + r) * K + k0 + c, true);
    }
}

template<int EPI>
__global__ __launch_bounds__(256, 2) void gemm1_k(
    const __nv_bfloat16* __restrict__ A, const __nv_bfloat16* __restrict__ Bw,
    const float* __restrict__ bias, float* __restrict__ Cf,
    __nv_bfloat16* __restrict__ Cb_hi, int M, int N, int K)
{
    extern __shared__ __nv_bfloat16 smem[];
    __nv_bfloat16* sA = smem;                   // [2][TILE_ELE]
    __nv_bfloat16* sB = smem + 2 * TILE_ELE;    // [2][TILE_ELE]

    const int tid = threadIdx.x;
    const int m0 = blockIdx.y * 128, n0 = blockIdx.x * 128;
    const int wid = tid >> 5, lane = tid & 31;
    const int wm = wid >> 2, wn = wid & 3;

    float acc[4][4][4];
    #pragma unroll
    for (int a = 0; a < 4; a++)
        #pragma unroll
        for (int b = 0; b < 4; b++)
            #pragma unroll
            for (int c = 0; c < 4; c++) acc[a][b][c] = 0.f;

    const int nIt = K >> 5;

    load1(A, Bw, sA, sB, tid, m0, n0, 0, M, K);
    cpcommit();
    cpwait0();
    __syncthreads();

    for (int it = 0; it < nIt; ++it) {
        const int buf = it & 1;
        const int nb = buf ^ 1;
        if (it + 1 < nIt) {
            load1(A, Bw, sA + nb * TILE_ELE, sB + nb * TILE_ELE,
                  tid, m0, n0, (it + 1) << 5, M, K);
            cpcommit();
        }
        const int bo = buf * TILE_ELE;
        #pragma unroll
        for (int kk = 0; kk < 2; ++kk) {
            const int kcol = kk << 4;
            uint32_t ah[4][4], bh[4][2];
            #pragma unroll
            for (int mt = 0; mt < 4; ++mt) {
                int row = wm * 64 + mt * 16 + (lane & 15);
                int col = kcol + ((lane >> 4) << 3);
                ldm4(ah[mt], &sA[bo + row * AS + col]);
            }
            #pragma unroll
            for (int j = 0; j < 2; ++j) {
                int row = wn * 32 + j * 16 + (lane & 7) + ((lane >> 4) << 3);
                int col = kcol + (((lane >> 3) & 1) << 3);
                uint32_t t[4];
                ldm4(t, &sB[bo + row * AS + col]);
                bh[2 * j][0] = t[0]; bh[2 * j][1] = t[1];
                bh[2 * j + 1][0] = t[2]; bh[2 * j + 1][1] = t[3];
            }
            #pragma unroll
            for (int mt = 0; mt < 4; ++mt)
                #pragma unroll
                for (int nt = 0; nt < 4; ++nt)
                    mma_bf16(acc[mt][nt], ah[mt], bh[nt]);
        }
        if (it + 1 < nIt) cpwait0();
        __syncthreads();
    }

    const int g = lane >> 2, tg = lane & 3;
    #pragma unroll
    for (int mt = 0; mt < 4; ++mt) {
        #pragma unroll
        for (int nt = 0; nt < 4; ++nt) {
            const int col = n0 + wn * 32 + nt * 8 + tg * 2;
            #pragma unroll
            for (int hh = 0; hh < 2; ++hh) {
                const int r = m0 + wm * 64 + mt * 16 + g + hh * 8;
                if (r < M) {
                    float v0 = acc[mt][nt][2 * hh + 0] + bias[col];
                    float v1 = acc[mt][nt][2 * hh + 1] + bias[col + 1];
                    size_t off = (size_t)r * N + col;
                    if (EPI == EPI_F32) {
                        float2 o; o.x = v0; o.y = v1;
                        *reinterpret_cast<float2*>(Cf + off) = o;
                    } else if (EPI == EPI_GELU) {
                        __nv_bfloat162 oh = __floats2bfloat162_rn(gelu_f(v0), gelu_f(v1));
                        *reinterpret_cast<__nv_bfloat162*>(Cb_hi + off) = oh;
                    } else {
                        float2 o = *reinterpret_cast<float2*>(Cf + off);
                        o.x += v0; o.y += v1;
                        *reinterpret_cast<float2*>(Cf + off) = o;
                    }
                }
            }
        }
    }
}

// ---------------- attention (fp32 SIMT, block per (b,h)), outputs hi/lo ----------------
__global__ __launch_bounds__(256) void attn_k(
    const float* __restrict__ qp, long long qbs, int qrs,
    const float* __restrict__ kp, long long kbs, int krs,
    const float* __restrict__ vp, long long vbs, int vrs,
    __nv_bfloat16* __restrict__ out_hi, __nv_bfloat16* __restrict__ out_lo, int nk)
{
    extern __shared__ float skvf[];
    float* Ks = skvf;                 // [64][KSTR] transposed
    float* Vs = skvf + 64 * KSTR;
    const int h = blockIdx.x, b = blockIdx.y;
    const int tid = threadIdx.x, lane = tid & 31, w = tid >> 5;

    const float* kb = kp + (long long)b * kbs + h * 64;
    const float* vb = vp + (long long)b * vbs + h * 64;
    for (int i = tid; i < nk * 64; i += 256) {
        int j = i >> 6, d = i & 63;
        Ks[d * KSTR + j] = kb[(long long)j * krs + d];
        Vs[d * KSTR + j] = vb[(long long)j * vrs + d];
    }
    __syncthreads();

    const int cnt = (nk > lane) ? ((nk - lane + 31) >> 5) : 0;

    for (int qi = w; qi < NT_; qi += 8) {
        const float* qrow = qp + (long long)b * qbs + (long long)qi * qrs + h * 64;
        float qv[64];
        #pragma unroll
        for (int d = 0; d < 64; ++d) qv[d] = qrow[d];

        float s[7];
        #pragma unroll
        for (int jj = 0; jj < 7; ++jj) s[jj] = 0.f;
        #pragma unroll
        for (int d = 0; d < 64; ++d) {
            const float qd = qv[d];
            #pragma unroll
            for (int jj = 0; jj < 7; ++jj)
                if (jj < cnt) s[jj] += qd * Ks[d * KSTR + lane + jj * 32];
        }
        float m = -1e30f;
        #pragma unroll
        for (int jj = 0; jj < 7; ++jj)
            if (jj < cnt) { s[jj] *= 0.125f; m = fmaxf(m, s[jj]); }
        #pragma unroll
        for (int o = 16; o; o >>= 1) m = fmaxf(m, __shfl_xor_sync(0xffffffffu, m, o));
        float sum = 0.f;
        #pragma unroll
        for (int jj = 0; jj < 7; ++jj) {
            s[jj] = (jj < cnt) ? __expf(s[jj] - m) : 0.f;
            sum += s[jj];
        }
        #pragma unroll
        for (int o = 16; o; o >>= 1) sum += __shfl_xor_sync(0xffffffffu, sum, o);
        const float inv = 1.f / sum;
        #pragma unroll
        for (int jj = 0; jj < 7; ++jj) s[jj] *= inv;

        float o0 = 0.f, o1 = 0.f;
        #pragma unroll
        for (int d = 0; d < 64; ++d) {
            float a = 0.f;
            #pragma unroll
            for (int jj = 0; jj < 7; ++jj)
                if (jj < cnt) a += s[jj] * Vs[d * KSTR + lane + jj * 32];
            #pragma unroll
            for (int o = 16; o; o >>= 1) a += __shfl_xor_sync(0xffffffffu, a, o);
            if (lane == (d & 31)) { if (d < 32) o0 = a; else o1 = a; }
        }
        size_t base = ((size_t)(b * NT_ + qi)) * D_ + h * 64;
        __nv_bfloat16 h0, l0, h1, l1;
        split_f(o0, h0, l0); split_f(o1, h1, l1);
        out_hi[base + lane] = h0;      out_lo[base + lane] = l0;
        out_hi[base + lane + 32] = h1; out_lo[base + lane + 32] = l1;
    }
}

// ---------------- layernorm (block per row) -> bf16 hi(/lo) ----------------
__global__ __launch_bounds__(256) void ln_k(const float* __restrict__ x,
    const float* __restrict__ s, const float* __restrict__ b,
    __nv_bfloat16* __restrict__ out_hi, __nv_bfloat16* __restrict__ out_lo)
{
    const int row = blockIdx.x, tid = threadIdx.x;
    const float* xr = x + (size_t)row * D_;
    float v[3], sum = 0.f, sq = 0.f;
    #pragma unroll
    for (int i = 0; i < 3; i++) { v[i] = xr[tid + i * 256]; sum += v[i]; sq += v[i] * v[i]; }
    __shared__ float rs[8], rq[8];
    #pragma unroll
    for (int o = 16; o; o >>= 1) {
        sum += __shfl_xor_sync(0xffffffffu, sum, o);
        sq  += __shfl_xor_sync(0xffffffffu, sq, o);
    }
    if ((tid & 31) == 0) { rs[tid >> 5] = sum; rq[tid >> 5] = sq; }
    __syncthreads();
    sum = 0.f; sq = 0.f;
    #pragma unroll
    for (int i = 0; i < 8; i++) { sum += rs[i]; sq += rq[i]; }
    const float mu = sum * (1.f / D_);
    const float var = sq * (1.f / D_) - mu * mu;
    const float rstd = rsqrtf(var + 1e-6f);
    #pragma unroll
    for (int i = 0; i < 3; i++) {
        int c = tid + i * 256;
        float y = (v[i] - mu) * rstd * s[c] + b[c];
        __nv_bfloat16 h, l;
        split_f(y, h, l);
        out_hi[(size_t)row * D_ + c] = h;
        if (out_lo) out_lo[(size_t)row * D_ + c] = l;
    }
}

// ---------------- small utility kernels ----------------
__global__ void split_arr_k(const float* __restrict__ in,
                            __nv_bfloat16* __restrict__ hi, __nv_bfloat16* __restrict__ lo,
                            size_t n) {
    size_t i = (size_t)blockIdx.x * 256 + threadIdx.x;
    if (i < n) {
        __nv_bfloat16 h, l;
        split_f(in[i], h, l);
        hi[i] = h; lo[i] = l;
    }
}
__global__ void copy_k(const float* __restrict__ in, float* __restrict__ out, size_t n) {
    size_t i = (size_t)blockIdx.x * 256 + threadIdx.x;
    if (i < n) out[i] = in[i];
}
__global__ void patchify_k(const float* __restrict__ in,
                           __nv_bfloat16* __restrict__ hi, __nv_bfloat16* __restrict__ lo) {
    size_t i = (size_t)blockIdx.x * 256 + threadIdx.x;
    if (i >= (size_t)B_ * NP_ * D_) return;
    int d = (int)(i % D_), r = (int)((i / D_) % NP_), b = (int)(i / ((size_t)D_ * NP_));
    int hp = r / 14, wp = r % 14;
    int c = d >> 8, ph = (d >> 4) & 15, pw = d & 15;
    float v = in[(((size_t)b * 3 + c) * 224 + hp * 16 + ph) * 224 + wp * 16 + pw];
    __nv_bfloat16 h, l;
    split_f(v, h, l);
    hi[i] = h; lo[i] = l;
}
__global__ void assemble_k(const float* __restrict__ ptmp, const float* __restrict__ cls,
                           const float* __restrict__ pos, float* __restrict__ x0,
                           float* __restrict__ x) {
    size_t i = (size_t)blockIdx.x * 256 + threadIdx.x;
    if (i >= (size_t)B_ * NT_ * D_) return;
    int d = (int)(i % D_), j = (int)((i / D_) % NT_), b = (int)(i / ((size_t)D_ * NT_));
    float v = (j == 0 ? cls[d] : ptmp[((size_t)b * NP_ + j - 1) * D_ + d]) + pos[(size_t)j * D_ + d];
    x0[i] = v; x[i] = v;
}
__global__ void concat_k(const __nv_bfloat16* __restrict__ h_hi, const __nv_bfloat16* __restrict__ h_lo,
                         const float* __restrict__ gp, const float* __restrict__ ep,
                         const int* __restrict__ idx,
                         __nv_bfloat16* __restrict__ xk_hi, __nv_bfloat16* __restrict__ xk_lo,
                         __nv_bfloat16* __restrict__ xv_hi, __nv_bfloat16* __restrict__ xv_lo,
                         int nkl, int plen, int pi, int isE)
{
    size_t i = (size_t)blockIdx.x * 256 + threadIdx.x;
    if (i >= (size_t)B_ * nkl * D_) return;
    int d = (int)(i % D_);
    int row = (int)(i / D_);
    int b = row / nkl, j = row % nkl;
    if (j < NT_) {
        size_t src = ((size_t)(b * NT_ + j)) * D_ + d;
        __nv_bfloat16 wh = h_hi[src], wl = h_lo[src];
        xk_hi[i] = wh; xk_lo[i] = wl;
        xv_hi[i] = wh; xv_lo[i] = wl;
    } else {
        int jj = j - NT_;
        const float* base = isE ? (ep + (size_t)idx[b] * 120 * D_) : gp;
        float vk = base[((size_t)(2 * pi) * plen + jj) * D_ + d];
        float vv = base[((size_t)(2 * pi + 1) * plen + jj) * D_ + d];
        __nv_bfloat16 h, l;
        split_f(vk, h, l); xk_hi[i] = h; xk_lo[i] = l;
        split_f(vv, h, l); xv_hi[i] = h; xv_lo[i] = l;
    }
}
__global__ __launch_bounds__(256) void select_k(const float* __restrict__ x,
    const float* __restrict__ key, int* __restrict__ idx)
{
    const int b = blockIdx.x, tid = threadIdx.x;
    const float* q = x + (size_t)b * NT_ * D_;
    float pq = 0.f, pd[T_], pk[T_];
    #pragma unroll
    for (int t = 0; t < T_; t++) { pd[t] = 0.f; pk[t] = 0.f; }
    for (int i = 0; i < 3; i++) {
        int d = tid + i * 256;
        float qd = q[d];
        pq += qd * qd;
        #pragma unroll
        for (int t = 0; t < T_; t++) {
            float kv = key[(size_t)t * D_ + d];
            pd[t] += qd * kv; pk[t] += kv * kv;
        }
    }
    __shared__ float red[256];
    __shared__ float tot[21];
    for (int a = 0; a < 21; a++) {
        float v = (a == 0) ? pq : (a <= 10 ? pd[a - 1] : pk[a - 11]);
        red[tid] = v; __syncthreads();
        for (int st = 128; st > 0; st >>= 1) {
            if (tid < st) red[tid] += red[tid + st];
            __syncthreads();
        }
        if (tid == 0) tot[a] = red[0];
        __syncthreads();
    }
    if (tid == 0) {
        float qn = sqrtf(tot[0]) + 1e-8f;
        float best = -2e30f; int bi = 0;
        for (int t = 0; t < T_; t++) {
            float cosv = tot[1 + t] / (qn * (sqrtf(tot[11 + t]) + 1e-8f));
            if (cosv > best) { best = cosv; bi = t; }
        }
        idx[b] = bi;
    }
}
__global__ __launch_bounds__(256) void head_k(const float* __restrict__ x,
    const float* __restrict__ ns, const float* __restrict__ nb,
    const float* __restrict__ hw, const float* __restrict__ hb,
    const float* __restrict__ mp, const int* __restrict__ idx,
    float* __restrict__ out)
{
    const int b = blockIdx.x, tid = threadIdx.x;
    __shared__ float feat[D_];
    __shared__ float rs[8], rq[8];
    const float* xr = x + (size_t)b * NT_ * D_;
    float v[3], sum = 0.f, sq = 0.f;
    #pragma unroll
    for (int i = 0; i < 3; i++) { v[i] = xr[tid + i * 256]; sum += v[i]; sq += v[i] * v[i]; }
    #pragma unroll
    for (int o = 16; o; o >>= 1) {
        sum += __shfl_xor_sync(0xffffffffu, sum, o);
        sq  += __shfl_xor_sync(0xffffffffu, sq, o);
    }
    if ((tid & 31) == 0) { rs[tid >> 5] = sum; rq[tid >> 5] = sq; }
    __syncthreads();
    sum = 0.f; sq = 0.f;
    #pragma unroll
    for (int i = 0; i < 8; i++) { sum += rs[i]; sq += rq[i]; }
    const float mu = sum * (1.f / D_);
    const float var = sq * (1.f / D_) - mu * mu;
    const float rstd = rsqrtf(var + 1e-6f);
    #pragma unroll
    for (int i = 0; i < 3; i++) {
        int c = tid + i * 256;
        feat[c] = (v[i] - mu) * rstd * ns[c] + nb[c];
    }
    __syncthreads();
    if (tid < NC_) {
        float a = hb[tid];
        const float* wr = hw + (size_t)tid * D_;
        for (int d = 0; d < D_; d++) a += feat[d] * wr[d];
        float m = mp[(size_t)idx[b] * NC_ + tid];
        out[b * NC_ + tid] = a * 2.f / (1.f + expf(-m));
    }
}

// ---------------- host side ----------------
static inline void launch_gemm3(int epi,
                                const __nv_bfloat16* Ahi, const __nv_bfloat16* Alo,
                                const __nv_bfloat16* Bhi, const __nv_bfloat16* Blo,
                                const float* bias, float* Cf,
                                __nv_bfloat16* Cb_hi, __nv_bfloat16* Cb_lo,
                                int M, int N, int K)
{
    dim3 grid(N / 128, (M + 127) / 128);
    switch (epi) {
        case 0:  gemm3_k<0><<<grid, 256, SMEM3>>>(Ahi, Alo, Bhi, Blo, bias, Cf, Cb_hi, Cb_lo, M, N, K); break;
        case 1:  gemm3_k<1><<<grid, 256, SMEM3>>>(Ahi, Alo, Bhi, Blo, bias, Cf, Cb_hi, Cb_lo, M, N, K); break;
        default: gemm3_k<2><<<grid, 256, SMEM3>>>(Ahi, Alo, Bhi, Blo, bias, Cf, Cb_hi, Cb_lo, M, N, K); break;
    }
}
static inline void launch_gemm1(int epi,
                                const __nv_bfloat16* A, const __nv_bfloat16* Bw,
                                const float* bias, float* Cf, __nv_bfloat16* Cb_hi,
                                int M, int N, int K)
{
    dim3 grid(N / 128, (M + 127) / 128);
    switch (epi) {
        case 0:  gemm1_k<0><<<grid, 256, SMEM1>>>(A, Bw, bias, Cf, Cb_hi, M, N, K); break;
        case 1:  gemm1_k<1><<<grid, 256, SMEM1>>>(A, Bw, bias, Cf, Cb_hi, M, N, K); break;
        default: gemm1_k<2><<<grid, 256, SMEM1>>>(A, Bw, bias, Cf, Cb_hi, M, N, K); break;
    }
}

extern "C" void kernel_launch(void* const* d_in, const int* in_sizes, int n_in,
                              void* d_out, int out_size)
{
    (void)in_sizes; (void)n_in; (void)out_size;
    const float* inputs     = (const float*)d_in[0];
    const float* patch_w    = (const float*)d_in[1];
    const float* patch_b    = (const float*)d_in[2];
    const float* cls_token  = (const float*)d_in[3];
    const float* pos_embed  = (const float*)d_in[4];
    const float* ln1_s      = (const float*)d_in[5];
    const float* ln1_b      = (const float*)d_in[6];
    const float* qkv_w      = (const float*)d_in[7];
    const float* qkv_b      = (const float*)d_in[8];
    const float* proj_w     = (const float*)d_in[9];
    const float* proj_b     = (const float*)d_in[10];
    const float* ln2_s      = (const float*)d_in[11];
    const float* ln2_b      = (const float*)d_in[12];
    const float* fc1_w      = (const float*)d_in[13];
    const float* fc1_b      = (const float*)d_in[14];
    const float* fc2_w      = (const float*)d_in[15];
    const float* fc2_b      = (const float*)d_in[16];
    const float* norm_s     = (const float*)d_in[17];
    const float* norm_b     = (const float*)d_in[18];
    const float* head_w     = (const float*)d_in[19];
    const float* head_b     = (const float*)d_in[20];
    const float* key_emb    = (const float*)d_in[21];
    const float* mask_param = (const float*)d_in[22];
    const float* g_prompts  = (const float*)d_in[23];
    const float* e_prompts  = (const float*)d_in[24];
    float* out = (float*)d_out;

    void* p;
    cudaGetSymbolAddress(&p, g_x);      float* x      = (float*)p;
    cudaGetSymbolAddress(&p, g_x0);     float* x0     = (float*)p;
    cudaGetSymbolAddress(&p, g_ptmp);   float* ptmp   = (float*)p;
    cudaGetSymbolAddress(&p, g_qkvf);   float* qkvf   = (float*)p;
    cudaGetSymbolAddress(&p, g_qf);     float* qf     = (float*)p;
    cudaGetSymbolAddress(&p, g_kf);     float* kf     = (float*)p;
    cudaGetSymbolAddress(&p, g_vf);     float* vf     = (float*)p;
    cudaGetSymbolAddress(&p, g_idx);    int*   idx    = (int*)p;
    cudaGetSymbolAddress(&p, g_h_hi);   __nv_bfloat16* h_hi  = (__nv_bfloat16*)p;
    cudaGetSymbolAddress(&p, g_h_lo);   __nv_bfloat16* h_lo  = (__nv_bfloat16*)p;
    cudaGetSymbolAddress(&p, g_at_hi);  __nv_bfloat16* at_hi = (__nv_bfloat16*)p;
    cudaGetSymbolAddress(&p, g_at_lo);  __nv_bfloat16* at_lo = (__nv_bfloat16*)p;
    cudaGetSymbolAddress(&p, g_ff_hi);  __nv_bfloat16* ff_hi = (__nv_bfloat16*)p;
    cudaGetSymbolAddress(&p, g_ff_lo);  __nv_bfloat16* ff_lo = (__nv_bfloat16*)p;
    cudaGetSymbolAddress(&p, g_xk_hi);  __nv_bfloat16* xk_hi = (__nv_bfloat16*)p;
    cudaGetSymbolAddress(&p, g_xk_lo);  __nv_bfloat16* xk_lo = (__nv_bfloat16*)p;
    cudaGetSymbolAddress(&p, g_xv_hi);  __nv_bfloat16* xv_hi = (__nv_bfloat16*)p;
    cudaGetSymbolAddress(&p, g_xv_lo);  __nv_bfloat16* xv_lo = (__nv_bfloat16*)p;
    cudaGetSymbolAddress(&p, g_p_hi);   __nv_bfloat16* p_hi  = (__nv_bfloat16*)p;
    cudaGetSymbolAddress(&p, g_p_lo);   __nv_bfloat16* p_lo  = (__nv_bfloat16*)p;
    cudaGetSymbolAddress(&p, g_wpatch_hi); __nv_bfloat16* wpatch_hi = (__nv_bfloat16*)p;
    cudaGetSymbolAddress(&p, g_wpatch_lo); __nv_bfloat16* wpatch_lo = (__nv_bfloat16*)p;
    cudaGetSymbolAddress(&p, g_wqkv_hi);   __nv_bfloat16* wqkv_hi   = (__nv_bfloat16*)p;
    cudaGetSymbolAddress(&p, g_wqkv_lo);   __nv_bfloat16* wqkv_lo   = (__nv_bfloat16*)p;
    cudaGetSymbolAddress(&p, g_wproj_hi);  __nv_bfloat16* wproj_hi  = (__nv_bfloat16*)p;
    cudaGetSymbolAddress(&p, g_wproj_lo);  __nv_bfloat16* wproj_lo  = (__nv_bfloat16*)p;
    cudaGetSymbolAddress(&p, g_wfc1_hi);   __nv_bfloat16* wfc1_hi   = (__nv_bfloat16*)p;
    cudaGetSymbolAddress(&p, g_wfc1_lo);   __nv_bfloat16* wfc1_lo   = (__nv_bfloat16*)p;
    cudaGetSymbolAddress(&p, g_wfc2_hi);   __nv_bfloat16* wfc2_hi   = (__nv_bfloat16*)p;
    cudaGetSymbolAddress(&p, g_wfc2_lo);   __nv_bfloat16* wfc2_lo   = (__nv_bfloat16*)p;

    const int ATT_SMEM = 2 * 64 * KSTR * (int)sizeof(float);   // 115200
    cudaFuncSetAttribute(attn_k, cudaFuncAttributeMaxDynamicSharedMemorySize, ATT_SMEM);
    cudaFuncSetAttribute(gemm3_k<0>, cudaFuncAttributeMaxDynamicSharedMemorySize, SMEM3);
    cudaFuncSetAttribute(gemm3_k<1>, cudaFuncAttributeMaxDynamicSharedMemorySize, SMEM3);
    cudaFuncSetAttribute(gemm3_k<2>, cudaFuncAttributeMaxDynamicSharedMemorySize, SMEM3);
    cudaFuncSetAttribute(gemm1_k<0>, cudaFuncAttributeMaxDynamicSharedMemorySize, SMEM1);
    cudaFuncSetAttribute(gemm1_k<1>, cudaFuncAttributeMaxDynamicSharedMemorySize, SMEM1);
    cudaFuncSetAttribute(gemm1_k<2>, cudaFuncAttributeMaxDynamicSharedMemorySize, SMEM1);

    auto split = [](const float* in, __nv_bfloat16* hi, __nv_bfloat16* lo, size_t n) {
        split_arr_k<<<(unsigned)((n + 255) / 256), 256>>>(in, hi, lo, n);
    };
    split(patch_w, wpatch_hi, wpatch_lo, (size_t)D_ * D_);
    split(qkv_w,  wqkv_hi,  wqkv_lo,  (size_t)L_ * 3 * D_ * D_);
    split(proj_w, wproj_hi, wproj_lo, (size_t)L_ * D_ * D_);
    split(fc1_w,  wfc1_hi,  wfc1_lo,  (size_t)L_ * FF_ * D_);
    split(fc2_w,  wfc2_hi,  wfc2_lo,  (size_t)L_ * D_ * FF_);

    // patch embed (3-product: feeds both passes)
    {
        size_t n = (size_t)B_ * NP_ * D_;
        patchify_k<<<(unsigned)((n + 255) / 256), 256>>>(inputs, p_hi, p_lo);
        launch_gemm3(EPI_F32, p_hi, p_lo, wpatch_hi, wpatch_lo, patch_b,
                     ptmp, nullptr, nullptr, B_ * NP_, D_, D_);
        size_t m = (size_t)B_ * NT_ * D_;
        assemble_k<<<(unsigned)((m + 255) / 256), 256>>>(ptmp, cls_token, pos_embed, x0, x);
    }

    // fast (1-product) transformer block: query pass only — feeds idx selection
    auto fast_block = [&](int l) {
        ln_k<<<M1, 256>>>(x, ln1_s + (size_t)l * D_, ln1_b + (size_t)l * D_, h_hi, nullptr);
        launch_gemm1(EPI_F32, h_hi, wqkv_hi + (size_t)l * 3 * D_ * D_,
                     qkv_b + (size_t)l * 3 * D_, qkvf, nullptr, M1, 3 * D_, D_);
        attn_k<<<dim3(H_, B_), 256, ATT_SMEM>>>(
            qkvf,            (long long)NT_ * 3 * D_, 3 * D_,
            qkvf + D_,       (long long)NT_ * 3 * D_, 3 * D_,
            qkvf + 2 * D_,   (long long)NT_ * 3 * D_, 3 * D_,
            at_hi, at_lo, NT_);
        launch_gemm1(EPI_RES, at_hi, wproj_hi + (size_t)l * D_ * D_,
                     proj_b + (size_t)l * D_, x, nullptr, M1, D_, D_);
        ln_k<<<M1, 256>>>(x, ln2_s + (size_t)l * D_, ln2_b + (size_t)l * D_, h_hi, nullptr);
        launch_gemm1(EPI_GELU, h_hi, wfc1_hi + (size_t)l * FF_ * D_,
                     fc1_b + (size_t)l * FF_, nullptr, ff_hi, M1, FF_, D_);
        launch_gemm1(EPI_RES, ff_hi, wfc2_hi + (size_t)l * D_ * FF_,
                     fc2_b + (size_t)l * D_, x, nullptr, M1, D_, FF_);
    };

    // accurate (3-product) transformer block: prompted pass
    auto std_block = [&](int l) {
        ln_k<<<M1, 256>>>(x, ln1_s + (size_t)l * D_, ln1_b + (size_t)l * D_, h_hi, h_lo);
        launch_gemm3(EPI_F32, h_hi, h_lo,
                     wqkv_hi + (size_t)l * 3 * D_ * D_, wqkv_lo + (size_t)l * 3 * D_ * D_,
                     qkv_b + (size_t)l * 3 * D_, qkvf, nullptr, nullptr, M1, 3 * D_, D_);
        attn_k<<<dim3(H_, B_), 256, ATT_SMEM>>>(
            qkvf,            (long long)NT_ * 3 * D_, 3 * D_,
            qkvf + D_,       (long long)NT_ * 3 * D_, 3 * D_,
            qkvf + 2 * D_,   (long long)NT_ * 3 * D_, 3 * D_,
            at_hi, at_lo, NT_);
        launch_gemm3(EPI_RES, at_hi, at_lo,
                     wproj_hi + (size_t)l * D_ * D_, wproj_lo + (size_t)l * D_ * D_,
                     proj_b + (size_t)l * D_, x, nullptr, nullptr, M1, D_, D_);
        ln_k<<<M1, 256>>>(x, ln2_s + (size_t)l * D_, ln2_b + (size_t)l * D_, h_hi, h_lo);
        launch_gemm3(EPI_GELU, h_hi, h_lo,
                     wfc1_hi + (size_t)l * FF_ * D_, wfc1_lo + (size_t)l * FF_ * D_,
                     fc1_b + (size_t)l * FF_, nullptr, ff_hi, ff_lo, M1, FF_, D_);
        launch_gemm3(EPI_RES, ff_hi, ff_lo,
                     wfc2_hi + (size_t)l * D_ * FF_, wfc2_lo + (size_t)l * D_ * FF_,
                     fc2_b + (size_t)l * D_, x, nullptr, nullptr, M1, D_, FF_);
    };

    // 1) frozen query pass (1-product bf16 — only idx depends on it)
    for (int l = 0; l < L_; ++l) fast_block(l);
    select_k<<<B_, 256>>>(x, key_emb, idx);

    // 2) reset x = x0 and run prompted pass (3-product, fp32-accurate)
    {
        size_t n = (size_t)M1 * D_;
        copy_k<<<(unsigned)((n + 255) / 256), 256>>>(x0, x, n);
    }
    for (int l = 0; l < L_; ++l) {
        const bool isG = (l < 2), isEL = (l >= 2 && l < 5);
        if (!isG && !isEL) { std_block(l); continue; }
        const int plen = isG ? 5 : 20;
        const int pi   = isG ? l : (l - 2);
        const int nkl  = NT_ + plen;
        const int Mk   = B_ * nkl;

        ln_k<<<M1, 256>>>(x, ln1_s + (size_t)l * D_, ln1_b + (size_t)l * D_, h_hi, h_lo);
        {
            size_t n = (size_t)Mk * D_;
            concat_k<<<(unsigned)((n + 255) / 256), 256>>>(
                h_hi, h_lo, g_prompts, e_prompts, idx,
                xk_hi, xk_lo, xv_hi, xv_lo, nkl, plen, pi, isEL ? 1 : 0);
        }
        const size_t wo = (size_t)l * 3 * D_ * D_;
        const float* bl = qkv_b + (size_t)l * 3 * D_;
        launch_gemm3(EPI_F32, h_hi, h_lo, wqkv_hi + wo, wqkv_lo + wo,
                     bl, qf, nullptr, nullptr, M1, D_, D_);
        launch_gemm3(EPI_F32, xk_hi, xk_lo,
                     wqkv_hi + wo + (size_t)D_ * D_, wqkv_lo + wo + (size_t)D_ * D_,
                     bl + D_, kf, nullptr, nullptr, Mk, D_, D_);
        launch_gemm3(EPI_F32, xv_hi, xv_lo,
                     wqkv_hi + wo + (size_t)2 * D_ * D_, wqkv_lo + wo + (size_t)2 * D_ * D_,
                     bl + 2 * D_, vf, nullptr, nullptr, Mk, D_, D_);
        attn_k<<<dim3(H_, B_), 256, ATT_SMEM>>>(
            qf, (long long)NT_ * D_, D_,
            kf, (long long)nkl * D_, D_,
            vf, (long long)nkl * D_, D_,
            at_hi, at_lo, nkl);
        launch_gemm3(EPI_RES, at_hi, at_lo,
                     wproj_hi + (size_t)l * D_ * D_, wproj_lo + (size_t)l * D_ * D_,
                     proj_b + (size_t)l * D_, x, nullptr, nullptr, M1, D_, D_);
        ln_k<<<M1, 256>>>(x, ln2_s + (size_t)l * D_, ln2_b + (size_t)l * D_, h_hi, h_lo);
        launch_gemm3(EPI_GELU, h_hi, h_lo,
                     wfc1_hi + (size_t)l * FF_ * D_, wfc1_lo + (size_t)l * FF_ * D_,
                     fc1_b + (size_t)l * FF_, nullptr, ff_hi, ff_lo, M1, FF_, D_);
        launch_gemm3(EPI_RES, ff_hi, ff_lo,
                     wfc2_hi + (size_t)l * D_ * FF_, wfc2_lo + (size_t)l * D_ * FF_,
                     fc2_b + (size_t)l * D_, x, nullptr, nullptr, M1, D_, FF_);
    }

    // 3) head
    head_k<<<B_, 256>>>(x, norm_s, norm_b, head_w, head_b, mask_param, idx, out);
}

// round 13
// speedup vs baseline: 1.4211x; 1.1456x over previous
#include <cuda_runtime.h>
#include <cuda_bf16.h>
#include <cstdint>
#include <cstddef>

#define DI __device__ __forceinline__

// ---------------- problem dims ----------------
constexpr int L_ = 12, D_ = 768, H_ = 12, FF_ = 3072;
constexpr int B_ = 64, NP_ = 196, NT_ = 197, NC_ = 100, T_ = 10;
constexpr int M1 = B_ * NT_;        // 12608 token rows
constexpr int NKMAX = 217;          // 197 + 20 (e-prompt layers)
constexpr int MKMAX = B_ * NKMAX;   // 13888
constexpr int KSTR = 228;           // attention K/V smem row stride (float4-aligned)
constexpr int PPAD = 224;           // padded key count (mult of 32)

// ---------------- device scratch (static, no runtime alloc) ----------------
__device__ float g_x   [(size_t)M1 * D_];
__device__ float g_x0  [(size_t)M1 * D_];
__device__ float g_ptmp[(size_t)B_ * NP_ * D_];
__device__ float g_qkvf[(size_t)M1 * 3 * D_];
__device__ float g_qf  [(size_t)M1 * D_];
__device__ float g_kf  [(size_t)MKMAX * D_];
__device__ float g_vf  [(size_t)MKMAX * D_];
__device__ int   g_idx [B_];
// hi/lo activation pairs
__device__ __nv_bfloat16 g_h_hi [(size_t)M1 * D_];
__device__ __nv_bfloat16 g_h_lo [(size_t)M1 * D_];
__device__ __nv_bfloat16 g_at_hi[(size_t)M1 * D_];
__device__ __nv_bfloat16 g_at_lo[(size_t)M1 * D_];
__device__ __nv_bfloat16 g_ff_hi[(size_t)M1 * FF_];
__device__ __nv_bfloat16 g_ff_lo[(size_t)M1 * FF_];
__device__ __nv_bfloat16 g_xk_hi[(size_t)MKMAX * D_];
__device__ __nv_bfloat16 g_xk_lo[(size_t)MKMAX * D_];
__device__ __nv_bfloat16 g_xv_hi[(size_t)MKMAX * D_];
__device__ __nv_bfloat16 g_xv_lo[(size_t)MKMAX * D_];
__device__ __nv_bfloat16 g_p_hi [(size_t)B_ * NP_ * D_];
__device__ __nv_bfloat16 g_p_lo [(size_t)B_ * NP_ * D_];
// hi/lo weight pairs
__device__ __nv_bfloat16 g_wpatch_hi[(size_t)D_ * D_];
__device__ __nv_bfloat16 g_wpatch_lo[(size_t)D_ * D_];
__device__ __nv_bfloat16 g_wqkv_hi  [(size_t)L_ * 3 * D_ * D_];
__device__ __nv_bfloat16 g_wqkv_lo  [(size_t)L_ * 3 * D_ * D_];
__device__ __nv_bfloat16 g_wproj_hi [(size_t)L_ * D_ * D_];
__device__ __nv_bfloat16 g_wproj_lo [(size_t)L_ * D_ * D_];
__device__ __nv_bfloat16 g_wfc1_hi  [(size_t)L_ * FF_ * D_];
__device__ __nv_bfloat16 g_wfc1_lo  [(size_t)L_ * FF_ * D_];
__device__ __nv_bfloat16 g_wfc2_hi  [(size_t)L_ * D_ * FF_];
__device__ __nv_bfloat16 g_wfc2_lo  [(size_t)L_ * D_ * FF_];

// ---------------- PTX helpers ----------------
DI uint32_t sptr(const void* p) { return (uint32_t)__cvta_generic_to_shared(p); }

DI void cp16(void* s, const void* g, bool pred) {
    asm volatile("cp.async.cg.shared.global [%0], [%1], 16, %2;\n"
                 :: "r"(sptr(s)), "l"(g), "r"(pred ? 16 : 0));
}
DI void cpcommit() { asm volatile("cp.async.commit_group;\n" ::); }
DI void cpwait0()  { asm volatile("cp.async.wait_group 0;\n" ::); }

DI void ldm4(uint32_t* r, const void* p) {
    asm volatile("ldmatrix.sync.aligned.m8n8.x4.shared.b16 {%0,%1,%2,%3}, [%4];\n"
                 : "=r"(r[0]), "=r"(r[1]), "=r"(r[2]), "=r"(r[3])
                 : "r"(sptr(p)) : "memory");
}
DI void mma_bf16(float* d, const uint32_t* a, const uint32_t* b) {
    asm volatile("mma.sync.aligned.m16n8k16.row.col.f32.bf16.bf16.f32 "
                 "{%0,%1,%2,%3}, {%4,%5,%6,%7}, {%8,%9}, {%0,%1,%2,%3};\n"
                 : "+f"(d[0]), "+f"(d[1]), "+f"(d[2]), "+f"(d[3])
                 : "r"(a[0]), "r"(a[1]), "r"(a[2]), "r"(a[3]),
                   "r"(b[0]), "r"(b[1]));
}
DI float gelu_f(float v) { return 0.5f * v * (1.f + erff(v * 0.70710678118654752f)); }
DI void split_f(float v, __nv_bfloat16& hi, __nv_bfloat16& lo) {
    hi = __float2bfloat16(v);
    lo = __float2bfloat16(v - __bfloat162float(hi));
}

constexpr int EPI_F32 = 0, EPI_GELU = 1, EPI_RES = 2;
constexpr int AS = 40;                    // smem row stride (32+8) -> conflict-free LDSM
constexpr int TILE_ELE = 128 * AS;        // 5120 bf16 per tile
constexpr int SMEM3 = 8 * TILE_ELE * 2;   // 81920 bytes (hi/lo A,B double-buffered)
constexpr int SMEM1 = 4 * TILE_ELE * 2;   // 40960 bytes (hi-only A,B double-buffered)

// ---------------- split-bf16 3-product TN GEMM: C = A * B^T (fp32-accurate) ----
DI void load3(const __nv_bfloat16* __restrict__ Ahi, const __nv_bfloat16* __restrict__ Alo,
              const __nv_bfloat16* __restrict__ Bhi, const __nv_bfloat16* __restrict__ Blo,
              __nv_bfloat16* sAh, __nv_bfloat16* sAl,
              __nv_bfloat16* sBh, __nv_bfloat16* sBl,
              int tid, int m0, int n0, int k0, int M, int K)
{
    #pragma unroll
    for (int i = 0; i < 2; i++) {
        int idx = tid + i * 256;          // 512 chunks: 128 rows x 4 x 16B
        int r = idx >> 2, c = (idx & 3) << 3;
        int gr = m0 + r;
        bool p = gr < M;
        size_t aoff = (size_t)(p ? gr : 0) * K + k0 + c;
        size_t boff = (size_t)(n0 + r) * K + k0 + c;
        cp16(sAh + r * AS + c, Ahi + aoff, p);
        cp16(sAl + r * AS + c, Alo + aoff, p);
        cp16(sBh + r * AS + c, Bhi + boff, true);
        cp16(sBl + r * AS + c, Blo + boff, true);
    }
}

template<int EPI>
__global__ __launch_bounds__(256, 2) void gemm3_k(
    const __nv_bfloat16* __restrict__ Ahi, const __nv_bfloat16* __restrict__ Alo,
    const __nv_bfloat16* __restrict__ Bhi, const __nv_bfloat16* __restrict__ Blo,
    const float* __restrict__ bias, float* __restrict__ Cf,
    __nv_bfloat16* __restrict__ Cb_hi, __nv_bfloat16* __restrict__ Cb_lo,
    int M, int N, int K)
{
    extern __shared__ __nv_bfloat16 smem[];
    __nv_bfloat16* sAh = smem;
    __nv_bfloat16* sAl = smem + 2 * TILE_ELE;
    __nv_bfloat16* sBh = smem + 4 * TILE_ELE;
    __nv_bfloat16* sBl = smem + 6 * TILE_ELE;

    const int tid = threadIdx.x;
    const int m0 = blockIdx.y * 128, n0 = blockIdx.x * 128;
    const int wid = tid >> 5, lane = tid & 31;
    const int wm = wid >> 2, wn = wid & 3;          // 2x4 warps, warp tile 64x32

    float acc[4][4][4];
    #pragma unroll
    for (int a = 0; a < 4; a++)
        #pragma unroll
        for (int b = 0; b < 4; b++)
            #pragma unroll
            for (int c = 0; c < 4; c++) acc[a][b][c] = 0.f;

    const int nIt = K >> 5;

    load3(Ahi, Alo, Bhi, Blo, sAh, sAl, sBh, sBl, tid, m0, n0, 0, M, K);
    cpcommit();
    cpwait0();
    __syncthreads();

    for (int it = 0; it < nIt; ++it) {
        const int buf = it & 1;
        const int nb = buf ^ 1;
        if (it + 1 < nIt) {
            load3(Ahi, Alo, Bhi, Blo,
                  sAh + nb * TILE_ELE, sAl + nb * TILE_ELE,
                  sBh + nb * TILE_ELE, sBl + nb * TILE_ELE,
                  tid, m0, n0, (it + 1) << 5, M, K);
            cpcommit();
        }
        const int bo = buf * TILE_ELE;
        #pragma unroll
        for (int kk = 0; kk < 2; ++kk) {
            const int kcol = kk << 4;
            uint32_t bh[4][2], bl[4][2], af[4][4];
            // B fragments (hi + lo)
            #pragma unroll
            for (int j = 0; j < 2; ++j) {
                int row = wn * 32 + j * 16 + (lane & 7) + ((lane >> 4) << 3);
                int col = kcol + (((lane >> 3) & 1) << 3);
                uint32_t t[4];
                ldm4(t, &sBh[bo + row * AS + col]);
                bh[2 * j][0] = t[0]; bh[2 * j][1] = t[1];
                bh[2 * j + 1][0] = t[2]; bh[2 * j + 1][1] = t[3];
                ldm4(t, &sBl[bo + row * AS + col]);
                bl[2 * j][0] = t[0]; bl[2 * j][1] = t[1];
                bl[2 * j + 1][0] = t[2]; bl[2 * j + 1][1] = t[3];
            }
            // A-hi fragments -> AhBh + AhBl
            #pragma unroll
            for (int mt = 0; mt < 4; ++mt) {
                int row = wm * 64 + mt * 16 + (lane & 15);
                int col = kcol + ((lane >> 4) << 3);
                ldm4(af[mt], &sAh[bo + row * AS + col]);
            }
            #pragma unroll
            for (int mt = 0; mt < 4; ++mt)
                #pragma unroll
                for (int nt = 0; nt < 4; ++nt)
                    mma_bf16(acc[mt][nt], af[mt], bh[nt]);
            #pragma unroll
            for (int mt = 0; mt < 4; ++mt)
                #pragma unroll
                for (int nt = 0; nt < 4; ++nt)
                    mma_bf16(acc[mt][nt], af[mt], bl[nt]);
            // A-lo fragments (reuse regs) -> AlBh
            #pragma unroll
            for (int mt = 0; mt < 4; ++mt) {
                int row = wm * 64 + mt * 16 + (lane & 15);
                int col = kcol + ((lane >> 4) << 3);
                ldm4(af[mt], &sAl[bo + row * AS + col]);
            }
            #pragma unroll
            for (int mt = 0; mt < 4; ++mt)
                #pragma unroll
                for (int nt = 0; nt < 4; ++nt)
                    mma_bf16(acc[mt][nt], af[mt], bh[nt]);
        }
        if (it + 1 < nIt) cpwait0();
        __syncthreads();
    }

    const int g = lane >> 2, tg = lane & 3;
    #pragma unroll
    for (int mt = 0; mt < 4; ++mt) {
        #pragma unroll
        for (int nt = 0; nt < 4; ++nt) {
            const int col = n0 + wn * 32 + nt * 8 + tg * 2;
            #pragma unroll
            for (int hh = 0; hh < 2; ++hh) {
                const int r = m0 + wm * 64 + mt * 16 + g + hh * 8;
                if (r < M) {
                    float v0 = acc[mt][nt][2 * hh + 0] + bias[col];
                    float v1 = acc[mt][nt][2 * hh + 1] + bias[col + 1];
                    size_t off = (size_t)r * N + col;
                    if (EPI == EPI_F32) {
                        float2 o; o.x = v0; o.y = v1;
                        *reinterpret_cast<float2*>(Cf + off) = o;
                    } else if (EPI == EPI_GELU) {
                        float g0 = gelu_f(v0), g1 = gelu_f(v1);
                        __nv_bfloat16 h0, l0, h1, l1;
                        split_f(g0, h0, l0); split_f(g1, h1, l1);
                        __nv_bfloat162 oh; oh.x = h0; oh.y = h1;
                        __nv_bfloat162 ol; ol.x = l0; ol.y = l1;
                        *reinterpret_cast<__nv_bfloat162*>(Cb_hi + off) = oh;
                        *reinterpret_cast<__nv_bfloat162*>(Cb_lo + off) = ol;
                    } else {
                        float2 o = *reinterpret_cast<float2*>(Cf + off);
                        o.x += v0; o.y += v1;
                        *reinterpret_cast<float2*>(Cf + off) = o;
                    }
                }
            }
        }
    }
}

// ---------------- 1-product bf16 TN GEMM (query pass: feeds only idx selection) --
DI void load1(const __nv_bfloat16* __restrict__ A, const __nv_bfloat16* __restrict__ Bw,
              __nv_bfloat16* sA, __nv_bfloat16* sB,
              int tid, int m0, int n0, int k0, int M, int K)
{
    #pragma unroll
    for (int i = 0; i < 2; i++) {
        int idx = tid + i * 256;
        int r = idx >> 2, c = (idx & 3) << 3;
        int gr = m0 + r;
        bool p = gr < M;
        cp16(sA + r * AS + c, A + (size_t)(p ? gr : 0) * K + k0 + c, p);
        cp16(sB + r * AS + c, Bw + (size_t)(n0 + r) * K + k0 + c, true);
    }
}

template<int EPI>
__global__ __launch_bounds__(256, 2) void gemm1_k(
    const __nv_bfloat16* __restrict__ A, const __nv_bfloat16* __restrict__ Bw,
    const float* __restrict__ bias, float* __restrict__ Cf,
    __nv_bfloat16* __restrict__ Cb_hi, int M, int N, int K)
{
    extern __shared__ __nv_bfloat16 smem[];
    __nv_bfloat16* sA = smem;                   // [2][TILE_ELE]
    __nv_bfloat16* sB = smem + 2 * TILE_ELE;    // [2][TILE_ELE]

    const int tid = threadIdx.x;
    const int m0 = blockIdx.y * 128, n0 = blockIdx.x * 128;
    const int wid = tid >> 5, lane = tid & 31;
    const int wm = wid >> 2, wn = wid & 3;

    float acc[4][4][4];
    #pragma unroll
    for (int a = 0; a < 4; a++)
        #pragma unroll
        for (int b = 0; b < 4; b++)
            #pragma unroll
            for (int c = 0; c < 4; c++) acc[a][b][c] = 0.f;

    const int nIt = K >> 5;

    load1(A, Bw, sA, sB, tid, m0, n0, 0, M, K);
    cpcommit();
    cpwait0();
    __syncthreads();

    for (int it = 0; it < nIt; ++it) {
        const int buf = it & 1;
        const int nb = buf ^ 1;
        if (it + 1 < nIt) {
            load1(A, Bw, sA + nb * TILE_ELE, sB + nb * TILE_ELE,
                  tid, m0, n0, (it + 1) << 5, M, K);
            cpcommit();
        }
        const int bo = buf * TILE_ELE;
        #pragma unroll
        for (int kk = 0; kk < 2; ++kk) {
            const int kcol = kk << 4;
            uint32_t ah[4][4], bh[4][2];
            #pragma unroll
            for (int mt = 0; mt < 4; ++mt) {
                int row = wm * 64 + mt * 16 + (lane & 15);
                int col = kcol + ((lane >> 4) << 3);
                ldm4(ah[mt], &sA[bo + row * AS + col]);
            }
            #pragma unroll
            for (int j = 0; j < 2; ++j) {
                int row = wn * 32 + j * 16 + (lane & 7) + ((lane >> 4) << 3);
                int col = kcol + (((lane >> 3) & 1) << 3);
                uint32_t t[4];
                ldm4(t, &sB[bo + row * AS + col]);
                bh[2 * j][0] = t[0]; bh[2 * j][1] = t[1];
                bh[2 * j + 1][0] = t[2]; bh[2 * j + 1][1] = t[3];
            }
            #pragma unroll
            for (int mt = 0; mt < 4; ++mt)
                #pragma unroll
                for (int nt = 0; nt < 4; ++nt)
                    mma_bf16(acc[mt][nt], ah[mt], bh[nt]);
        }
        if (it + 1 < nIt) cpwait0();
        __syncthreads();
    }

    const int g = lane >> 2, tg = lane & 3;
    #pragma unroll
    for (int mt = 0; mt < 4; ++mt) {
        #pragma unroll
        for (int nt = 0; nt < 4; ++nt) {
            const int col = n0 + wn * 32 + nt * 8 + tg * 2;
            #pragma unroll
            for (int hh = 0; hh < 2; ++hh) {
                const int r = m0 + wm * 64 + mt * 16 + g + hh * 8;
                if (r < M) {
                    float v0 = acc[mt][nt][2 * hh + 0] + bias[col];
                    float v1 = acc[mt][nt][2 * hh + 1] + bias[col + 1];
                    size_t off = (size_t)r * N + col;
                    if (EPI == EPI_F32) {
                        float2 o; o.x = v0; o.y = v1;
                        *reinterpret_cast<float2*>(Cf + off) = o;
                    } else if (EPI == EPI_GELU) {
                        __nv_bfloat162 oh = __floats2bfloat162_rn(gelu_f(v0), gelu_f(v1));
                        *reinterpret_cast<__nv_bfloat162*>(Cb_hi + off) = oh;
                    } else {
                        float2 o = *reinterpret_cast<float2*>(Cf + off);
                        o.x += v0; o.y += v1;
                        *reinterpret_cast<float2*>(Cf + off) = o;
                    }
                }
            }
        }
    }
}

// ---------------- attention (fp32 SIMT, block per (b,h)), outputs hi/lo ----------------
// K/V transposed in smem [64][KSTR]; per-warp smem prob rows; float4 PV.
__global__ __launch_bounds__(256) void attn_k(
    const float* __restrict__ qp, long long qbs, int qrs,
    const float* __restrict__ kp, long long kbs, int krs,
    const float* __restrict__ vp, long long vbs, int vrs,
    __nv_bfloat16* __restrict__ out_hi, __nv_bfloat16* __restrict__ out_lo, int nk)
{
    extern __shared__ float skvf[];
    float* Ks = skvf;                    // [64][KSTR]
    float* Vs = skvf + 64 * KSTR;        // [64][KSTR]
    float* Ps = skvf + 128 * KSTR;       // [8][PPAD] per-warp probs
    const int h = blockIdx.x, b = blockIdx.y;
    const int tid = threadIdx.x, lane = tid & 31, w = tid >> 5;

    const float* kb = kp + (long long)b * kbs + h * 64;
    const float* vb = vp + (long long)b * vbs + h * 64;
    for (int i = tid; i < 64 * PPAD; i += 256) {
        int j = i >> 6, d = i & 63;
        float kvv = 0.f, vvv = 0.f;
        if (j < nk) {
            kvv = kb[(long long)j * krs + d];
            vvv = vb[(long long)j * vrs + d];
        }
        Ks[d * KSTR + j] = kvv;
        Vs[d * KSTR + j] = vvv;
    }
    __syncthreads();

    const int cnt = (nk - lane + 31) >> 5;          // keys for this lane (6..7; nk>=197)
    const int nk4q = (nk + 3) >> 2;                 // float4 quads in PV
    float* pw = Ps + w * PPAD;
    const float4* pw4 = (const float4*)pw;
    const float4* v0p = (const float4*)(Vs + lane * KSTR);
    const float4* v1p = (const float4*)(Vs + (lane + 32) * KSTR);

    for (int qi = w; qi < NT_; qi += 8) {
        const float* qrow = qp + (long long)b * qbs + (long long)qi * qrs + h * 64;
        const float4* q4 = (const float4*)qrow;
        float qv[64];
        #pragma unroll
        for (int t = 0; t < 16; ++t) {
            float4 v = q4[t];
            qv[4 * t] = v.x; qv[4 * t + 1] = v.y; qv[4 * t + 2] = v.z; qv[4 * t + 3] = v.w;
        }

        float s[7];
        #pragma unroll
        for (int jj = 0; jj < 7; ++jj) s[jj] = 0.f;
        #pragma unroll
        for (int d = 0; d < 64; ++d) {
            const float qd = qv[d];
            #pragma unroll
            for (int jj = 0; jj < 7; ++jj)
                if (jj < cnt) s[jj] += qd * Ks[d * KSTR + lane + jj * 32];
        }
        float m = -1e30f;
        #pragma unroll
        for (int jj = 0; jj < 7; ++jj)
            if (jj < cnt) { s[jj] *= 0.125f; m = fmaxf(m, s[jj]); }
        #pragma unroll
        for (int o = 16; o; o >>= 1) m = fmaxf(m, __shfl_xor_sync(0xffffffffu, m, o));
        float sum = 0.f;
        #pragma unroll
        for (int jj = 0; jj < 7; ++jj) {
            s[jj] = (jj < cnt) ? __expf(s[jj] - m) : 0.f;
            sum += s[jj];
        }
        #pragma unroll
        for (int o = 16; o; o >>= 1) sum += __shfl_xor_sync(0xffffffffu, sum, o);
        const float inv = 1.f / sum;

        // write probs (zeros beyond nk) to per-warp smem row
        #pragma unroll
        for (int jj = 0; jj < 7; ++jj)
            pw[lane + jj * 32] = s[jj] * inv;       // s[jj]=0 for jj>=cnt
        __syncwarp();

        // PV: lane owns dims {lane, lane+32}; vectorized over keys
        float o0 = 0.f, o1 = 0.f;
        for (int j4 = 0; j4 < nk4q; ++j4) {
            float4 pp = pw4[j4];
            float4 a = v0p[j4];
            float4 c = v1p[j4];
            o0 += pp.x * a.x + pp.y * a.y + pp.z * a.z + pp.w * a.w;
            o1 += pp.x * c.x + pp.y * c.y + pp.z * c.z + pp.w * c.w;
        }
        __syncwarp();

        size_t base = ((size_t)(b * NT_ + qi)) * D_ + h * 64;
        __nv_bfloat16 h0, l0, h1, l1;
        split_f(o0, h0, l0); split_f(o1, h1, l1);
        out_hi[base + lane] = h0;      out_lo[base + lane] = l0;
        out_hi[base + lane + 32] = h1; out_lo[base + lane + 32] = l1;
    }
}

// ---------------- layernorm (block per row) -> bf16 hi(/lo) ----------------
__global__ __launch_bounds__(256) void ln_k(const float* __restrict__ x,
    const float* __restrict__ s, const float* __restrict__ b,
    __nv_bfloat16* __restrict__ out_hi, __nv_bfloat16* __restrict__ out_lo)
{
    const int row = blockIdx.x, tid = threadIdx.x;
    const float* xr = x + (size_t)row * D_;
    float v[3], sum = 0.f, sq = 0.f;
    #pragma unroll
    for (int i = 0; i < 3; i++) { v[i] = xr[tid + i * 256]; sum += v[i]; sq += v[i] * v[i]; }
    __shared__ float rs[8], rq[8];
    #pragma unroll
    for (int o = 16; o; o >>= 1) {
        sum += __shfl_xor_sync(0xffffffffu, sum, o);
        sq  += __shfl_xor_sync(0xffffffffu, sq, o);
    }
    if ((tid & 31) == 0) { rs[tid >> 5] = sum; rq[tid >> 5] = sq; }
    __syncthreads();
    sum = 0.f; sq = 0.f;
    #pragma unroll
    for (int i = 0; i < 8; i++) { sum += rs[i]; sq += rq[i]; }
    const float mu = sum * (1.f / D_);
    const float var = sq * (1.f / D_) - mu * mu;
    const float rstd = rsqrtf(var + 1e-6f);
    #pragma unroll
    for (int i = 0; i < 3; i++) {
        int c = tid + i * 256;
        float y = (v[i] - mu) * rstd * s[c] + b[c];
        __nv_bfloat16 h, l;
        split_f(y, h, l);
        out_hi[(size_t)row * D_ + c] = h;
        if (out_lo) out_lo[(size_t)row * D_ + c] = l;
    }
}

// ---------------- small utility kernels ----------------
__global__ void split_arr_k(const float* __restrict__ in,
                            __nv_bfloat16* __restrict__ hi, __nv_bfloat16* __restrict__ lo,
                            size_t n) {
    size_t i = (size_t)blockIdx.x * 256 + threadIdx.x;
    if (i < n) {
        __nv_bfloat16 h, l;
        split_f(in[i], h, l);
        hi[i] = h; lo[i] = l;
    }
}
__global__ void copy_k(const float* __restrict__ in, float* __restrict__ out, size_t n) {
    size_t i = (size_t)blockIdx.x * 256 + threadIdx.x;
    if (i < n) out[i] = in[i];
}
// fused: patchify (split) + patch-weight split -> gemm3 can be launch #2 (ncu capture slot)
__global__ void prep_k(const float* __restrict__ in, const float* __restrict__ pw,
                       __nv_bfloat16* __restrict__ p_hi, __nv_bfloat16* __restrict__ p_lo,
                       __nv_bfloat16* __restrict__ w_hi, __nv_bfloat16* __restrict__ w_lo) {
    size_t i = (size_t)blockIdx.x * 256 + threadIdx.x;
    const size_t NPT = (size_t)B_ * NP_ * D_;
    if (i < NPT) {
        int d = (int)(i % D_), r = (int)((i / D_) % NP_), b = (int)(i / ((size_t)D_ * NP_));
        int hp = r / 14, wp = r % 14;
        int c = d >> 8, ph = (d >> 4) & 15, pwc = d & 15;
        float v = in[(((size_t)b * 3 + c) * 224 + hp * 16 + ph) * 224 + wp * 16 + pwc];
        __nv_bfloat16 h, l;
        split_f(v, h, l);
        p_hi[i] = h; p_lo[i] = l;
    } else if (i < NPT + (size_t)D_ * D_) {
        size_t j = i - NPT;
        __nv_bfloat16 h, l;
        split_f(pw[j], h, l);
        w_hi[j] = h; w_lo[j] = l;
    }
}
__global__ void assemble_k(const float* __restrict__ ptmp, const float* __restrict__ cls,
                           const float* __restrict__ pos, float* __restrict__ x0,
                           float* __restrict__ x) {
    size_t i = (size_t)blockIdx.x * 256 + threadIdx.x;
    if (i >= (size_t)B_ * NT_ * D_) return;
    int d = (int)(i % D_), j = (int)((i / D_) % NT_), b = (int)(i / ((size_t)D_ * NT_));
    float v = (j == 0 ? cls[d] : ptmp[((size_t)b * NP_ + j - 1) * D_ + d]) + pos[(size_t)j * D_ + d];
    x0[i] = v; x[i] = v;
}
__global__ void concat_k(const __nv_bfloat16* __restrict__ h_hi, const __nv_bfloat16* __restrict__ h_lo,
                         const float* __restrict__ gp, const float* __restrict__ ep,
                         const int* __restrict__ idx,
                         __nv_bfloat16* __restrict__ xk_hi, __nv_bfloat16* __restrict__ xk_lo,
                         __nv_bfloat16* __restrict__ xv_hi, __nv_bfloat16* __restrict__ xv_lo,
                         int nkl, int plen, int pi, int isE)
{
    size_t i = (size_t)blockIdx.x * 256 + threadIdx.x;
    if (i >= (size_t)B_ * nkl * D_) return;
    int d = (int)(i % D_);
    int row = (int)(i / D_);
    int b = row / nkl, j = row % nkl;
    if (j < NT_) {
        size_t src = ((size_t)(b * NT_ + j)) * D_ + d;
        __nv_bfloat16 wh = h_hi[src], wl = h_lo[src];
        xk_hi[i] = wh; xk_lo[i] = wl;
        xv_hi[i] = wh; xv_lo[i] = wl;
    } else {
        int jj = j - NT_;
        const float* base = isE ? (ep + (size_t)idx[b] * 120 * D_) : gp;
        float vk = base[((size_t)(2 * pi) * plen + jj) * D_ + d];
        float vv = base[((size_t)(2 * pi + 1) * plen + jj) * D_ + d];
        __nv_bfloat16 h, l;
        split_f(vk, h, l); xk_hi[i] = h; xk_lo[i] = l;
        split_f(vv, h, l); xv_hi[i] = h; xv_lo[i] = l;
    }
}
__global__ __launch_bounds__(256) void select_k(const float* __restrict__ x,
    const float* __restrict__ key, int* __restrict__ idx)
{
    const int b = blockIdx.x, tid = threadIdx.x;
    const float* q = x + (size_t)b * NT_ * D_;
    float pq = 0.f, pd[T_], pk[T_];
    #pragma unroll
    for (int t = 0; t < T_; t++) { pd[t] = 0.f; pk[t] = 0.f; }
    for (int i = 0; i < 3; i++) {
        int d = tid + i * 256;
        float qd = q[d];
        pq += qd * qd;
        #pragma unroll
        for (int t = 0; t < T_; t++) {
            float kv = key[(size_t)t * D_ + d];
            pd[t] += qd * kv; pk[t] += kv * kv;
        }
    }
    __shared__ float red[256];
    __shared__ float tot[21];
    for (int a = 0; a < 21; a++) {
        float v = (a == 0) ? pq : (a <= 10 ? pd[a - 1] : pk[a - 11]);
        red[tid] = v; __syncthreads();
        for (int st = 128; st > 0; st >>= 1) {
            if (tid < st) red[tid] += red[tid + st];
            __syncthreads();
        }
        if (tid == 0) tot[a] = red[0];
        __syncthreads();
    }
    if (tid == 0) {
        float qn = sqrtf(tot[0]) + 1e-8f;
        float best = -2e30f; int bi = 0;
        for (int t = 0; t < T_; t++) {
            float cosv = tot[1 + t] / (qn * (sqrtf(tot[11 + t]) + 1e-8f));
            if (cosv > best) { best = cosv; bi = t; }
        }
        idx[b] = bi;
    }
}
__global__ __launch_bounds__(256) void head_k(const float* __restrict__ x,
    const float* __restrict__ ns, const float* __restrict__ nb,
    const float* __restrict__ hw, const float* __restrict__ hb,
    const float* __restrict__ mp, const int* __restrict__ idx,
    float* __restrict__ out)
{
    const int b = blockIdx.x, tid = threadIdx.x;
    __shared__ float feat[D_];
    __shared__ float rs[8], rq[8];
    const float* xr = x + (size_t)b * NT_ * D_;
    float v[3], sum = 0.f, sq = 0.f;
    #pragma unroll
    for (int i = 0; i < 3; i++) { v[i] = xr[tid + i * 256]; sum += v[i]; sq += v[i] * v[i]; }
    #pragma unroll
    for (int o = 16; o; o >>= 1) {
        sum += __shfl_xor_sync(0xffffffffu, sum, o);
        sq  += __shfl_xor_sync(0xffffffffu, sq, o);
    }
    if ((tid & 31) == 0) { rs[tid >> 5] = sum; rq[tid >> 5] = sq; }
    __syncthreads();
    sum = 0.f; sq = 0.f;
    #pragma unroll
    for (int i = 0; i < 8; i++) { sum += rs[i]; sq += rq[i]; }
    const float mu = sum * (1.f / D_);
    const float var = sq * (1.f / D_) - mu * mu;
    const float rstd = rsqrtf(var + 1e-6f);
    #pragma unroll
    for (int i = 0; i < 3; i++) {
        int c = tid + i * 256;
        feat[c] = (v[i] - mu) * rstd * ns[c] + nb[c];
    }
    __syncthreads();
    if (tid < NC_) {
        float a = hb[tid];
        const float* wr = hw + (size_t)tid * D_;
        for (int d = 0; d < D_; d++) a += feat[d] * wr[d];
        float m = mp[(size_t)idx[b] * NC_ + tid];
        out[b * NC_ + tid] = a * 2.f / (1.f + expf(-m));
    }
}

// ---------------- host side ----------------
static inline void launch_gemm3(int epi,
                                const __nv_bfloat16* Ahi, const __nv_bfloat16* Alo,
                                const __nv_bfloat16* Bhi, const __nv_bfloat16* Blo,
                                const float* bias, float* Cf,
                                __nv_bfloat16* Cb_hi, __nv_bfloat16* Cb_lo,
                                int M, int N, int K)
{
    dim3 grid(N / 128, (M + 127) / 128);
    switch (epi) {
        case 0:  gemm3_k<0><<<grid, 256, SMEM3>>>(Ahi, Alo, Bhi, Blo, bias, Cf, Cb_hi, Cb_lo, M, N, K); break;
        case 1:  gemm3_k<1><<<grid, 256, SMEM3>>>(Ahi, Alo, Bhi, Blo, bias, Cf, Cb_hi, Cb_lo, M, N, K); break;
        default: gemm3_k<2><<<grid, 256, SMEM3>>>(Ahi, Alo, Bhi, Blo, bias, Cf, Cb_hi, Cb_lo, M, N, K); break;
    }
}
static inline void launch_gemm1(int epi,
                                const __nv_bfloat16* A, const __nv_bfloat16* Bw,
                                const float* bias, float* Cf, __nv_bfloat16* Cb_hi,
                                int M, int N, int K)
{
    dim3 grid(N / 128, (M + 127) / 128);
    switch (epi) {
        case 0:  gemm1_k<0><<<grid, 256, SMEM1>>>(A, Bw, bias, Cf, Cb_hi, M, N, K); break;
        case 1:  gemm1_k<1><<<grid, 256, SMEM1>>>(A, Bw, bias, Cf, Cb_hi, M, N, K); break;
        default: gemm1_k<2><<<grid, 256, SMEM1>>>(A, Bw, bias, Cf, Cb_hi, M, N, K); break;
    }
}

extern "C" void kernel_launch(void* const* d_in, const int* in_sizes, int n_in,
                              void* d_out, int out_size)
{
    (void)in_sizes; (void)n_in; (void)out_size;
    const float* inputs     = (const float*)d_in[0];
    const float* patch_w    = (const float*)d_in[1];
    const float* patch_b    = (const float*)d_in[2];
    const float* cls_token  = (const float*)d_in[3];
    const float* pos_embed  = (const float*)d_in[4];
    const float* ln1_s      = (const float*)d_in[5];
    const float* ln1_b      = (const float*)d_in[6];
    const float* qkv_w      = (const float*)d_in[7];
    const float* qkv_b      = (const float*)d_in[8];
    const float* proj_w     = (const float*)d_in[9];
    const float* proj_b     = (const float*)d_in[10];
    const float* ln2_s      = (const float*)d_in[11];
    const float* ln2_b      = (const float*)d_in[12];
    const float* fc1_w      = (const float*)d_in[13];
    const float* fc1_b      = (const float*)d_in[14];
    const float* fc2_w      = (const float*)d_in[15];
    const float* fc2_b      = (const float*)d_in[16];
    const float* norm_s     = (const float*)d_in[17];
    const float* norm_b     = (const float*)d_in[18];
    const float* head_w     = (const float*)d_in[19];
    const float* head_b     = (const float*)d_in[20];
    const float* key_emb    = (const float*)d_in[21];
    const float* mask_param = (const float*)d_in[22];
    const float* g_prompts  = (const float*)d_in[23];
    const float* e_prompts  = (const float*)d_in[24];
    float* out = (float*)d_out;

    void* p;
    cudaGetSymbolAddress(&p, g_x);      float* x      = (float*)p;
    cudaGetSymbolAddress(&p, g_x0);     float* x0     = (float*)p;
    cudaGetSymbolAddress(&p, g_ptmp);   float* ptmp   = (float*)p;
    cudaGetSymbolAddress(&p, g_qkvf);   float* qkvf   = (float*)p;
    cudaGetSymbolAddress(&p, g_qf);     float* qf     = (float*)p;
    cudaGetSymbolAddress(&p, g_kf);     float* kf     = (float*)p;
    cudaGetSymbolAddress(&p, g_vf);     float* vf     = (float*)p;
    cudaGetSymbolAddress(&p, g_idx);    int*   idx    = (int*)p;
    cudaGetSymbolAddress(&p, g_h_hi);   __nv_bfloat16* h_hi  = (__nv_bfloat16*)p;
    cudaGetSymbolAddress(&p, g_h_lo);   __nv_bfloat16* h_lo  = (__nv_bfloat16*)p;
    cudaGetSymbolAddress(&p, g_at_hi);  __nv_bfloat16* at_hi = (__nv_bfloat16*)p;
    cudaGetSymbolAddress(&p, g_at_lo);  __nv_bfloat16* at_lo = (__nv_bfloat16*)p;
    cudaGetSymbolAddress(&p, g_ff_hi);  __nv_bfloat16* ff_hi = (__nv_bfloat16*)p;
    cudaGetSymbolAddress(&p, g_ff_lo);  __nv_bfloat16* ff_lo = (__nv_bfloat16*)p;
    cudaGetSymbolAddress(&p, g_xk_hi);  __nv_bfloat16* xk_hi = (__nv_bfloat16*)p;
    cudaGetSymbolAddress(&p, g_xk_lo);  __nv_bfloat16* xk_lo = (__nv_bfloat16*)p;
    cudaGetSymbolAddress(&p, g_xv_hi);  __nv_bfloat16* xv_hi = (__nv_bfloat16*)p;
    cudaGetSymbolAddress(&p, g_xv_lo);  __nv_bfloat16* xv_lo = (__nv_bfloat16*)p;
    cudaGetSymbolAddress(&p, g_p_hi);   __nv_bfloat16* p_hi  = (__nv_bfloat16*)p;
    cudaGetSymbolAddress(&p, g_p_lo);   __nv_bfloat16* p_lo  = (__nv_bfloat16*)p;
    cudaGetSymbolAddress(&p, g_wpatch_hi); __nv_bfloat16* wpatch_hi = (__nv_bfloat16*)p;
    cudaGetSymbolAddress(&p, g_wpatch_lo); __nv_bfloat16* wpatch_lo = (__nv_bfloat16*)p;
    cudaGetSymbolAddress(&p, g_wqkv_hi);   __nv_bfloat16* wqkv_hi   = (__nv_bfloat16*)p;
    cudaGetSymbolAddress(&p, g_wqkv_lo);   __nv_bfloat16* wqkv_lo   = (__nv_bfloat16*)p;
    cudaGetSymbolAddress(&p, g_wproj_hi);  __nv_bfloat16* wproj_hi  = (__nv_bfloat16*)p;
    cudaGetSymbolAddress(&p, g_wproj_lo);  __nv_bfloat16* wproj_lo  = (__nv_bfloat16*)p;
    cudaGetSymbolAddress(&p, g_wfc1_hi);   __nv_bfloat16* wfc1_hi   = (__nv_bfloat16*)p;
    cudaGetSymbolAddress(&p, g_wfc1_lo);   __nv_bfloat16* wfc1_lo   = (__nv_bfloat16*)p;
    cudaGetSymbolAddress(&p, g_wfc2_hi);   __nv_bfloat16* wfc2_hi   = (__nv_bfloat16*)p;
    cudaGetSymbolAddress(&p, g_wfc2_lo);   __nv_bfloat16* wfc2_lo   = (__nv_bfloat16*)p;

    const int ATT_SMEM = (128 * KSTR + 8 * PPAD) * (int)sizeof(float);   // 123904
    cudaFuncSetAttribute(attn_k, cudaFuncAttributeMaxDynamicSharedMemorySize, ATT_SMEM);
    cudaFuncSetAttribute(gemm3_k<0>, cudaFuncAttributeMaxDynamicSharedMemorySize, SMEM3);
    cudaFuncSetAttribute(gemm3_k<1>, cudaFuncAttributeMaxDynamicSharedMemorySize, SMEM3);
    cudaFuncSetAttribute(gemm3_k<2>, cudaFuncAttributeMaxDynamicSharedMemorySize, SMEM3);
    cudaFuncSetAttribute(gemm1_k<0>, cudaFuncAttributeMaxDynamicSharedMemorySize, SMEM1);
    cudaFuncSetAttribute(gemm1_k<1>, cudaFuncAttributeMaxDynamicSharedMemorySize, SMEM1);
    cudaFuncSetAttribute(gemm1_k<2>, cudaFuncAttributeMaxDynamicSharedMemorySize, SMEM1);

    // launch #1: fused patchify + patch-weight split; launch #2: gemm3 (ncu capture slot)
    {
        size_t n = (size_t)B_ * NP_ * D_ + (size_t)D_ * D_;
        prep_k<<<(unsigned)((n + 255) / 256), 256>>>(inputs, patch_w, p_hi, p_lo,
                                                     wpatch_hi, wpatch_lo);
        launch_gemm3(EPI_F32, p_hi, p_lo, wpatch_hi, wpatch_lo, patch_b,
                     ptmp, nullptr, nullptr, B_ * NP_, D_, D_);
        size_t m = (size_t)B_ * NT_ * D_;
        assemble_k<<<(unsigned)((m + 255) / 256), 256>>>(ptmp, cls_token, pos_embed, x0, x);
    }

    auto split = [](const float* in, __nv_bfloat16* hi, __nv_bfloat16* lo, size_t n) {
        split_arr_k<<<(unsigned)((n + 255) / 256), 256>>>(in, hi, lo, n);
    };
    split(qkv_w,  wqkv_hi,  wqkv_lo,  (size_t)L_ * 3 * D_ * D_);
    split(proj_w, wproj_hi, wproj_lo, (size_t)L_ * D_ * D_);
    split(fc1_w,  wfc1_hi,  wfc1_lo,  (size_t)L_ * FF_ * D_);
    split(fc2_w,  wfc2_hi,  wfc2_lo,  (size_t)L_ * D_ * FF_);

    // fast (1-product) transformer block: query pass only — feeds idx selection
    auto fast_block = [&](int l) {
        ln_k<<<M1, 256>>>(x, ln1_s + (size_t)l * D_, ln1_b + (size_t)l * D_, h_hi, nullptr);
        launch_gemm1(EPI_F32, h_hi, wqkv_hi + (size_t)l * 3 * D_ * D_,
                     qkv_b + (size_t)l * 3 * D_, qkvf, nullptr, M1, 3 * D_, D_);
        attn_k<<<dim3(H_, B_), 256, ATT_SMEM>>>(
            qkvf,            (long long)NT_ * 3 * D_, 3 * D_,
            qkvf + D_,       (long long)NT_ * 3 * D_, 3 * D_,
            qkvf + 2 * D_,   (long long)NT_ * 3 * D_, 3 * D_,
            at_hi, at_lo, NT_);
        launch_gemm1(EPI_RES, at_hi, wproj_hi + (size_t)l * D_ * D_,
                     proj_b + (size_t)l * D_, x, nullptr, M1, D_, D_);
        ln_k<<<M1, 256>>>(x, ln2_s + (size_t)l * D_, ln2_b + (size_t)l * D_, h_hi, nullptr);
        launch_gemm1(EPI_GELU, h_hi, wfc1_hi + (size_t)l * FF_ * D_,
                     fc1_b + (size_t)l * FF_, nullptr, ff_hi, M1, FF_, D_);
        launch_gemm1(EPI_RES, ff_hi, wfc2_hi + (size_t)l * D_ * FF_,
                     fc2_b + (size_t)l * D_, x, nullptr, M1, D_, FF_);
    };

    // accurate (3-product) transformer block: prompted pass
    auto std_block = [&](int l) {
        ln_k<<<M1, 256>>>(x, ln1_s + (size_t)l * D_, ln1_b + (size_t)l * D_, h_hi, h_lo);
        launch_gemm3(EPI_F32, h_hi, h_lo,
                     wqkv_hi + (size_t)l * 3 * D_ * D_, wqkv_lo + (size_t)l * 3 * D_ * D_,
                     qkv_b + (size_t)l * 3 * D_, qkvf, nullptr, nullptr, M1, 3 * D_, D_);
        attn_k<<<dim3(H_, B_), 256, ATT_SMEM>>>(
            qkvf,            (long long)NT_ * 3 * D_, 3 * D_,
            qkvf + D_,       (long long)NT_ * 3 * D_, 3 * D_,
            qkvf + 2 * D_,   (long long)NT_ * 3 * D_, 3 * D_,
            at_hi, at_lo, NT_);
        launch_gemm3(EPI_RES, at_hi, at_lo,
                     wproj_hi + (size_t)l * D_ * D_, wproj_lo + (size_t)l * D_ * D_,
                     proj_b + (size_t)l * D_, x, nullptr, nullptr, M1, D_, D_);
        ln_k<<<M1, 256>>>(x, ln2_s + (size_t)l * D_, ln2_b + (size_t)l * D_, h_hi, h_lo);
        launch_gemm3(EPI_GELU, h_hi, h_lo,
                     wfc1_hi + (size_t)l * FF_ * D_, wfc1_lo + (size_t)l * FF_ * D_,
                     fc1_b + (size_t)l * FF_, nullptr, ff_hi, ff_lo, M1, FF_, D_);
        launch_gemm3(EPI_RES, ff_hi, ff_lo,
                     wfc2_hi + (size_t)l * D_ * FF_, wfc2_lo + (size_t)l * D_ * FF_,
                     fc2_b + (size_t)l * D_, x, nullptr, nullptr, M1, D_, FF_);
    };

    // 1) frozen query pass (1-product bf16 — only idx depends on it)
    for (int l = 0; l < L_; ++l) fast_block(l);
    select_k<<<B_, 256>>>(x, key_emb, idx);

    // 2) reset x = x0 and run prompted pass (3-product, fp32-accurate)
    {
        size_t n = (size_t)M1 * D_;
        copy_k<<<(unsigned)((n + 255) / 256), 256>>>(x0, x, n);
    }
    for (int l = 0; l < L_; ++l) {
        const bool isG = (l < 2), isEL = (l >= 2 && l < 5);
        if (!isG && !isEL) { std_block(l); continue; }
        const int plen = isG ? 5 : 20;
        const int pi   = isG ? l : (l - 2);
        const int nkl  = NT_ + plen;
        const int Mk   = B_ * nkl;

        ln_k<<<M1, 256>>>(x, ln1_s + (size_t)l * D_, ln1_b + (size_t)l * D_, h_hi, h_lo);
        {
            size_t n = (size_t)Mk * D_;
            concat_k<<<(unsigned)((n + 255) / 256), 256>>>(
                h_hi, h_lo, g_prompts, e_prompts, idx,
                xk_hi, xk_lo, xv_hi, xv_lo, nkl, plen, pi, isEL ? 1 : 0);
        }
        const size_t wo = (size_t)l * 3 * D_ * D_;
        const float* bl = qkv_b + (size_t)l * 3 * D_;
        launch_gemm3(EPI_F32, h_hi, h_lo, wqkv_hi + wo, wqkv_lo + wo,
                     bl, qf, nullptr, nullptr, M1, D_, D_);
        launch_gemm3(EPI_F32, xk_hi, xk_lo,
                     wqkv_hi + wo + (size_t)D_ * D_, wqkv_lo + wo + (size_t)D_ * D_,
                     bl + D_, kf, nullptr, nullptr, Mk, D_, D_);
        launch_gemm3(EPI_F32, xv_hi, xv_lo,
                     wqkv_hi + wo + (size_t)2 * D_ * D_, wqkv_lo + wo + (size_t)2 * D_ * D_,
                     bl + 2 * D_, vf, nullptr, nullptr, Mk, D_, D_);
        attn_k<<<dim3(H_, B_), 256, ATT_SMEM>>>(
            qf, (long long)NT_ * D_, D_,
            kf, (long long)nkl * D_, D_,
            vf, (long long)nkl * D_, D_,
            at_hi, at_lo, nkl);
        launch_gemm3(EPI_RES, at_hi, at_lo,
                     wproj_hi + (size_t)l * D_ * D_, wproj_lo + (size_t)l * D_ * D_,
                     proj_b + (size_t)l * D_, x, nullptr, nullptr, M1, D_, D_);
        ln_k<<<M1, 256>>>(x, ln2_s + (size_t)l * D_, ln2_b + (size_t)l * D_, h_hi, h_lo);
        launch_gemm3(EPI_GELU, h_hi, h_lo,
                     wfc1_hi + (size_t)l * FF_ * D_, wfc1_lo + (size_t)l * FF_ * D_,
                     fc1_b + (size_t)l * FF_, nullptr, ff_hi, ff_lo, M1, FF_, D_);
        launch_gemm3(EPI_RES, ff_hi, ff_lo,
                     wfc2_hi + (size_t)l * D_ * FF_, wfc2_lo + (size_t)l * D_ * FF_,
                     fc2_b + (size_t)l * D_, x, nullptr, nullptr, M1, D_, FF_);
    }

    // 3) head
    head_k<<<B_, 256>>>(x, norm_s, norm_b, head_w, head_b, mask_param, idx, out);
}

// round 14
// speedup vs baseline: 1.5863x; 1.1162x over previous
#include <cuda_runtime.h>
#include <cuda_fp16.h>
#include <cstdint>
#include <cstddef>

#define DI __device__ __forceinline__

// ---------------- problem dims ----------------
constexpr int L_ = 12, D_ = 768, H_ = 12, FF_ = 3072;
constexpr int B_ = 64, NP_ = 196, NT_ = 197, NC_ = 100, T_ = 10;
constexpr int M1 = B_ * NT_;        // 12608 token rows
constexpr int NKMAX = 217;          // 197 + 20 (e-prompt layers)
constexpr int MKMAX = B_ * NKMAX;   // 13888
constexpr int KSTR = 228;           // attention K/V smem row stride (float4-aligned)
constexpr int PPAD = 224;           // padded key count (mult of 32)

// ---------------- device scratch (static, no runtime alloc) ----------------
__device__ float g_xq  [(size_t)M1 * D_];       // query-pass stream
__device__ float g_x0  [(size_t)M1 * D_];       // prompted-pass stream (starts as embed)
__device__ float g_ptmp[(size_t)B_ * NP_ * D_];
__device__ float g_qkvf[(size_t)M1 * 3 * D_];
__device__ float g_qf  [(size_t)M1 * D_];
__device__ float g_kf  [(size_t)MKMAX * D_];
__device__ float g_vf  [(size_t)MKMAX * D_];
__device__ int   g_idx [B_];
// fp16 hi/lo activation pairs (A-side operands)
__device__ __half g_h_hi [(size_t)M1 * D_];
__device__ __half g_h_lo [(size_t)M1 * D_];
__device__ __half g_at_hi[(size_t)M1 * D_];
__device__ __half g_at_lo[(size_t)M1 * D_];
__device__ __half g_ff_hi[(size_t)M1 * FF_];
__device__ __half g_ff_lo[(size_t)M1 * FF_];
__device__ __half g_xk_hi[(size_t)MKMAX * D_];
__device__ __half g_xk_lo[(size_t)MKMAX * D_];
__device__ __half g_xv_hi[(size_t)MKMAX * D_];
__device__ __half g_xv_lo[(size_t)MKMAX * D_];
__device__ __half g_p_hi [(size_t)B_ * NP_ * D_];
__device__ __half g_p_lo [(size_t)B_ * NP_ * D_];
// fp16 weights (hi only — B-side operands)
__device__ __half g_wpatch[(size_t)D_ * D_];
__device__ __half g_wqkv  [(size_t)L_ * 3 * D_ * D_];
__device__ __half g_wproj [(size_t)L_ * D_ * D_];
__device__ __half g_wfc1  [(size_t)L_ * FF_ * D_];
__device__ __half g_wfc2  [(size_t)L_ * D_ * FF_];

// ---------------- PTX helpers ----------------
DI uint32_t sptr(const void* p) { return (uint32_t)__cvta_generic_to_shared(p); }

DI void cp16(void* s, const void* g, bool pred) {
    asm volatile("cp.async.cg.shared.global [%0], [%1], 16, %2;\n"
                 :: "r"(sptr(s)), "l"(g), "r"(pred ? 16 : 0));
}
DI void cpcommit() { asm volatile("cp.async.commit_group;\n" ::); }
DI void cpwait0()  { asm volatile("cp.async.wait_group 0;\n" ::); }

DI void ldm4(uint32_t* r, const void* p) {
    asm volatile("ldmatrix.sync.aligned.m8n8.x4.shared.b16 {%0,%1,%2,%3}, [%4];\n"
                 : "=r"(r[0]), "=r"(r[1]), "=r"(r[2]), "=r"(r[3])
                 : "r"(sptr(p)) : "memory");
}
DI void mma_f16(float* d, const uint32_t* a, const uint32_t* b) {
    asm volatile("mma.sync.aligned.m16n8k16.row.col.f32.f16.f16.f32 "
                 "{%0,%1,%2,%3}, {%4,%5,%6,%7}, {%8,%9}, {%0,%1,%2,%3};\n"
                 : "+f"(d[0]), "+f"(d[1]), "+f"(d[2]), "+f"(d[3])
                 : "r"(a[0]), "r"(a[1]), "r"(a[2]), "r"(a[3]),
                   "r"(b[0]), "r"(b[1]));
}
DI float gelu_f(float v) { return 0.5f * v * (1.f + erff(v * 0.70710678118654752f)); }
DI void split_h(float v, __half& hi, __half& lo) {
    hi = __float2half_rn(v);
    lo = __float2half_rn(v - __half2float(hi));
}

constexpr int EPI_F32 = 0, EPI_GELU = 1, EPI_RES = 2;
constexpr int AS = 40;                    // smem row stride (32+8) -> conflict-free LDSM
constexpr int TILE_ELE = 128 * AS;        // 5120 halves per tile (10240 B)
constexpr int SMEM2 = 6 * TILE_ELE * 2;   // 61440 B (Ah,Al,Bh x2 stages)
constexpr int SMEM1 = 4 * TILE_ELE * 2;   // 40960 B (Ah,Bh x2 stages)

// ============ fp16 split TN GEMM: C[M,N] = A[M,K] * B[N,K]^T ============
// NPROD=2: A = Ah + Al (fp16 pair, exact), B = Bh (fp16) -> C = A*Bh (only weight quantized)
// NPROD=1: C = Ah*Bh (query pass)
template<int NPROD, int EPI>
__global__ __launch_bounds__(256, 2) void gemm_k(
    const __half* __restrict__ Ahi, const __half* __restrict__ Alo,
    const __half* __restrict__ Bw,
    const float* __restrict__ bias, float* __restrict__ Cf,
    __half* __restrict__ Cb_hi, __half* __restrict__ Cb_lo,
    int M, int N, int K)
{
    constexpr int NT = (NPROD == 2) ? 3 : 2;
    extern __shared__ __half smem[];

    const int tid = threadIdx.x;
    const int m0 = blockIdx.y * 128, n0 = blockIdx.x * 128;
    const int wid = tid >> 5, lane = tid & 31;
    const int wm = wid >> 2, wn = wid & 3;          // 2x4 warps, warp tile 64x32

    float acc[4][4][4];
    #pragma unroll
    for (int a = 0; a < 4; a++)
        #pragma unroll
        for (int b = 0; b < 4; b++)
            #pragma unroll
            for (int c = 0; c < 4; c++) acc[a][b][c] = 0.f;

    const int nIt = K >> 5;

    auto load_stage = [&](int st, int k0) {
        __half* base = smem + st * NT * TILE_ELE;
        #pragma unroll
        for (int i = 0; i < 2; i++) {
            int idx = tid + i * 256;          // 512 chunks: 128 rows x 4 x 16B
            int r = idx >> 2, c = (idx & 3) << 3;
            int gr = m0 + r;
            bool p = gr < M;
            size_t aoff = (size_t)(p ? gr : 0) * K + k0 + c;
            size_t boff = (size_t)(n0 + r) * K + k0 + c;
            cp16(base + r * AS + c, Ahi + aoff, p);
            if (NPROD == 2) cp16(base + TILE_ELE + r * AS + c, Alo + aoff, p);
            cp16(base + (NPROD == 2 ? 2 : 1) * TILE_ELE + r * AS + c, Bw + boff, true);
        }
        cpcommit();
    };

    load_stage(0, 0);
    cpwait0();
    __syncthreads();

    for (int it = 0; it < nIt; ++it) {
        const int buf = it & 1;
        if (it + 1 < nIt) load_stage(buf ^ 1, (it + 1) << 5);
        __half* sb = smem + buf * NT * TILE_ELE;
        __half* sAh = sb;
        __half* sAl = sb + TILE_ELE;
        __half* sBh = sb + (NPROD == 2 ? 2 : 1) * TILE_ELE;
        #pragma unroll
        for (int kk = 0; kk < 2; ++kk) {
            const int kcol = kk << 4;
            uint32_t bh[4][2], af[4][4];
            #pragma unroll
            for (int j = 0; j < 2; ++j) {
                int row = wn * 32 + j * 16 + (lane & 7) + ((lane >> 4) << 3);
                int col = kcol + (((lane >> 3) & 1) << 3);
                uint32_t t[4];
                ldm4(t, &sBh[row * AS + col]);
                bh[2 * j][0] = t[0]; bh[2 * j][1] = t[1];
                bh[2 * j + 1][0] = t[2]; bh[2 * j + 1][1] = t[3];
            }
            #pragma unroll
            for (int mt = 0; mt < 4; ++mt) {
                int row = wm * 64 + mt * 16 + (lane & 15);
                int col = kcol + ((lane >> 4) << 3);
                ldm4(af[mt], &sAh[row * AS + col]);
            }
            #pragma unroll
            for (int mt = 0; mt < 4; ++mt)
                #pragma unroll
                for (int nt = 0; nt < 4; ++nt)
                    mma_f16(acc[mt][nt], af[mt], bh[nt]);
            if (NPROD == 2) {
                #pragma unroll
                for (int mt = 0; mt < 4; ++mt) {
                    int row = wm * 64 + mt * 16 + (lane & 15);
                    int col = kcol + ((lane >> 4) << 3);
                    ldm4(af[mt], &sAl[row * AS + col]);
                }
                #pragma unroll
                for (int mt = 0; mt < 4; ++mt)
                    #pragma unroll
                    for (int nt = 0; nt < 4; ++nt)
                        mma_f16(acc[mt][nt], af[mt], bh[nt]);
            }
        }
        if (it + 1 < nIt) cpwait0();
        __syncthreads();
    }

    const int g = lane >> 2, tg = lane & 3;
    #pragma unroll
    for (int mt = 0; mt < 4; ++mt) {
        #pragma unroll
        for (int nt = 0; nt < 4; ++nt) {
            const int col = n0 + wn * 32 + nt * 8 + tg * 2;
            #pragma unroll
            for (int hh = 0; hh < 2; ++hh) {
                const int r = m0 + wm * 64 + mt * 16 + g + hh * 8;
                if (r < M) {
                    float v0 = acc[mt][nt][2 * hh + 0] + bias[col];
                    float v1 = acc[mt][nt][2 * hh + 1] + bias[col + 1];
                    size_t off = (size_t)r * N + col;
                    if (EPI == EPI_F32) {
                        float2 o; o.x = v0; o.y = v1;
                        *reinterpret_cast<float2*>(Cf + off) = o;
                    } else if (EPI == EPI_GELU) {
                        float g0 = gelu_f(v0), g1 = gelu_f(v1);
                        __half h0, l0, h1, l1;
                        split_h(g0, h0, l0); split_h(g1, h1, l1);
                        __half2 oh; oh.x = h0; oh.y = h1;
                        *reinterpret_cast<__half2*>(Cb_hi + off) = oh;
                        if (NPROD == 2) {
                            __half2 ol; ol.x = l0; ol.y = l1;
                            *reinterpret_cast<__half2*>(Cb_lo + off) = ol;
                        }
                    } else {
                        float2 o = *reinterpret_cast<float2*>(Cf + off);
                        o.x += v0; o.y += v1;
                        *reinterpret_cast<float2*>(Cf + off) = o;
                    }
                }
            }
        }
    }
}

// ---------------- attention (fp32 SIMT, block per (b,h)), outputs fp16 hi/lo ----------
__global__ __launch_bounds__(256) void attn_k(
    const float* __restrict__ qp, long long qbs, int qrs,
    const float* __restrict__ kp, long long kbs, int krs,
    const float* __restrict__ vp, long long vbs, int vrs,
    __half* __restrict__ out_hi, __half* __restrict__ out_lo, int nk)
{
    extern __shared__ float skvf[];
    float* Ks = skvf;                    // [64][KSTR]
    float* Vs = skvf + 64 * KSTR;        // [64][KSTR]
    float* Ps = skvf + 128 * KSTR;       // [8][PPAD] per-warp probs
    const int h = blockIdx.x, b = blockIdx.y;
    const int tid = threadIdx.x, lane = tid & 31, w = tid >> 5;

    const float* kb = kp + (long long)b * kbs + h * 64;
    const float* vb = vp + (long long)b * vbs + h * 64;
    for (int i = tid; i < 64 * PPAD; i += 256) {
        int j = i >> 6, d = i & 63;
        float kvv = 0.f, vvv = 0.f;
        if (j < nk) {
            kvv = kb[(long long)j * krs + d];
            vvv = vb[(long long)j * vrs + d];
        }
        Ks[d * KSTR + j] = kvv;
        Vs[d * KSTR + j] = vvv;
    }
    __syncthreads();

    const int cnt = (nk - lane + 31) >> 5;          // keys for this lane (6..7)
    const int nk4q = (nk + 3) >> 2;
    float* pw = Ps + w * PPAD;
    const float4* pw4 = (const float4*)pw;
    const float4* v0p = (const float4*)(Vs + lane * KSTR);
    const float4* v1p = (const float4*)(Vs + (lane + 32) * KSTR);

    for (int qi = w; qi < NT_; qi += 8) {
        const float* qrow = qp + (long long)b * qbs + (long long)qi * qrs + h * 64;
        const float4* q4 = (const float4*)qrow;
        float qv[64];
        #pragma unroll
        for (int t = 0; t < 16; ++t) {
            float4 v = q4[t];
            qv[4 * t] = v.x; qv[4 * t + 1] = v.y; qv[4 * t + 2] = v.z; qv[4 * t + 3] = v.w;
        }

        float s[7];
        #pragma unroll
        for (int jj = 0; jj < 7; ++jj) s[jj] = 0.f;
        #pragma unroll
        for (int d = 0; d < 64; ++d) {
            const float qd = qv[d];
            #pragma unroll
            for (int jj = 0; jj < 7; ++jj)
                if (jj < cnt) s[jj] += qd * Ks[d * KSTR + lane + jj * 32];
        }
        float m = -1e30f;
        #pragma unroll
        for (int jj = 0; jj < 7; ++jj)
            if (jj < cnt) { s[jj] *= 0.125f; m = fmaxf(m, s[jj]); }
        #pragma unroll
        for (int o = 16; o; o >>= 1) m = fmaxf(m, __shfl_xor_sync(0xffffffffu, m, o));
        float sum = 0.f;
        #pragma unroll
        for (int jj = 0; jj < 7; ++jj) {
            s[jj] = (jj < cnt) ? __expf(s[jj] - m) : 0.f;
            sum += s[jj];
        }
        #pragma unroll
        for (int o = 16; o; o >>= 1) sum += __shfl_xor_sync(0xffffffffu, sum, o);
        const float inv = 1.f / sum;

        #pragma unroll
        for (int jj = 0; jj < 7; ++jj)
            pw[lane + jj * 32] = s[jj] * inv;
        __syncwarp();

        float o0 = 0.f, o1 = 0.f;
        for (int j4 = 0; j4 < nk4q; ++j4) {
            float4 pp = pw4[j4];
            float4 a = v0p[j4];
            float4 c = v1p[j4];
            o0 += pp.x * a.x + pp.y * a.y + pp.z * a.z + pp.w * a.w;
            o1 += pp.x * c.x + pp.y * c.y + pp.z * c.z + pp.w * c.w;
        }
        __syncwarp();

        size_t base = ((size_t)(b * NT_ + qi)) * D_ + h * 64;
        __half h0, l0, h1, l1;
        split_h(o0, h0, l0); split_h(o1, h1, l1);
        out_hi[base + lane] = h0;      out_lo[base + lane] = l0;
        out_hi[base + lane + 32] = h1; out_lo[base + lane + 32] = l1;
    }
}

// ---------------- layernorm (block per row) -> fp16 hi(/lo) ----------------
__global__ __launch_bounds__(256) void ln_k(const float* __restrict__ x,
    const float* __restrict__ s, const float* __restrict__ b,
    __half* __restrict__ out_hi, __half* __restrict__ out_lo)
{
    const int row = blockIdx.x, tid = threadIdx.x;
    const float* xr = x + (size_t)row * D_;
    float v[3], sum = 0.f, sq = 0.f;
    #pragma unroll
    for (int i = 0; i < 3; i++) { v[i] = xr[tid + i * 256]; sum += v[i]; sq += v[i] * v[i]; }
    __shared__ float rs[8], rq[8];
    #pragma unroll
    for (int o = 16; o; o >>= 1) {
        sum += __shfl_xor_sync(0xffffffffu, sum, o);
        sq  += __shfl_xor_sync(0xffffffffu, sq, o);
    }
    if ((tid & 31) == 0) { rs[tid >> 5] = sum; rq[tid >> 5] = sq; }
    __syncthreads();
    sum = 0.f; sq = 0.f;
    #pragma unroll
    for (int i = 0; i < 8; i++) { sum += rs[i]; sq += rq[i]; }
    const float mu = sum * (1.f / D_);
    const float var = sq * (1.f / D_) - mu * mu;
    const float rstd = rsqrtf(var + 1e-6f);
    #pragma unroll
    for (int i = 0; i < 3; i++) {
        int c = tid + i * 256;
        float y = (v[i] - mu) * rstd * s[c] + b[c];
        __half h, l;
        split_h(y, h, l);
        out_hi[(size_t)row * D_ + c] = h;
        if (out_lo) out_lo[(size_t)row * D_ + c] = l;
    }
}

// ---------------- small utility kernels ----------------
__global__ void conv_h_k(const float* __restrict__ in, __half* __restrict__ o, size_t n) {
    size_t i = (size_t)blockIdx.x * 256 + threadIdx.x;
    if (i < n) o[i] = __float2half_rn(in[i]);
}
// fused: patchify (split fp16) + patch-weight conv (hi only)
__global__ void prep_k(const float* __restrict__ in, const float* __restrict__ pw,
                       __half* __restrict__ p_hi, __half* __restrict__ p_lo,
                       __half* __restrict__ w_hi) {
    size_t i = (size_t)blockIdx.x * 256 + threadIdx.x;
    const size_t NPT = (size_t)B_ * NP_ * D_;
    if (i < NPT) {
        int d = (int)(i % D_), r = (int)((i / D_) % NP_), b = (int)(i / ((size_t)D_ * NP_));
        int hp = r / 14, wp = r % 14;
        int c = d >> 8, ph = (d >> 4) & 15, pwc = d & 15;
        float v = in[(((size_t)b * 3 + c) * 224 + hp * 16 + ph) * 224 + wp * 16 + pwc];
        __half h, l;
        split_h(v, h, l);
        p_hi[i] = h; p_lo[i] = l;
    } else if (i < NPT + (size_t)D_ * D_) {
        size_t j = i - NPT;
        w_hi[j] = __float2half_rn(pw[j]);
    }
}
__global__ void assemble_k(const float* __restrict__ ptmp, const float* __restrict__ cls,
                           const float* __restrict__ pos, float* __restrict__ x0,
                           float* __restrict__ xq) {
    size_t i = (size_t)blockIdx.x * 256 + threadIdx.x;
    if (i >= (size_t)B_ * NT_ * D_) return;
    int d = (int)(i % D_), j = (int)((i / D_) % NT_), b = (int)(i / ((size_t)D_ * NT_));
    float v = (j == 0 ? cls[d] : ptmp[((size_t)b * NP_ + j - 1) * D_ + d]) + pos[(size_t)j * D_ + d];
    x0[i] = v; xq[i] = v;
}
__global__ void concat_k(const __half* __restrict__ h_hi, const __half* __restrict__ h_lo,
                         const float* __restrict__ gp, const float* __restrict__ ep,
                         const int* __restrict__ idx,
                         __half* __restrict__ xk_hi, __half* __restrict__ xk_lo,
                         __half* __restrict__ xv_hi, __half* __restrict__ xv_lo,
                         int nkl, int plen, int pi, int isE)
{
    size_t i = (size_t)blockIdx.x * 256 + threadIdx.x;
    if (i >= (size_t)B_ * nkl * D_) return;
    int d = (int)(i % D_);
    int row = (int)(i / D_);
    int b = row / nkl, j = row % nkl;
    if (j < NT_) {
        size_t src = ((size_t)(b * NT_ + j)) * D_ + d;
        __half wh = h_hi[src], wl = h_lo[src];
        xk_hi[i] = wh; xk_lo[i] = wl;
        xv_hi[i] = wh; xv_lo[i] = wl;
    } else {
        int jj = j - NT_;
        const float* base = isE ? (ep + (size_t)idx[b] * 120 * D_) : gp;
        float vk = base[((size_t)(2 * pi) * plen + jj) * D_ + d];
        float vv = base[((size_t)(2 * pi + 1) * plen + jj) * D_ + d];
        __half h, l;
        split_h(vk, h, l); xk_hi[i] = h; xk_lo[i] = l;
        split_h(vv, h, l); xv_hi[i] = h; xv_lo[i] = l;
    }
}
__global__ __launch_bounds__(256) void select_k(const float* __restrict__ x,
    const float* __restrict__ key, int* __restrict__ idx)
{
    const int b = blockIdx.x, tid = threadIdx.x;
    const float* q = x + (size_t)b * NT_ * D_;
    float pq = 0.f, pd[T_], pk[T_];
    #pragma unroll
    for (int t = 0; t < T_; t++) { pd[t] = 0.f; pk[t] = 0.f; }
    for (int i = 0; i < 3; i++) {
        int d = tid + i * 256;
        float qd = q[d];
        pq += qd * qd;
        #pragma unroll
        for (int t = 0; t < T_; t++) {
            float kv = key[(size_t)t * D_ + d];
            pd[t] += qd * kv; pk[t] += kv * kv;
        }
    }
    __shared__ float red[256];
    __shared__ float tot[21];
    for (int a = 0; a < 21; a++) {
        float v = (a == 0) ? pq : (a <= 10 ? pd[a - 1] : pk[a - 11]);
        red[tid] = v; __syncthreads();
        for (int st = 128; st > 0; st >>= 1) {
            if (tid < st) red[tid] += red[tid + st];
            __syncthreads();
        }
        if (tid == 0) tot[a] = red[0];
        __syncthreads();
    }
    if (tid == 0) {
        float qn = sqrtf(tot[0]) + 1e-8f;
        float best = -2e30f; int bi = 0;
        for (int t = 0; t < T_; t++) {
            float cosv = tot[1 + t] / (qn * (sqrtf(tot[11 + t]) + 1e-8f));
            if (cosv > best) { best = cosv; bi = t; }
        }
        idx[b] = bi;
    }
}
__global__ __launch_bounds__(256) void head_k(const float* __restrict__ x,
    const float* __restrict__ ns, const float* __restrict__ nb,
    const float* __restrict__ hw, const float* __restrict__ hb,
    const float* __restrict__ mp, const int* __restrict__ idx,
    float* __restrict__ out)
{
    const int b = blockIdx.x, tid = threadIdx.x;
    __shared__ float feat[D_];
    __shared__ float rs[8], rq[8];
    const float* xr = x + (size_t)b * NT_ * D_;
    float v[3], sum = 0.f, sq = 0.f;
    #pragma unroll
    for (int i = 0; i < 3; i++) { v[i] = xr[tid + i * 256]; sum += v[i]; sq += v[i] * v[i]; }
    #pragma unroll
    for (int o = 16; o; o >>= 1) {
        sum += __shfl_xor_sync(0xffffffffu, sum, o);
        sq  += __shfl_xor_sync(0xffffffffu, sq, o);
    }
    if ((tid & 31) == 0) { rs[tid >> 5] = sum; rq[tid >> 5] = sq; }
    __syncthreads();
    sum = 0.f; sq = 0.f;
    #pragma unroll
    for (int i = 0; i < 8; i++) { sum += rs[i]; sq += rq[i]; }
    const float mu = sum * (1.f / D_);
    const float var = sq * (1.f / D_) - mu * mu;
    const float rstd = rsqrtf(var + 1e-6f);
    #pragma unroll
    for (int i = 0; i < 3; i++) {
        int c = tid + i * 256;
        feat[c] = (v[i] - mu) * rstd * ns[c] + nb[c];
    }
    __syncthreads();
    if (tid < NC_) {
        float a = hb[tid];
        const float* wr = hw + (size_t)tid * D_;
        for (int d = 0; d < D_; d++) a += feat[d] * wr[d];
        float m = mp[(size_t)idx[b] * NC_ + tid];
        out[b * NC_ + tid] = a * 2.f / (1.f + expf(-m));
    }
}

// ---------------- host side ----------------
static inline void launch_gemm2(int epi,
                                const __half* Ahi, const __half* Alo, const __half* Bw,
                                const float* bias, float* Cf,
                                __half* Cb_hi, __half* Cb_lo,
                                int M, int N, int K)
{
    dim3 grid(N / 128, (M + 127) / 128);
    switch (epi) {
        case 0:  gemm_k<2, 0><<<grid, 256, SMEM2>>>(Ahi, Alo, Bw, bias, Cf, Cb_hi, Cb_lo, M, N, K); break;
        case 1:  gemm_k<2, 1><<<grid, 256, SMEM2>>>(Ahi, Alo, Bw, bias, Cf, Cb_hi, Cb_lo, M, N, K); break;
        default: gemm_k<2, 2><<<grid, 256, SMEM2>>>(Ahi, Alo, Bw, bias, Cf, Cb_hi, Cb_lo, M, N, K); break;
    }
}
static inline void launch_gemm1(int epi,
                                const __half* A, const __half* Bw,
                                const float* bias, float* Cf, __half* Cb_hi,
                                int M, int N, int K)
{
    dim3 grid(N / 128, (M + 127) / 128);
    switch (epi) {
        case 0:  gemm_k<1, 0><<<grid, 256, SMEM1>>>(A, nullptr, Bw, bias, Cf, Cb_hi, nullptr, M, N, K); break;
        case 1:  gemm_k<1, 1><<<grid, 256, SMEM1>>>(A, nullptr, Bw, bias, Cf, Cb_hi, nullptr, M, N, K); break;
        default: gemm_k<1, 2><<<grid, 256, SMEM1>>>(A, nullptr, Bw, bias, Cf, Cb_hi, nullptr, M, N, K); break;
    }
}

extern "C" void kernel_launch(void* const* d_in, const int* in_sizes, int n_in,
                              void* d_out, int out_size)
{
    (void)in_sizes; (void)n_in; (void)out_size;
    const float* inputs     = (const float*)d_in[0];
    const float* patch_w    = (const float*)d_in[1];
    const float* patch_b    = (const float*)d_in[2];
    const float* cls_token  = (const float*)d_in[3];
    const float* pos_embed  = (const float*)d_in[4];
    const float* ln1_s      = (const float*)d_in[5];
    const float* ln1_b      = (const float*)d_in[6];
    const float* qkv_w      = (const float*)d_in[7];
    const float* qkv_b      = (const float*)d_in[8];
    const float* proj_w     = (const float*)d_in[9];
    const float* proj_b     = (const float*)d_in[10];
    const float* ln2_s      = (const float*)d_in[11];
    const float* ln2_b      = (const float*)d_in[12];
    const float* fc1_w      = (const float*)d_in[13];
    const float* fc1_b      = (const float*)d_in[14];
    const float* fc2_w      = (const float*)d_in[15];
    const float* fc2_b      = (const float*)d_in[16];
    const float* norm_s     = (const float*)d_in[17];
    const float* norm_b     = (const float*)d_in[18];
    const float* head_w     = (const float*)d_in[19];
    const float* head_b     = (const float*)d_in[20];
    const float* key_emb    = (const float*)d_in[21];
    const float* mask_param = (const float*)d_in[22];
    const float* g_prompts  = (const float*)d_in[23];
    const float* e_prompts  = (const float*)d_in[24];
    float* out = (float*)d_out;

    void* p;
    cudaGetSymbolAddress(&p, g_xq);     float* xq     = (float*)p;
    cudaGetSymbolAddress(&p, g_x0);     float* x0     = (float*)p;
    cudaGetSymbolAddress(&p, g_ptmp);   float* ptmp   = (float*)p;
    cudaGetSymbolAddress(&p, g_qkvf);   float* qkvf   = (float*)p;
    cudaGetSymbolAddress(&p, g_qf);     float* qf     = (float*)p;
    cudaGetSymbolAddress(&p, g_kf);     float* kf     = (float*)p;
    cudaGetSymbolAddress(&p, g_vf);     float* vf     = (float*)p;
    cudaGetSymbolAddress(&p, g_idx);    int*   idx    = (int*)p;
    cudaGetSymbolAddress(&p, g_h_hi);   __half* h_hi  = (__half*)p;
    cudaGetSymbolAddress(&p, g_h_lo);   __half* h_lo  = (__half*)p;
    cudaGetSymbolAddress(&p, g_at_hi);  __half* at_hi = (__half*)p;
    cudaGetSymbolAddress(&p, g_at_lo);  __half* at_lo = (__half*)p;
    cudaGetSymbolAddress(&p, g_ff_hi);  __half* ff_hi = (__half*)p;
    cudaGetSymbolAddress(&p, g_ff_lo);  __half* ff_lo = (__half*)p;
    cudaGetSymbolAddress(&p, g_xk_hi);  __half* xk_hi = (__half*)p;
    cudaGetSymbolAddress(&p, g_xk_lo);  __half* xk_lo = (__half*)p;
    cudaGetSymbolAddress(&p, g_xv_hi);  __half* xv_hi = (__half*)p;
    cudaGetSymbolAddress(&p, g_xv_lo);  __half* xv_lo = (__half*)p;
    cudaGetSymbolAddress(&p, g_p_hi);   __half* p_hi  = (__half*)p;
    cudaGetSymbolAddress(&p, g_p_lo);   __half* p_lo  = (__half*)p;
    cudaGetSymbolAddress(&p, g_wpatch); __half* wpatch = (__half*)p;
    cudaGetSymbolAddress(&p, g_wqkv);   __half* wqkv   = (__half*)p;
    cudaGetSymbolAddress(&p, g_wproj);  __half* wproj  = (__half*)p;
    cudaGetSymbolAddress(&p, g_wfc1);   __half* wfc1   = (__half*)p;
    cudaGetSymbolAddress(&p, g_wfc2);   __half* wfc2   = (__half*)p;

    const int ATT_SMEM = (128 * KSTR + 8 * PPAD) * (int)sizeof(float);   // 123904
    cudaFuncSetAttribute(attn_k, cudaFuncAttributeMaxDynamicSharedMemorySize, ATT_SMEM);
    cudaFuncSetAttribute(gemm_k<2, 0>, cudaFuncAttributeMaxDynamicSharedMemorySize, SMEM2);
    cudaFuncSetAttribute(gemm_k<2, 1>, cudaFuncAttributeMaxDynamicSharedMemorySize, SMEM2);
    cudaFuncSetAttribute(gemm_k<2, 2>, cudaFuncAttributeMaxDynamicSharedMemorySize, SMEM2);
    cudaFuncSetAttribute(gemm_k<1, 0>, cudaFuncAttributeMaxDynamicSharedMemorySize, SMEM1);
    cudaFuncSetAttribute(gemm_k<1, 1>, cudaFuncAttributeMaxDynamicSharedMemorySize, SMEM1);
    cudaFuncSetAttribute(gemm_k<1, 2>, cudaFuncAttributeMaxDynamicSharedMemorySize, SMEM1);

    auto conv = [](const float* in, __half* o, size_t n) {
        conv_h_k<<<(unsigned)((n + 255) / 256), 256>>>(in, o, n);
    };
    // launches #1-4: weight conversions (fp16 hi only)
    conv(qkv_w,  wqkv,  (size_t)L_ * 3 * D_ * D_);
    conv(proj_w, wproj, (size_t)L_ * D_ * D_);
    conv(fc1_w,  wfc1,  (size_t)L_ * FF_ * D_);
    conv(fc2_w,  wfc2,  (size_t)L_ * D_ * FF_);
    // launch #5: prep (patchify split + patch weight)  -> launch #6 = GEMM (ncu slot)
    {
        size_t n = (size_t)B_ * NP_ * D_ + (size_t)D_ * D_;
        prep_k<<<(unsigned)((n + 255) / 256), 256>>>(inputs, patch_w, p_hi, p_lo, wpatch);
        launch_gemm2(EPI_F32, p_hi, p_lo, wpatch, patch_b,
                     ptmp, nullptr, nullptr, B_ * NP_, D_, D_);
        size_t m = (size_t)B_ * NT_ * D_;
        assemble_k<<<(unsigned)((m + 255) / 256), 256>>>(ptmp, cls_token, pos_embed, x0, xq);
    }

    // fast (1-product fp16) transformer block on xq: query pass — feeds idx selection
    auto fast_block = [&](int l) {
        ln_k<<<M1, 256>>>(xq, ln1_s + (size_t)l * D_, ln1_b + (size_t)l * D_, h_hi, nullptr);
        launch_gemm1(EPI_F32, h_hi, wqkv + (size_t)l * 3 * D_ * D_,
                     qkv_b + (size_t)l * 3 * D_, qkvf, nullptr, M1, 3 * D_, D_);
        attn_k<<<dim3(H_, B_), 256, ATT_SMEM>>>(
            qkvf,            (long long)NT_ * 3 * D_, 3 * D_,
            qkvf + D_,       (long long)NT_ * 3 * D_, 3 * D_,
            qkvf + 2 * D_,   (long long)NT_ * 3 * D_, 3 * D_,
            at_hi, at_lo, NT_);
        launch_gemm1(EPI_RES, at_hi, wproj + (size_t)l * D_ * D_,
                     proj_b + (size_t)l * D_, xq, nullptr, M1, D_, D_);
        ln_k<<<M1, 256>>>(xq, ln2_s + (size_t)l * D_, ln2_b + (size_t)l * D_, h_hi, nullptr);
        launch_gemm1(EPI_GELU, h_hi, wfc1 + (size_t)l * FF_ * D_,
                     fc1_b + (size_t)l * FF_, nullptr, ff_hi, M1, FF_, D_);
        launch_gemm1(EPI_RES, ff_hi, wfc2 + (size_t)l * D_ * FF_,
                     fc2_b + (size_t)l * D_, xq, nullptr, M1, D_, FF_);
    };

    // accurate (2-product fp16, A exact) transformer block on x0: prompted pass
    auto std_block = [&](int l) {
        ln_k<<<M1, 256>>>(x0, ln1_s + (size_t)l * D_, ln1_b + (size_t)l * D_, h_hi, h_lo);
        launch_gemm2(EPI_F32, h_hi, h_lo, wqkv + (size_t)l * 3 * D_ * D_,
                     qkv_b + (size_t)l * 3 * D_, qkvf, nullptr, nullptr, M1, 3 * D_, D_);
        attn_k<<<dim3(H_, B_), 256, ATT_SMEM>>>(
            qkvf,            (long long)NT_ * 3 * D_, 3 * D_,
            qkvf + D_,       (long long)NT_ * 3 * D_, 3 * D_,
            qkvf + 2 * D_,   (long long)NT_ * 3 * D_, 3 * D_,
            at_hi, at_lo, NT_);
        launch_gemm2(EPI_RES, at_hi, at_lo, wproj + (size_t)l * D_ * D_,
                     proj_b + (size_t)l * D_, x0, nullptr, nullptr, M1, D_, D_);
        ln_k<<<M1, 256>>>(x0, ln2_s + (size_t)l * D_, ln2_b + (size_t)l * D_, h_hi, h_lo);
        launch_gemm2(EPI_GELU, h_hi, h_lo, wfc1 + (size_t)l * FF_ * D_,
                     fc1_b + (size_t)l * FF_, nullptr, ff_hi, ff_lo, M1, FF_, D_);
        launch_gemm2(EPI_RES, ff_hi, ff_lo, wfc2 + (size_t)l * D_ * FF_,
                     fc2_b + (size_t)l * D_, x0, nullptr, nullptr, M1, D_, FF_);
    };

    // 1) frozen query pass (1-product fp16 — only idx depends on it)
    for (int l = 0; l < L_; ++l) fast_block(l);
    select_k<<<B_, 256>>>(xq, key_emb, idx);

    // 2) prompted pass runs directly on x0 (no copy needed)
    for (int l = 0; l < L_; ++l) {
        const bool isG = (l < 2), isEL = (l >= 2 && l < 5);
        if (!isG && !isEL) { std_block(l); continue; }
        const int plen = isG ? 5 : 20;
        const int pi   = isG ? l : (l - 2);
        const int nkl  = NT_ + plen;
        const int Mk   = B_ * nkl;

        ln_k<<<M1, 256>>>(x0, ln1_s + (size_t)l * D_, ln1_b + (size_t)l * D_, h_hi, h_lo);
        {
            size_t n = (size_t)Mk * D_;
            concat_k<<<(unsigned)((n + 255) / 256), 256>>>(
                h_hi, h_lo, g_prompts, e_prompts, idx,
                xk_hi, xk_lo, xv_hi, xv_lo, nkl, plen, pi, isEL ? 1 : 0);
        }
        const size_t wo = (size_t)l * 3 * D_ * D_;
        const float* bl = qkv_b + (size_t)l * 3 * D_;
        launch_gemm2(EPI_F32, h_hi, h_lo, wqkv + wo, bl, qf, nullptr, nullptr, M1, D_, D_);
        launch_gemm2(EPI_F32, xk_hi, xk_lo, wqkv + wo + (size_t)D_ * D_,
                     bl + D_, kf, nullptr, nullptr, Mk, D_, D_);
        launch_gemm2(EPI_F32, xv_hi, xv_lo, wqkv + wo + (size_t)2 * D_ * D_,
                     bl + 2 * D_, vf, nullptr, nullptr, Mk, D_, D_);
        attn_k<<<dim3(H_, B_), 256, ATT_SMEM>>>(
            qf, (long long)NT_ * D_, D_,
            kf, (long long)nkl * D_, D_,
            vf, (long long)nkl * D_, D_,
            at_hi, at_lo, nkl);
        launch_gemm2(EPI_RES, at_hi, at_lo, wproj + (size_t)l * D_ * D_,
                     proj_b + (size_t)l * D_, x0, nullptr, nullptr, M1, D_, D_);
        ln_k<<<M1, 256>>>(x0, ln2_s + (size_t)l * D_, ln2_b + (size_t)l * D_, h_hi, h_lo);
        launch_gemm2(EPI_GELU, h_hi, h_lo, wfc1 + (size_t)l * FF_ * D_,
                     fc1_b + (size_t)l * FF_, nullptr, ff_hi, ff_lo, M1, FF_, D_);
        launch_gemm2(EPI_RES, ff_hi, ff_lo, wfc2 + (size_t)l * D_ * FF_,
                     fc2_b + (size_t)l * D_, x0, nullptr, nullptr, M1, D_, FF_);
    }

    // 3) head
    head_k<<<B_, 256>>>(x0, norm_s, norm_b, head_w, head_b, mask_param, idx, out);
}

// round 15
// speedup vs baseline: 1.6283x; 1.0265x over previous
#include <cuda_runtime.h>
#include <cuda_fp16.h>
#include <cstdint>
#include <cstddef>

#define DI __device__ __forceinline__

// ---------------- problem dims ----------------
constexpr int L_ = 12, D_ = 768, H_ = 12, FF_ = 3072;
constexpr int B_ = 64, NP_ = 196, NT_ = 197, NC_ = 100, T_ = 10;
constexpr int M1 = B_ * NT_;        // 12608 token rows
constexpr int NKMAX = 217;          // 197 + 20 (e-prompt layers)
constexpr int MKMAX = B_ * NKMAX;   // 13888
constexpr int KSTR = 228;           // attention K/V smem row stride (float4-aligned)
constexpr int PPAD = 224;           // padded key count (mult of 32)

// ---------------- device scratch (static, no runtime alloc) ----------------
__device__ float g_xq  [(size_t)M1 * D_];       // query-pass stream
__device__ float g_x0  [(size_t)M1 * D_];       // prompted-pass stream
__device__ float g_ptmp[(size_t)B_ * NP_ * D_];
__device__ float g_qkvf[(size_t)M1 * 3 * D_];
__device__ float g_qf  [(size_t)M1 * D_];
__device__ float g_kf  [(size_t)MKMAX * D_];
__device__ float g_vf  [(size_t)MKMAX * D_];
__device__ int   g_idx [B_];
// fp16 hi/lo activation pairs (A-side operands)
__device__ __half g_h_hi [(size_t)M1 * D_];
__device__ __half g_h_lo [(size_t)M1 * D_];
__device__ __half g_at_hi[(size_t)M1 * D_];
__device__ __half g_at_lo[(size_t)M1 * D_];
__device__ __half g_ff_hi[(size_t)M1 * FF_];
__device__ __half g_ff_lo[(size_t)M1 * FF_];
__device__ __half g_xk_hi[(size_t)MKMAX * D_];
__device__ __half g_xk_lo[(size_t)MKMAX * D_];
__device__ __half g_xv_hi[(size_t)MKMAX * D_];
__device__ __half g_xv_lo[(size_t)MKMAX * D_];
__device__ __half g_p_hi [(size_t)B_ * NP_ * D_];
__device__ __half g_p_lo [(size_t)B_ * NP_ * D_];
// fp16 weights (hi only — B-side operands)
__device__ __half g_wpatch[(size_t)D_ * D_];
__device__ __half g_wqkv  [(size_t)L_ * 3 * D_ * D_];
__device__ __half g_wproj [(size_t)L_ * D_ * D_];
__device__ __half g_wfc1  [(size_t)L_ * FF_ * D_];
__device__ __half g_wfc2  [(size_t)L_ * D_ * FF_];

// ---------------- PTX helpers ----------------
DI uint32_t sptr(const void* p) { return (uint32_t)__cvta_generic_to_shared(p); }

DI void cp16(void* s, const void* g, bool pred) {
    asm volatile("cp.async.cg.shared.global [%0], [%1], 16, %2;\n"
                 :: "r"(sptr(s)), "l"(g), "r"(pred ? 16 : 0));
}
DI void cpcommit() { asm volatile("cp.async.commit_group;\n" ::); }
DI void cpwait0()  { asm volatile("cp.async.wait_group 0;\n" ::); }
DI void cpwait1()  { asm volatile("cp.async.wait_group 1;\n" ::); }

DI void ldm4(uint32_t* r, const void* p) {
    asm volatile("ldmatrix.sync.aligned.m8n8.x4.shared.b16 {%0,%1,%2,%3}, [%4];\n"
                 : "=r"(r[0]), "=r"(r[1]), "=r"(r[2]), "=r"(r[3])
                 : "r"(sptr(p)) : "memory");
}
DI void mma_f16(float* d, const uint32_t* a, const uint32_t* b) {
    asm volatile("mma.sync.aligned.m16n8k16.row.col.f32.f16.f16.f32 "
                 "{%0,%1,%2,%3}, {%4,%5,%6,%7}, {%8,%9}, {%0,%1,%2,%3};\n"
                 : "+f"(d[0]), "+f"(d[1]), "+f"(d[2]), "+f"(d[3])
                 : "r"(a[0]), "r"(a[1]), "r"(a[2]), "r"(a[3]),
                   "r"(b[0]), "r"(b[1]));
}
DI float gelu_f(float v) { return 0.5f * v * (1.f + erff(v * 0.70710678118654752f)); }
DI void split_h(float v, __half& hi, __half& lo) {
    hi = __float2half_rn(v);
    lo = __float2half_rn(v - __half2float(hi));
}

constexpr int EPI_F32 = 0, EPI_GELU = 1, EPI_RES = 2;
constexpr int AS = 40;                    // smem row stride (32+8) -> conflict-free LDSM
constexpr int TILE_ELE = 128 * AS;        // 5120 halves per tile (10240 B)
constexpr int SMEM2 = 3 * 3 * TILE_ELE * 2;   // 92160 B (Ah,Al,Bh x3 stages)
constexpr int SMEM1 = 3 * 2 * TILE_ELE * 2;   // 61440 B (Ah,Bh x3 stages)

// ============ fp16 split TN GEMM: C[M,N] = A[M,K] * B[N,K]^T ============
// NPROD=2: A = Ah + Al (fp16 pair, exact), B = Bh (fp16) -> only weight quantized
// NPROD=1: C = Ah*Bh (query pass)
// lda: element stride between A rows; ldc: element stride between C rows.
template<int NPROD, int EPI>
__global__ __launch_bounds__(256, 2) void gemm_k(
    const __half* __restrict__ Ahi, const __half* __restrict__ Alo,
    const __half* __restrict__ Bw,
    const float* __restrict__ bias, float* __restrict__ Cf,
    __half* __restrict__ Cb_hi, __half* __restrict__ Cb_lo,
    int M, int N, int K, long long lda, long long ldc)
{
    constexpr int NT = (NPROD == 2) ? 3 : 2;
    extern __shared__ __half smem[];

    const int tid = threadIdx.x;
    const int m0 = blockIdx.y * 128, n0 = blockIdx.x * 128;
    const int wid = tid >> 5, lane = tid & 31;
    const int wm = wid >> 2, wn = wid & 3;          // 2x4 warps, warp tile 64x32

    float acc[4][4][4];
    #pragma unroll
    for (int a = 0; a < 4; a++)
        #pragma unroll
        for (int b = 0; b < 4; b++)
            #pragma unroll
            for (int c = 0; c < 4; c++) acc[a][b][c] = 0.f;

    const int nIt = K >> 5;

    auto load_stage = [&](int st, int k0) {
        __half* base = smem + st * NT * TILE_ELE;
        #pragma unroll
        for (int i = 0; i < 2; i++) {
            int idx = tid + i * 256;          // 512 chunks: 128 rows x 4 x 16B
            int r = idx >> 2, c = (idx & 3) << 3;
            int gr = m0 + r;
            bool p = gr < M;
            size_t aoff = (size_t)(p ? gr : 0) * lda + k0 + c;
            size_t boff = (size_t)(n0 + r) * K + k0 + c;
            cp16(base + r * AS + c, Ahi + aoff, p);
            if (NPROD == 2) cp16(base + TILE_ELE + r * AS + c, Alo + aoff, p);
            cp16(base + (NPROD == 2 ? 2 : 1) * TILE_ELE + r * AS + c, Bw + boff, true);
        }
        cpcommit();
    };

    load_stage(0, 0);
    load_stage(1, 32);
    cpwait1();
    __syncthreads();

    for (int it = 0; it < nIt; ++it) {
        const bool pre = (it + 2 < nIt);
        int stn = it + 2;
        if (pre) load_stage(stn - 3 * (stn / 3), stn << 5);
        const int buf = it - 3 * (it / 3);
        __half* sb = smem + buf * NT * TILE_ELE;
        __half* sAh = sb;
        __half* sAl = sb + TILE_ELE;
        __half* sBh = sb + (NPROD == 2 ? 2 : 1) * TILE_ELE;
        #pragma unroll
        for (int kk = 0; kk < 2; ++kk) {
            const int kcol = kk << 4;
            uint32_t bh[4][2], af[4][4];
            #pragma unroll
            for (int j = 0; j < 2; ++j) {
                int row = wn * 32 + j * 16 + (lane & 7) + ((lane >> 4) << 3);
                int col = kcol + (((lane >> 3) & 1) << 3);
                uint32_t t[4];
                ldm4(t, &sBh[row * AS + col]);
                bh[2 * j][0] = t[0]; bh[2 * j][1] = t[1];
                bh[2 * j + 1][0] = t[2]; bh[2 * j + 1][1] = t[3];
            }
            #pragma unroll
            for (int mt = 0; mt < 4; ++mt) {
                int row = wm * 64 + mt * 16 + (lane & 15);
                int col = kcol + ((lane >> 4) << 3);
                ldm4(af[mt], &sAh[row * AS + col]);
            }
            #pragma unroll
            for (int mt = 0; mt < 4; ++mt)
                #pragma unroll
                for (int nt = 0; nt < 4; ++nt)
                    mma_f16(acc[mt][nt], af[mt], bh[nt]);
            if (NPROD == 2) {
                #pragma unroll
                for (int mt = 0; mt < 4; ++mt) {
                    int row = wm * 64 + mt * 16 + (lane & 15);
                    int col = kcol + ((lane >> 4) << 3);
                    ldm4(af[mt], &sAl[row * AS + col]);
                }
                #pragma unroll
                for (int mt = 0; mt < 4; ++mt)
                    #pragma unroll
                    for (int nt = 0; nt < 4; ++nt)
                        mma_f16(acc[mt][nt], af[mt], bh[nt]);
            }
        }
        if (pre) cpwait1(); else cpwait0();
        __syncthreads();
    }

    const int g = lane >> 2, tg = lane & 3;
    #pragma unroll
    for (int mt = 0; mt < 4; ++mt) {
        #pragma unroll
        for (int nt = 0; nt < 4; ++nt) {
            const int col = n0 + wn * 32 + nt * 8 + tg * 2;
            #pragma unroll
            for (int hh = 0; hh < 2; ++hh) {
                const int r = m0 + wm * 64 + mt * 16 + g + hh * 8;
                if (r < M) {
                    float v0 = acc[mt][nt][2 * hh + 0] + bias[col];
                    float v1 = acc[mt][nt][2 * hh + 1] + bias[col + 1];
                    size_t off = (size_t)r * ldc + col;
                    if (EPI == EPI_F32) {
                        float2 o; o.x = v0; o.y = v1;
                        *reinterpret_cast<float2*>(Cf + off) = o;
                    } else if (EPI == EPI_GELU) {
                        float g0 = gelu_f(v0), g1 = gelu_f(v1);
                        __half h0, l0, h1, l1;
                        split_h(g0, h0, l0); split_h(g1, h1, l1);
                        __half2 oh; oh.x = h0; oh.y = h1;
                        *reinterpret_cast<__half2*>(Cb_hi + off) = oh;
                        if (NPROD == 2) {
                            __half2 ol; ol.x = l0; ol.y = l1;
                            *reinterpret_cast<__half2*>(Cb_lo + off) = ol;
                        }
                    } else {
                        float2 o = *reinterpret_cast<float2*>(Cf + off);
                        o.x += v0; o.y += v1;
                        *reinterpret_cast<float2*>(Cf + off) = o;
                    }
                }
            }
        }
    }
}

// ---------------- attention (fp32 SIMT, block per (b,h)), outputs fp16 hi/lo ----------
__global__ __launch_bounds__(256) void attn_k(
    const float* __restrict__ qp, long long qbs, int qrs,
    const float* __restrict__ kp, long long kbs, int krs,
    const float* __restrict__ vp, long long vbs, int vrs,
    __half* __restrict__ out_hi, __half* __restrict__ out_lo, int nk)
{
    extern __shared__ float skvf[];
    float* Ks = skvf;                    // [64][KSTR]
    float* Vs = skvf + 64 * KSTR;        // [64][KSTR]
    float* Ps = skvf + 128 * KSTR;       // [8][PPAD] per-warp probs
    const int h = blockIdx.x, b = blockIdx.y;
    const int tid = threadIdx.x, lane = tid & 31, w = tid >> 5;

    const float* kb = kp + (long long)b * kbs + h * 64;
    const float* vb = vp + (long long)b * vbs + h * 64;
    for (int i = tid; i < 64 * PPAD; i += 256) {
        int j = i >> 6, d = i & 63;
        float kvv = 0.f, vvv = 0.f;
        if (j < nk) {
            kvv = kb[(long long)j * krs + d];
            vvv = vb[(long long)j * vrs + d];
        }
        Ks[d * KSTR + j] = kvv;
        Vs[d * KSTR + j] = vvv;
    }
    __syncthreads();

    const int cnt = (nk - lane + 31) >> 5;          // keys for this lane (6..7)
    const int nk4q = (nk + 3) >> 2;
    float* pw = Ps + w * PPAD;
    const float4* pw4 = (const float4*)pw;
    const float4* v0p = (const float4*)(Vs + lane * KSTR);
    const float4* v1p = (const float4*)(Vs + (lane + 32) * KSTR);

    for (int qi = w; qi < NT_; qi += 8) {
        const float* qrow = qp + (long long)b * qbs + (long long)qi * qrs + h * 64;
        const float4* q4 = (const float4*)qrow;
        float qv[64];
        #pragma unroll
        for (int t = 0; t < 16; ++t) {
            float4 v = q4[t];
            qv[4 * t] = v.x; qv[4 * t + 1] = v.y; qv[4 * t + 2] = v.z; qv[4 * t + 3] = v.w;
        }

        float s[7];
        #pragma unroll
        for (int jj = 0; jj < 7; ++jj) s[jj] = 0.f;
        #pragma unroll
        for (int d = 0; d < 64; ++d) {
            const float qd = qv[d];
            #pragma unroll
            for (int jj = 0; jj < 7; ++jj)
                if (jj < cnt) s[jj] += qd * Ks[d * KSTR + lane + jj * 32];
        }
        float m = -1e30f;
        #pragma unroll
        for (int jj = 0; jj < 7; ++jj)
            if (jj < cnt) { s[jj] *= 0.125f; m = fmaxf(m, s[jj]); }
        #pragma unroll
        for (int o = 16; o; o >>= 1) m = fmaxf(m, __shfl_xor_sync(0xffffffffu, m, o));
        float sum = 0.f;
        #pragma unroll
        for (int jj = 0; jj < 7; ++jj) {
            s[jj] = (jj < cnt) ? __expf(s[jj] - m) : 0.f;
            sum += s[jj];
        }
        #pragma unroll
        for (int o = 16; o; o >>= 1) sum += __shfl_xor_sync(0xffffffffu, sum, o);
        const float inv = 1.f / sum;

        #pragma unroll
        for (int jj = 0; jj < 7; ++jj)
            pw[lane + jj * 32] = s[jj] * inv;
        __syncwarp();

        float o0 = 0.f, o1 = 0.f;
        for (int j4 = 0; j4 < nk4q; ++j4) {
            float4 pp = pw4[j4];
            float4 a = v0p[j4];
            float4 c = v1p[j4];
            o0 += pp.x * a.x + pp.y * a.y + pp.z * a.z + pp.w * a.w;
            o1 += pp.x * c.x + pp.y * c.y + pp.z * c.z + pp.w * c.w;
        }
        __syncwarp();

        size_t base = ((size_t)(b * NT_ + qi)) * D_ + h * 64;
        __half h0, l0, h1, l1;
        split_h(o0, h0, l0); split_h(o1, h1, l1);
        out_hi[base + lane] = h0;      out_lo[base + lane] = l0;
        out_hi[base + lane + 32] = h1; out_lo[base + lane + 32] = l1;
    }
}

// ---------------- CLS-only attention (query pass tail layer) ----------------
// q: [B_, D_] compact; kvf: [M1, 1536] rows = tokens, cols 0..767=K, 768..1535=V
// out: [B_, D_] fp16 (hi only)
__global__ __launch_bounds__(256) void attn_cls_k(
    const float* __restrict__ qcls, const float* __restrict__ kvf,
    __half* __restrict__ out)
{
    extern __shared__ float skvf[];
    float* Ks = skvf;
    float* Vs = skvf + 64 * KSTR;
    float* Ps = skvf + 128 * KSTR;
    const int h = blockIdx.x, b = blockIdx.y;
    const int tid = threadIdx.x;

    const float* kb = kvf + (size_t)b * NT_ * 1536 + h * 64;
    const float* vb = kb + 768;
    for (int i = tid; i < 64 * PPAD; i += 256) {
        int j = i >> 6, d = i & 63;
        float kvv = 0.f, vvv = 0.f;
        if (j < NT_) {
            kvv = kb[(size_t)j * 1536 + d];
            vvv = vb[(size_t)j * 1536 + d];
        }
        Ks[d * KSTR + j] = kvv;
        Vs[d * KSTR + j] = vvv;
    }
    __syncthreads();
    if (tid >= 32) return;
    const int lane = tid;
    const int cnt = (NT_ - lane + 31) >> 5;
    const float* qrow = qcls + (size_t)b * D_ + h * 64;
    float qv[64];
    #pragma unroll
    for (int d = 0; d < 64; ++d) qv[d] = qrow[d];

    float s[7];
    #pragma unroll
    for (int jj = 0; jj < 7; ++jj) s[jj] = 0.f;
    #pragma unroll
    for (int d = 0; d < 64; ++d) {
        const float qd = qv[d];
        #pragma unroll
        for (int jj = 0; jj < 7; ++jj)
            if (jj < cnt) s[jj] += qd * Ks[d * KSTR + lane + jj * 32];
    }
    float m = -1e30f;
    #pragma unroll
    for (int jj = 0; jj < 7; ++jj)
        if (jj < cnt) { s[jj] *= 0.125f; m = fmaxf(m, s[jj]); }
    #pragma unroll
    for (int o = 16; o; o >>= 1) m = fmaxf(m, __shfl_xor_sync(0xffffffffu, m, o));
    float sum = 0.f;
    #pragma unroll
    for (int jj = 0; jj < 7; ++jj) {
        s[jj] = (jj < cnt) ? __expf(s[jj] - m) : 0.f;
        sum += s[jj];
    }
    #pragma unroll
    for (int o = 16; o; o >>= 1) sum += __shfl_xor_sync(0xffffffffu, sum, o);
    const float inv = 1.f / sum;
    #pragma unroll
    for (int jj = 0; jj < 7; ++jj)
        Ps[lane + jj * 32] = s[jj] * inv;
    __syncwarp();

    const float4* pw4 = (const float4*)Ps;
    const float4* v0p = (const float4*)(Vs + lane * KSTR);
    const float4* v1p = (const float4*)(Vs + (lane + 32) * KSTR);
    const int nk4q = (NT_ + 3) >> 2;
    float o0 = 0.f, o1 = 0.f;
    for (int j4 = 0; j4 < nk4q; ++j4) {
        float4 pp = pw4[j4];
        float4 a = v0p[j4];
        float4 c = v1p[j4];
        o0 += pp.x * a.x + pp.y * a.y + pp.z * a.z + pp.w * a.w;
        o1 += pp.x * c.x + pp.y * c.y + pp.z * c.z + pp.w * c.w;
    }
    out[(size_t)b * D_ + h * 64 + lane]      = __float2half_rn(o0);
    out[(size_t)b * D_ + h * 64 + lane + 32] = __float2half_rn(o1);
}

// ---------------- layernorm (block per row) -> fp16 hi(/lo) ----------------
__global__ __launch_bounds__(256) void ln_k(const float* __restrict__ x,
    const float* __restrict__ s, const float* __restrict__ b,
    __half* __restrict__ out_hi, __half* __restrict__ out_lo, long long ldx)
{
    const int row = blockIdx.x, tid = threadIdx.x;
    const float* xr = x + (size_t)row * ldx;
    float v[3], sum = 0.f, sq = 0.f;
    #pragma unroll
    for (int i = 0; i < 3; i++) { v[i] = xr[tid + i * 256]; sum += v[i]; sq += v[i] * v[i]; }
    __shared__ float rs[8], rq[8];
    #pragma unroll
    for (int o = 16; o; o >>= 1) {
        sum += __shfl_xor_sync(0xffffffffu, sum, o);
        sq  += __shfl_xor_sync(0xffffffffu, sq, o);
    }
    if ((tid & 31) == 0) { rs[tid >> 5] = sum; rq[tid >> 5] = sq; }
    __syncthreads();
    sum = 0.f; sq = 0.f;
    #pragma unroll
    for (int i = 0; i < 8; i++) { sum += rs[i]; sq += rq[i]; }
    const float mu = sum * (1.f / D_);
    const float var = sq * (1.f / D_) - mu * mu;
    const float rstd = rsqrtf(var + 1e-6f);
    #pragma unroll
    for (int i = 0; i < 3; i++) {
        int c = tid + i * 256;
        float y = (v[i] - mu) * rstd * s[c] + b[c];
        __half h, l;
        split_h(y, h, l);
        out_hi[(size_t)row * D_ + c] = h;
        if (out_lo) out_lo[(size_t)row * D_ + c] = l;
    }
}

// ---------------- small utility kernels ----------------
__global__ void conv_h_k(const float* __restrict__ in, __half* __restrict__ o, size_t n) {
    size_t i = (size_t)blockIdx.x * 256 + threadIdx.x;
    if (i < n) o[i] = __float2half_rn(in[i]);
}
__global__ void prep_k(const float* __restrict__ in, const float* __restrict__ pw,
                       __half* __restrict__ p_hi, __half* __restrict__ p_lo,
                       __half* __restrict__ w_hi) {
    size_t i = (size_t)blockIdx.x * 256 + threadIdx.x;
    const size_t NPT = (size_t)B_ * NP_ * D_;
    if (i < NPT) {
        int d = (int)(i % D_), r = (int)((i / D_) % NP_), b = (int)(i / ((size_t)D_ * NP_));
        int hp = r / 14, wp = r % 14;
        int c = d >> 8, ph = (d >> 4) & 15, pwc = d & 15;
        float v = in[(((size_t)b * 3 + c) * 224 + hp * 16 + ph) * 224 + wp * 16 + pwc];
        __half h, l;
        split_h(v, h, l);
        p_hi[i] = h; p_lo[i] = l;
    } else if (i < NPT + (size_t)D_ * D_) {
        size_t j = i - NPT;
        w_hi[j] = __float2half_rn(pw[j]);
    }
}
__global__ void assemble_k(const float* __restrict__ ptmp, const float* __restrict__ cls,
                           const float* __restrict__ pos, float* __restrict__ x0,
                           float* __restrict__ xq) {
    size_t i = (size_t)blockIdx.x * 256 + threadIdx.x;
    if (i >= (size_t)B_ * NT_ * D_) return;
    int d = (int)(i % D_), j = (int)((i / D_) % NT_), b = (int)(i / ((size_t)D_ * NT_));
    float v = (j == 0 ? cls[d] : ptmp[((size_t)b * NP_ + j - 1) * D_ + d]) + pos[(size_t)j * D_ + d];
    x0[i] = v; xq[i] = v;
}
__global__ void concat_k(const __half* __restrict__ h_hi, const __half* __restrict__ h_lo,
                         const float* __restrict__ gp, const float* __restrict__ ep,
                         const int* __restrict__ idx,
                         __half* __restrict__ xk_hi, __half* __restrict__ xk_lo,
                         __half* __restrict__ xv_hi, __half* __restrict__ xv_lo,
                         int nkl, int plen, int pi, int isE)
{
    size_t i = (size_t)blockIdx.x * 256 + threadIdx.x;
    if (i >= (size_t)B_ * nkl * D_) return;
    int d = (int)(i % D_);
    int row = (int)(i / D_);
    int b = row / nkl, j = row % nkl;
    if (j < NT_) {
        size_t src = ((size_t)(b * NT_ + j)) * D_ + d;
        __half wh = h_hi[src], wl = h_lo[src];
        xk_hi[i] = wh; xk_lo[i] = wl;
        xv_hi[i] = wh; xv_lo[i] = wl;
    } else {
        int jj = j - NT_;
        const float* base = isE ? (ep + (size_t)idx[b] * 120 * D_) : gp;
        float vk = base[((size_t)(2 * pi) * plen + jj) * D_ + d];
        float vv = base[((size_t)(2 * pi + 1) * plen + jj) * D_ + d];
        __half h, l;
        split_h(vk, h, l); xk_hi[i] = h; xk_lo[i] = l;
        split_h(vv, h, l); xv_hi[i] = h; xv_lo[i] = l;
    }
}
__global__ __launch_bounds__(256) void select_k(const float* __restrict__ x,
    const float* __restrict__ key, int* __restrict__ idx)
{
    const int b = blockIdx.x, tid = threadIdx.x;
    const float* q = x + (size_t)b * NT_ * D_;
    float pq = 0.f, pd[T_], pk[T_];
    #pragma unroll
    for (int t = 0; t < T_; t++) { pd[t] = 0.f; pk[t] = 0.f; }
    for (int i = 0; i < 3; i++) {
        int d = tid + i * 256;
        float qd = q[d];
        pq += qd * qd;
        #pragma unroll
        for (int t = 0; t < T_; t++) {
            float kv = key[(size_t)t * D_ + d];
            pd[t] += qd * kv; pk[t] += kv * kv;
        }
    }
    __shared__ float red[256];
    __shared__ float tot[21];
    for (int a = 0; a < 21; a++) {
        float v = (a == 0) ? pq : (a <= 10 ? pd[a - 1] : pk[a - 11]);
        red[tid] = v; __syncthreads();
        for (int st = 128; st > 0; st >>= 1) {
            if (tid < st) red[tid] += red[tid + st];
            __syncthreads();
        }
        if (tid == 0) tot[a] = red[0];
        __syncthreads();
    }
    if (tid == 0) {
        float qn = sqrtf(tot[0]) + 1e-8f;
        float best = -2e30f; int bi = 0;
        for (int t = 0; t < T_; t++) {
            float cosv = tot[1 + t] / (qn * (sqrtf(tot[11 + t]) + 1e-8f));
            if (cosv > best) { best = cosv; bi = t; }
        }
        idx[b] = bi;
    }
}
__global__ __launch_bounds__(256) void head_k(const float* __restrict__ x,
    const float* __restrict__ ns, const float* __restrict__ nb,
    const float* __restrict__ hw, const float* __restrict__ hb,
    const float* __restrict__ mp, const int* __restrict__ idx,
    float* __restrict__ out)
{
    const int b = blockIdx.x, tid = threadIdx.x;
    __shared__ float feat[D_];
    __shared__ float rs[8], rq[8];
    const float* xr = x + (size_t)b * NT_ * D_;
    float v[3], sum = 0.f, sq = 0.f;
    #pragma unroll
    for (int i = 0; i < 3; i++) { v[i] = xr[tid + i * 256]; sum += v[i]; sq += v[i] * v[i]; }
    #pragma unroll
    for (int o = 16; o; o >>= 1) {
        sum += __shfl_xor_sync(0xffffffffu, sum, o);
        sq  += __shfl_xor_sync(0xffffffffu, sq, o);
    }
    if ((tid & 31) == 0) { rs[tid >> 5] = sum; rq[tid >> 5] = sq; }
    __syncthreads();
    sum = 0.f; sq = 0.f;
    #pragma unroll
    for (int i = 0; i < 8; i++) { sum += rs[i]; sq += rq[i]; }
    const float mu = sum * (1.f / D_);
    const float var = sq * (1.f / D_) - mu * mu;
    const float rstd = rsqrtf(var + 1e-6f);
    #pragma unroll
    for (int i = 0; i < 3; i++) {
        int c = tid + i * 256;
        feat[c] = (v[i] - mu) * rstd * ns[c] + nb[c];
    }
    __syncthreads();
    if (tid < NC_) {
        float a = hb[tid];
        const float* wr = hw + (size_t)tid * D_;
        for (int d = 0; d < D_; d++) a += feat[d] * wr[d];
        float m = mp[(size_t)idx[b] * NC_ + tid];
        out[b * NC_ + tid] = a * 2.f / (1.f + expf(-m));
    }
}

// ---------------- host side ----------------
static inline void launch_gemm2(int epi,
                                const __half* Ahi, const __half* Alo, const __half* Bw,
                                const float* bias, float* Cf,
                                __half* Cb_hi, __half* Cb_lo,
                                int M, int N, int K,
                                long long lda = -1, long long ldc = -1)
{
    if (lda < 0) lda = K;
    if (ldc < 0) ldc = N;
    dim3 grid(N / 128, (M + 127) / 128);
    switch (epi) {
        case 0:  gemm_k<2, 0><<<grid, 256, SMEM2>>>(Ahi, Alo, Bw, bias, Cf, Cb_hi, Cb_lo, M, N, K, lda, ldc); break;
        case 1:  gemm_k<2, 1><<<grid, 256, SMEM2>>>(Ahi, Alo, Bw, bias, Cf, Cb_hi, Cb_lo, M, N, K, lda, ldc); break;
        default: gemm_k<2, 2><<<grid, 256, SMEM2>>>(Ahi, Alo, Bw, bias, Cf, Cb_hi, Cb_lo, M, N, K, lda, ldc); break;
    }
}
static inline void launch_gemm1(int epi,
                                const __half* A, const __half* Bw,
                                const float* bias, float* Cf, __half* Cb_hi,
                                int M, int N, int K,
                                long long lda = -1, long long ldc = -1)
{
    if (lda < 0) lda = K;
    if (ldc < 0) ldc = N;
    dim3 grid(N / 128, (M + 127) / 128);
    switch (epi) {
        case 0:  gemm_k<1, 0><<<grid, 256, SMEM1>>>(A, nullptr, Bw, bias, Cf, Cb_hi, nullptr, M, N, K, lda, ldc); break;
        case 1:  gemm_k<1, 1><<<grid, 256, SMEM1>>>(A, nullptr, Bw, bias, Cf, Cb_hi, nullptr, M, N, K, lda, ldc); break;
        default: gemm_k<1, 2><<<grid, 256, SMEM1>>>(A, nullptr, Bw, bias, Cf, Cb_hi, nullptr, M, N, K, lda, ldc); break;
    }
}

extern "C" void kernel_launch(void* const* d_in, const int* in_sizes, int n_in,
                              void* d_out, int out_size)
{
    (void)in_sizes; (void)n_in; (void)out_size;
    const float* inputs     = (const float*)d_in[0];
    const float* patch_w    = (const float*)d_in[1];
    const float* patch_b    = (const float*)d_in[2];
    const float* cls_token  = (const float*)d_in[3];
    const float* pos_embed  = (const float*)d_in[4];
    const float* ln1_s      = (const float*)d_in[5];
    const float* ln1_b      = (const float*)d_in[6];
    const float* qkv_w      = (const float*)d_in[7];
    const float* qkv_b      = (const float*)d_in[8];
    const float* proj_w     = (const float*)d_in[9];
    const float* proj_b     = (const float*)d_in[10];
    const float* ln2_s      = (const float*)d_in[11];
    const float* ln2_b      = (const float*)d_in[12];
    const float* fc1_w      = (const float*)d_in[13];
    const float* fc1_b      = (const float*)d_in[14];
    const float* fc2_w      = (const float*)d_in[15];
    const float* fc2_b      = (const float*)d_in[16];
    const float* norm_s     = (const float*)d_in[17];
    const float* norm_b     = (const float*)d_in[18];
    const float* head_w     = (const float*)d_in[19];
    const float* head_b     = (const float*)d_in[20];
    const float* key_emb    = (const float*)d_in[21];
    const float* mask_param = (const float*)d_in[22];
    const float* g_prompts  = (const float*)d_in[23];
    const float* e_prompts  = (const float*)d_in[24];
    float* out = (float*)d_out;

    void* p;
    cudaGetSymbolAddress(&p, g_xq);     float* xq     = (float*)p;
    cudaGetSymbolAddress(&p, g_x0);     float* x0     = (float*)p;
    cudaGetSymbolAddress(&p, g_ptmp);   float* ptmp   = (float*)p;
    cudaGetSymbolAddress(&p, g_qkvf);   float* qkvf   = (float*)p;
    cudaGetSymbolAddress(&p, g_qf);     float* qf     = (float*)p;
    cudaGetSymbolAddress(&p, g_kf);     float* kf     = (float*)p;
    cudaGetSymbolAddress(&p, g_vf);     float* vf     = (float*)p;
    cudaGetSymbolAddress(&p, g_idx);    int*   idx    = (int*)p;
    cudaGetSymbolAddress(&p, g_h_hi);   __half* h_hi  = (__half*)p;
    cudaGetSymbolAddress(&p, g_h_lo);   __half* h_lo  = (__half*)p;
    cudaGetSymbolAddress(&p, g_at_hi);  __half* at_hi = (__half*)p;
    cudaGetSymbolAddress(&p, g_at_lo);  __half* at_lo = (__half*)p;
    cudaGetSymbolAddress(&p, g_ff_hi);  __half* ff_hi = (__half*)p;
    cudaGetSymbolAddress(&p, g_ff_lo);  __half* ff_lo = (__half*)p;
    cudaGetSymbolAddress(&p, g_xk_hi);  __half* xk_hi = (__half*)p;
    cudaGetSymbolAddress(&p, g_xk_lo);  __half* xk_lo = (__half*)p;
    cudaGetSymbolAddress(&p, g_xv_hi);  __half* xv_hi = (__half*)p;
    cudaGetSymbolAddress(&p, g_xv_lo);  __half* xv_lo = (__half*)p;
    cudaGetSymbolAddress(&p, g_p_hi);   __half* p_hi  = (__half*)p;
    cudaGetSymbolAddress(&p, g_p_lo);   __half* p_lo  = (__half*)p;
    cudaGetSymbolAddress(&p, g_wpatch); __half* wpatch = (__half*)p;
    cudaGetSymbolAddress(&p, g_wqkv);   __half* wqkv   = (__half*)p;
    cudaGetSymbolAddress(&p, g_wproj);  __half* wproj  = (__half*)p;
    cudaGetSymbolAddress(&p, g_wfc1);   __half* wfc1   = (__half*)p;
    cudaGetSymbolAddress(&p, g_wfc2);   __half* wfc2   = (__half*)p;

    const int ATT_SMEM = (128 * KSTR + 8 * PPAD) * (int)sizeof(float);   // 123904
    cudaFuncSetAttribute(attn_k, cudaFuncAttributeMaxDynamicSharedMemorySize, ATT_SMEM);
    cudaFuncSetAttribute(attn_cls_k, cudaFuncAttributeMaxDynamicSharedMemorySize, ATT_SMEM);
    cudaFuncSetAttribute(gemm_k<2, 0>, cudaFuncAttributeMaxDynamicSharedMemorySize, SMEM2);
    cudaFuncSetAttribute(gemm_k<2, 1>, cudaFuncAttributeMaxDynamicSharedMemorySize, SMEM2);
    cudaFuncSetAttribute(gemm_k<2, 2>, cudaFuncAttributeMaxDynamicSharedMemorySize, SMEM2);
    cudaFuncSetAttribute(gemm_k<1, 0>, cudaFuncAttributeMaxDynamicSharedMemorySize, SMEM1);
    cudaFuncSetAttribute(gemm_k<1, 1>, cudaFuncAttributeMaxDynamicSharedMemorySize, SMEM1);
    cudaFuncSetAttribute(gemm_k<1, 2>, cudaFuncAttributeMaxDynamicSharedMemorySize, SMEM1);

    auto conv = [](const float* in, __half* o, size_t n) {
        conv_h_k<<<(unsigned)((n + 255) / 256), 256>>>(in, o, n);
    };
    conv(qkv_w,  wqkv,  (size_t)L_ * 3 * D_ * D_);
    conv(proj_w, wproj, (size_t)L_ * D_ * D_);
    conv(fc1_w,  wfc1,  (size_t)L_ * FF_ * D_);
    conv(fc2_w,  wfc2,  (size_t)L_ * D_ * FF_);
    {
        size_t n = (size_t)B_ * NP_ * D_ + (size_t)D_ * D_;
        prep_k<<<(unsigned)((n + 255) / 256), 256>>>(inputs, patch_w, p_hi, p_lo, wpatch);
        launch_gemm2(EPI_F32, p_hi, p_lo, wpatch, patch_b,
                     ptmp, nullptr, nullptr, B_ * NP_, D_, D_);
        size_t m = (size_t)B_ * NT_ * D_;
        assemble_k<<<(unsigned)((m + 255) / 256), 256>>>(ptmp, cls_token, pos_embed, x0, xq);
    }

    // fast (1-product fp16) transformer block on xq: query pass layers 0..10
    auto fast_block = [&](int l) {
        ln_k<<<M1, 256>>>(xq, ln1_s + (size_t)l * D_, ln1_b + (size_t)l * D_, h_hi, nullptr, D_);
        launch_gemm1(EPI_F32, h_hi, wqkv + (size_t)l * 3 * D_ * D_,
                     qkv_b + (size_t)l * 3 * D_, qkvf, nullptr, M1, 3 * D_, D_);
        attn_k<<<dim3(H_, B_), 256, ATT_SMEM>>>(
            qkvf,            (long long)NT_ * 3 * D_, 3 * D_,
            qkvf + D_,       (long long)NT_ * 3 * D_, 3 * D_,
            qkvf + 2 * D_,   (long long)NT_ * 3 * D_, 3 * D_,
            at_hi, at_lo, NT_);
        launch_gemm1(EPI_RES, at_hi, wproj + (size_t)l * D_ * D_,
                     proj_b + (size_t)l * D_, xq, nullptr, M1, D_, D_);
        ln_k<<<M1, 256>>>(xq, ln2_s + (size_t)l * D_, ln2_b + (size_t)l * D_, h_hi, nullptr, D_);
        launch_gemm1(EPI_GELU, h_hi, wfc1 + (size_t)l * FF_ * D_,
                     fc1_b + (size_t)l * FF_, nullptr, ff_hi, M1, FF_, D_);
        launch_gemm1(EPI_RES, ff_hi, wfc2 + (size_t)l * D_ * FF_,
                     fc2_b + (size_t)l * D_, xq, nullptr, M1, D_, FF_);
    };

    // accurate (2-product fp16, A exact) transformer block on x0: prompted pass
    auto std_block = [&](int l) {
        ln_k<<<M1, 256>>>(x0, ln1_s + (size_t)l * D_, ln1_b + (size_t)l * D_, h_hi, h_lo, D_);
        launch_gemm2(EPI_F32, h_hi, h_lo, wqkv + (size_t)l * 3 * D_ * D_,
                     qkv_b + (size_t)l * 3 * D_, qkvf, nullptr, nullptr, M1, 3 * D_, D_);
        attn_k<<<dim3(H_, B_), 256, ATT_SMEM>>>(
            qkvf,            (long long)NT_ * 3 * D_, 3 * D_,
            qkvf + D_,       (long long)NT_ * 3 * D_, 3 * D_,
            qkvf + 2 * D_,   (long long)NT_ * 3 * D_, 3 * D_,
            at_hi, at_lo, NT_);
        launch_gemm2(EPI_RES, at_hi, at_lo, wproj + (size_t)l * D_ * D_,
                     proj_b + (size_t)l * D_, x0, nullptr, nullptr, M1, D_, D_);
        ln_k<<<M1, 256>>>(x0, ln2_s + (size_t)l * D_, ln2_b + (size_t)l * D_, h_hi, h_lo, D_);
        launch_gemm2(EPI_GELU, h_hi, h_lo, wfc1 + (size_t)l * FF_ * D_,
                     fc1_b + (size_t)l * FF_, nullptr, ff_hi, ff_lo, M1, FF_, D_);
        launch_gemm2(EPI_RES, ff_hi, ff_lo, wfc2 + (size_t)l * D_ * FF_,
                     fc2_b + (size_t)l * D_, x0, nullptr, nullptr, M1, D_, FF_);
    };

    // 1) frozen query pass: layers 0..10 full, layer 11 CLS-only tail
    for (int l = 0; l < L_ - 1; ++l) fast_block(l);
    {
        const int l = L_ - 1;
        const long long LDX = (long long)NT_ * D_;
        // LN1 on all rows (needed for K,V)
        ln_k<<<M1, 256>>>(xq, ln1_s + (size_t)l * D_, ln1_b + (size_t)l * D_, h_hi, nullptr, D_);
        // K,V for all tokens: [M1, 1536] into qkvf
        launch_gemm1(EPI_F32, h_hi, wqkv + (size_t)l * 3 * D_ * D_ + (size_t)D_ * D_,
                     qkv_b + (size_t)l * 3 * D_ + D_, qkvf, nullptr, M1, 2 * D_, D_);
        // Q for CLS rows only (strided A): [B_, 768] into qf
        launch_gemm1(EPI_F32, h_hi, wqkv + (size_t)l * 3 * D_ * D_,
                     qkv_b + (size_t)l * 3 * D_, qf, nullptr, B_, D_, D_, LDX, D_);
        // CLS attention -> at_hi [B_, 768]
        attn_cls_k<<<dim3(H_, B_), 256, ATT_SMEM>>>(qf, qkvf, at_hi);
        // proj on 64 rows, residual into xq CLS rows (strided C)
        launch_gemm1(EPI_RES, at_hi, wproj + (size_t)l * D_ * D_,
                     proj_b + (size_t)l * D_, xq, nullptr, B_, D_, D_, D_, LDX);
        // LN2 on CLS rows (strided in), compact out
        ln_k<<<B_, 256>>>(xq, ln2_s + (size_t)l * D_, ln2_b + (size_t)l * D_, h_hi, nullptr, LDX);
        launch_gemm1(EPI_GELU, h_hi, wfc1 + (size_t)l * FF_ * D_,
                     fc1_b + (size_t)l * FF_, nullptr, ff_hi, B_, FF_, D_);
        launch_gemm1(EPI_RES, ff_hi, wfc2 + (size_t)l * D_ * FF_,
                     fc2_b + (size_t)l * D_, xq, nullptr, B_, D_, FF_, FF_, LDX);
    }
    select_k<<<B_, 256>>>(xq, key_emb, idx);

    // 2) prompted pass runs directly on x0
    for (int l = 0; l < L_; ++l) {
        const bool isG = (l < 2), isEL = (l >= 2 && l < 5);
        if (!isG && !isEL) { std_block(l); continue; }
        const int plen = isG ? 5 : 20;
        const int pi   = isG ? l : (l - 2);
        const int nkl  = NT_ + plen;
        const int Mk   = B_ * nkl;

        ln_k<<<M1, 256>>>(x0, ln1_s + (size_t)l * D_, ln1_b + (size_t)l * D_, h_hi, h_lo, D_);
        {
            size_t n = (size_t)Mk * D_;
            concat_k<<<(unsigned)((n + 255) / 256), 256>>>(
                h_hi, h_lo, g_prompts, e_prompts, idx,
                xk_hi, xk_lo, xv_hi, xv_lo, nkl, plen, pi, isEL ? 1 : 0);
        }
        const size_t wo = (size_t)l * 3 * D_ * D_;
        const float* bl = qkv_b + (size_t)l * 3 * D_;
        launch_gemm2(EPI_F32, h_hi, h_lo, wqkv + wo, bl, qf, nullptr, nullptr, M1, D_, D_);
        launch_gemm2(EPI_F32, xk_hi, xk_lo, wqkv + wo + (size_t)D_ * D_,
                     bl + D_, kf, nullptr, nullptr, Mk, D_, D_);
        launch_gemm2(EPI_F32, xv_hi, xv_lo, wqkv + wo + (size_t)2 * D_ * D_,
                     bl + 2 * D_, vf, nullptr, nullptr, Mk, D_, D_);
        attn_k<<<dim3(H_, B_), 256, ATT_SMEM>>>(
            qf, (long long)NT_ * D_, D_,
            kf, (long long)nkl * D_, D_,
            vf, (long long)nkl * D_, D_,
            at_hi, at_lo, nkl);
        launch_gemm2(EPI_RES, at_hi, at_lo, wproj + (size_t)l * D_ * D_,
                     proj_b + (size_t)l * D_, x0, nullptr, nullptr, M1, D_, D_);
        ln_k<<<M1, 256>>>(x0, ln2_s + (size_t)l * D_, ln2_b + (size_t)l * D_, h_hi, h_lo, D_);
        launch_gemm2(EPI_GELU, h_hi, h_lo, wfc1 + (size_t)l * FF_ * D_,
                     fc1_b + (size_t)l * FF_, nullptr, ff_hi, ff_lo, M1, FF_, D_);
        launch_gemm2(EPI_RES, ff_hi, ff_lo, wfc2 + (size_t)l * D_ * FF_,
                     fc2_b + (size_t)l * D_, x0, nullptr, nullptr, M1, D_, FF_);
    }

    // 3) head
    head_k<<<B_, 256>>>(x0, norm_s, norm_b, head_w, head_b, mask_param, idx, out);
}

// round 16
// speedup vs baseline: 1.7007x; 1.0445x over previous
#include <cuda_runtime.h>
#include <cuda_fp16.h>
#include <cstdint>
#include <cstddef>

#define DI __device__ __forceinline__

// ---------------- problem dims ----------------
constexpr int L_ = 12, D_ = 768, H_ = 12, FF_ = 3072;
constexpr int B_ = 64, NP_ = 196, NT_ = 197, NC_ = 100, T_ = 10;
constexpr int M1 = B_ * NT_;        // 12608 token rows
constexpr int NKMAX = 217;          // 197 + 20 (e-prompt layers)
constexpr int MKMAX = B_ * NKMAX;   // 13888
constexpr int KSTR = 228;           // fp32 attention K/V smem row stride
constexpr int PPAD = 224;           // padded key count (mult of 32)
constexpr int KHQ = 68;             // fp16 attention row stride (halves)

// ---------------- device scratch (static, no runtime alloc) ----------------
__device__ float g_xq  [(size_t)M1 * D_];       // query-pass stream
__device__ float g_x0  [(size_t)M1 * D_];       // prompted-pass stream
__device__ float g_ptmp[(size_t)B_ * NP_ * D_];
__device__ float g_qkvf[(size_t)M1 * 3 * D_];
__device__ float g_qf  [(size_t)M1 * D_];
__device__ float g_kf  [(size_t)MKMAX * D_];
__device__ float g_vf  [(size_t)MKMAX * D_];
__device__ int   g_idx [B_];
// fp16 hi/lo activation pairs (A-side operands) — query chain + serial prompted
__device__ __half g_h_hi [(size_t)M1 * D_];
__device__ __half g_h_lo [(size_t)M1 * D_];
__device__ __half g_at_hi[(size_t)M1 * D_];
__device__ __half g_at_lo[(size_t)M1 * D_];
__device__ __half g_ff_hi[(size_t)M1 * FF_];
__device__ __half g_ff_lo[(size_t)M1 * FF_];
__device__ __half g_xk_hi[(size_t)MKMAX * D_];
__device__ __half g_xk_lo[(size_t)MKMAX * D_];
__device__ __half g_xv_hi[(size_t)MKMAX * D_];
__device__ __half g_xv_lo[(size_t)MKMAX * D_];
__device__ __half g_p_hi [(size_t)B_ * NP_ * D_];
__device__ __half g_p_lo [(size_t)B_ * NP_ * D_];
// dedicated buffers for overlapped prompted layers 0-1 (no aliasing with query chain)
__device__ float  g_q2  [(size_t)M1 * D_];
__device__ float  g_k2  [(size_t)MKMAX * D_];
__device__ float  g_v2  [(size_t)MKMAX * D_];
__device__ __half g_h2_hi [(size_t)M1 * D_];
__device__ __half g_h2_lo [(size_t)M1 * D_];
__device__ __half g_at2_hi[(size_t)M1 * D_];
__device__ __half g_at2_lo[(size_t)M1 * D_];
__device__ __half g_ff2_hi[(size_t)M1 * FF_];
__device__ __half g_ff2_lo[(size_t)M1 * FF_];
// fp16 weights (hi only — B-side operands)
__device__ __half g_wpatch[(size_t)D_ * D_];
__device__ __half g_wqkv  [(size_t)L_ * 3 * D_ * D_];
__device__ __half g_wproj [(size_t)L_ * D_ * D_];
__device__ __half g_wfc1  [(size_t)L_ * FF_ * D_];
__device__ __half g_wfc2  [(size_t)L_ * D_ * FF_];

// ---------------- PTX helpers ----------------
DI uint32_t sptr(const void* p) { return (uint32_t)__cvta_generic_to_shared(p); }

DI void cp16(void* s, const void* g, bool pred) {
    asm volatile("cp.async.cg.shared.global [%0], [%1], 16, %2;\n"
                 :: "r"(sptr(s)), "l"(g), "r"(pred ? 16 : 0));
}
DI void cpcommit() { asm volatile("cp.async.commit_group;\n" ::); }
DI void cpwait0()  { asm volatile("cp.async.wait_group 0;\n" ::); }
DI void cpwait1()  { asm volatile("cp.async.wait_group 1;\n" ::); }

DI void ldm4(uint32_t* r, const void* p) {
    asm volatile("ldmatrix.sync.aligned.m8n8.x4.shared.b16 {%0,%1,%2,%3}, [%4];\n"
                 : "=r"(r[0]), "=r"(r[1]), "=r"(r[2]), "=r"(r[3])
                 : "r"(sptr(p)) : "memory");
}
DI void mma_f16(float* d, const uint32_t* a, const uint32_t* b) {
    asm volatile("mma.sync.aligned.m16n8k16.row.col.f32.f16.f16.f32 "
                 "{%0,%1,%2,%3}, {%4,%5,%6,%7}, {%8,%9}, {%0,%1,%2,%3};\n"
                 : "+f"(d[0]), "+f"(d[1]), "+f"(d[2]), "+f"(d[3])
                 : "r"(a[0]), "r"(a[1]), "r"(a[2]), "r"(a[3]),
                   "r"(b[0]), "r"(b[1]));
}
DI float gelu_f(float v) { return 0.5f * v * (1.f + erff(v * 0.70710678118654752f)); }
DI void split_h(float v, __half& hi, __half& lo) {
    hi = __float2half_rn(v);
    lo = __float2half_rn(v - __half2float(hi));
}

constexpr int EPI_F32 = 0, EPI_GELU = 1, EPI_RES = 2;
constexpr int AS = 40;
constexpr int TILE_ELE = 128 * AS;            // 5120 halves / tile
constexpr int SMEM2 = 3 * 3 * TILE_ELE * 2;   // 92160 B
constexpr int SMEM1 = 3 * 2 * TILE_ELE * 2;   // 61440 B

// ============ fp16 split TN GEMM: C[M,N] = A[M,K] * B[N,K]^T ============
template<int NPROD, int EPI>
__global__ __launch_bounds__(256, 2) void gemm_k(
    const __half* __restrict__ Ahi, const __half* __restrict__ Alo,
    const __half* __restrict__ Bw,
    const float* __restrict__ bias, float* __restrict__ Cf,
    __half* __restrict__ Cb_hi, __half* __restrict__ Cb_lo,
    int M, int N, int K, long long lda, long long ldc)
{
    constexpr int NT = (NPROD == 2) ? 3 : 2;
    extern __shared__ __half smem[];

    const int tid = threadIdx.x;
    const int m0 = blockIdx.y * 128, n0 = blockIdx.x * 128;
    const int wid = tid >> 5, lane = tid & 31;
    const int wm = wid >> 2, wn = wid & 3;

    float acc[4][4][4];
    #pragma unroll
    for (int a = 0; a < 4; a++)
        #pragma unroll
        for (int b = 0; b < 4; b++)
            #pragma unroll
            for (int c = 0; c < 4; c++) acc[a][b][c] = 0.f;

    const int nIt = K >> 5;

    auto load_stage = [&](int st, int k0) {
        __half* base = smem + st * NT * TILE_ELE;
        #pragma unroll
        for (int i = 0; i < 2; i++) {
            int idx = tid + i * 256;
            int r = idx >> 2, c = (idx & 3) << 3;
            int gr = m0 + r;
            bool p = gr < M;
            size_t aoff = (size_t)(p ? gr : 0) * lda + k0 + c;
            size_t boff = (size_t)(n0 + r) * K + k0 + c;
            cp16(base + r * AS + c, Ahi + aoff, p);
            if (NPROD == 2) cp16(base + TILE_ELE + r * AS + c, Alo + aoff, p);
            cp16(base + (NPROD == 2 ? 2 : 1) * TILE_ELE + r * AS + c, Bw + boff, true);
        }
        cpcommit();
    };

    load_stage(0, 0);
    load_stage(1, 32);
    cpwait1();
    __syncthreads();

    for (int it = 0; it < nIt; ++it) {
        const bool pre = (it + 2 < nIt);
        int stn = it + 2;
        if (pre) load_stage(stn - 3 * (stn / 3), stn << 5);
        const int buf = it - 3 * (it / 3);
        __half* sb = smem + buf * NT * TILE_ELE;
        __half* sAh = sb;
        __half* sAl = sb + TILE_ELE;
        __half* sBh = sb + (NPROD == 2 ? 2 : 1) * TILE_ELE;
        #pragma unroll
        for (int kk = 0; kk < 2; ++kk) {
            const int kcol = kk << 4;
            uint32_t bh[4][2], af[4][4];
            #pragma unroll
            for (int j = 0; j < 2; ++j) {
                int row = wn * 32 + j * 16 + (lane & 7) + ((lane >> 4) << 3);
                int col = kcol + (((lane >> 3) & 1) << 3);
                uint32_t t[4];
                ldm4(t, &sBh[row * AS + col]);
                bh[2 * j][0] = t[0]; bh[2 * j][1] = t[1];
                bh[2 * j + 1][0] = t[2]; bh[2 * j + 1][1] = t[3];
            }
            #pragma unroll
            for (int mt = 0; mt < 4; ++mt) {
                int row = wm * 64 + mt * 16 + (lane & 15);
                int col = kcol + ((lane >> 4) << 3);
                ldm4(af[mt], &sAh[row * AS + col]);
            }
            #pragma unroll
            for (int mt = 0; mt < 4; ++mt)
                #pragma unroll
                for (int nt = 0; nt < 4; ++nt)
                    mma_f16(acc[mt][nt], af[mt], bh[nt]);
            if (NPROD == 2) {
                #pragma unroll
                for (int mt = 0; mt < 4; ++mt) {
                    int row = wm * 64 + mt * 16 + (lane & 15);
                    int col = kcol + ((lane >> 4) << 3);
                    ldm4(af[mt], &sAl[row * AS + col]);
                }
                #pragma unroll
                for (int mt = 0; mt < 4; ++mt)
                    #pragma unroll
                    for (int nt = 0; nt < 4; ++nt)
                        mma_f16(acc[mt][nt], af[mt], bh[nt]);
            }
        }
        if (pre) cpwait1(); else cpwait0();
        __syncthreads();
    }

    const int g = lane >> 2, tg = lane & 3;
    #pragma unroll
    for (int mt = 0; mt < 4; ++mt) {
        #pragma unroll
        for (int nt = 0; nt < 4; ++nt) {
            const int col = n0 + wn * 32 + nt * 8 + tg * 2;
            #pragma unroll
            for (int hh = 0; hh < 2; ++hh) {
                const int r = m0 + wm * 64 + mt * 16 + g + hh * 8;
                if (r < M) {
                    float v0 = acc[mt][nt][2 * hh + 0] + bias[col];
                    float v1 = acc[mt][nt][2 * hh + 1] + bias[col + 1];
                    size_t off = (size_t)r * ldc + col;
                    if (EPI == EPI_F32) {
                        float2 o; o.x = v0; o.y = v1;
                        *reinterpret_cast<float2*>(Cf + off) = o;
                    } else if (EPI == EPI_GELU) {
                        float g0 = gelu_f(v0), g1 = gelu_f(v1);
                        __half h0, l0, h1, l1;
                        split_h(g0, h0, l0); split_h(g1, h1, l1);
                        __half2 oh; oh.x = h0; oh.y = h1;
                        *reinterpret_cast<__half2*>(Cb_hi + off) = oh;
                        if (NPROD == 2) {
                            __half2 ol; ol.x = l0; ol.y = l1;
                            *reinterpret_cast<__half2*>(Cb_lo + off) = ol;
                        }
                    } else {
                        float2 o = *reinterpret_cast<float2*>(Cf + off);
                        o.x += v0; o.y += v1;
                        *reinterpret_cast<float2*>(Cf + off) = o;
                    }
                }
            }
        }
    }
}

// ---------------- prompted-pass attention (fp32, bit-identical) ----------------
__global__ __launch_bounds__(256) void attn_k(
    const float* __restrict__ qp, long long qbs, int qrs,
    const float* __restrict__ kp, long long kbs, int krs,
    const float* __restrict__ vp, long long vbs, int vrs,
    __half* __restrict__ out_hi, __half* __restrict__ out_lo, int nk)
{
    extern __shared__ float skvf[];
    float* Ks = skvf;
    float* Vs = skvf + 64 * KSTR;
    float* Ps = skvf + 128 * KSTR;
    const int h = blockIdx.x, b = blockIdx.y;
    const int tid = threadIdx.x, lane = tid & 31, w = tid >> 5;

    const float* kb = kp + (long long)b * kbs + h * 64;
    const float* vb = vp + (long long)b * vbs + h * 64;
    for (int i = tid; i < 64 * PPAD; i += 256) {
        int j = i >> 6, d = i & 63;
        float kvv = 0.f, vvv = 0.f;
        if (j < nk) {
            kvv = kb[(long long)j * krs + d];
            vvv = vb[(long long)j * vrs + d];
        }
        Ks[d * KSTR + j] = kvv;
        Vs[d * KSTR + j] = vvv;
    }
    __syncthreads();

    const int cnt = (nk - lane + 31) >> 5;
    const int nk4q = (nk + 3) >> 2;
    float* pw = Ps + w * PPAD;
    const float4* pw4 = (const float4*)pw;
    const float4* v0p = (const float4*)(Vs + lane * KSTR);
    const float4* v1p = (const float4*)(Vs + (lane + 32) * KSTR);

    for (int qi = w; qi < NT_; qi += 8) {
        const float* qrow = qp + (long long)b * qbs + (long long)qi * qrs + h * 64;
        const float4* q4 = (const float4*)qrow;
        float qv[64];
        #pragma unroll
        for (int t = 0; t < 16; ++t) {
            float4 v = q4[t];
            qv[4 * t] = v.x; qv[4 * t + 1] = v.y; qv[4 * t + 2] = v.z; qv[4 * t + 3] = v.w;
        }

        float s[7];
        #pragma unroll
        for (int jj = 0; jj < 7; ++jj) s[jj] = 0.f;
        #pragma unroll
        for (int d = 0; d < 64; ++d) {
            const float qd = qv[d];
            #pragma unroll
            for (int jj = 0; jj < 7; ++jj)
                if (jj < cnt) s[jj] += qd * Ks[d * KSTR + lane + jj * 32];
        }
        float m = -1e30f;
        #pragma unroll
        for (int jj = 0; jj < 7; ++jj)
            if (jj < cnt) { s[jj] *= 0.125f; m = fmaxf(m, s[jj]); }
        #pragma unroll
        for (int o = 16; o; o >>= 1) m = fmaxf(m, __shfl_xor_sync(0xffffffffu, m, o));
        float sum = 0.f;
        #pragma unroll
        for (int jj = 0; jj < 7; ++jj) {
            s[jj] = (jj < cnt) ? __expf(s[jj] - m) : 0.f;
            sum += s[jj];
        }
        #pragma unroll
        for (int o = 16; o; o >>= 1) sum += __shfl_xor_sync(0xffffffffu, sum, o);
        const float inv = 1.f / sum;

        #pragma unroll
        for (int jj = 0; jj < 7; ++jj)
            pw[lane + jj * 32] = s[jj] * inv;
        __syncwarp();

        float o0 = 0.f, o1 = 0.f;
        for (int j4 = 0; j4 < nk4q; ++j4) {
            float4 pp = pw4[j4];
            float4 a = v0p[j4];
            float4 c = v1p[j4];
            o0 += pp.x * a.x + pp.y * a.y + pp.z * a.z + pp.w * a.w;
            o1 += pp.x * c.x + pp.y * c.y + pp.z * c.z + pp.w * c.w;
        }
        __syncwarp();

        size_t base = ((size_t)(b * NT_ + qi)) * D_ + h * 64;
        __half h0, l0, h1, l1;
        split_h(o0, h0, l0); split_h(o1, h1, l1);
        out_hi[base + lane] = h0;      out_lo[base + lane] = l0;
        out_hi[base + lane + 32] = h1; out_lo[base + lane + 32] = l1;
    }
}

// ---------------- query-pass attention (fp16 K/V smem, 3 CTAs/SM) ----------------
constexpr int ATTQ_SMEM = 2 * (PPAD * KHQ * 2) + 8 * PPAD * 4;   // 68096 B
__global__ __launch_bounds__(256, 3) void attn_q_k(
    const float* __restrict__ qp, long long qbs, int qrs,
    const float* __restrict__ kp, long long kbs, int krs,
    const float* __restrict__ vp, long long vbs, int vrs,
    __half* __restrict__ out_hi, int nk)
{
    extern __shared__ char smemq[];
    __half* Ks = (__half*)smemq;                       // [PPAD][KHQ] row-major (key, dim)
    __half* Vs = Ks + PPAD * KHQ;                      // [PPAD][KHQ]
    float*  Ps = (float*)(Vs + PPAD * KHQ);            // [8][PPAD]
    const int h = blockIdx.x, b = blockIdx.y;
    const int tid = threadIdx.x, lane = tid & 31, w = tid >> 5;

    const float* kb = kp + (long long)b * kbs + h * 64;
    const float* vb = vp + (long long)b * vbs + h * 64;
    for (int i = tid; i < PPAD * 64; i += 256) {
        int j = i >> 6, d = i & 63;
        float kvv = 0.f, vvv = 0.f;
        if (j < nk) {
            kvv = kb[(long long)j * krs + d];
            vvv = vb[(long long)j * vrs + d];
        }
        Ks[j * KHQ + d] = __float2half_rn(kvv);
        Vs[j * KHQ + d] = __float2half_rn(vvv);
    }
    __syncthreads();

    const int cnt = (nk - lane + 31) >> 5;
    float* pw = Ps + w * PPAD;

    for (int qi = w; qi < NT_; qi += 8) {
        const float4* q4 = (const float4*)(qp + (long long)b * qbs + (long long)qi * qrs + h * 64);

        float s[7];
        #pragma unroll
        for (int jj = 0; jj < 7; ++jj) s[jj] = 0.f;
        #pragma unroll
        for (int jj = 0; jj < 7; ++jj) {
            if (jj < cnt) {
                const __half2* k2 = (const __half2*)(Ks + (lane + jj * 32) * KHQ);
                float acc = 0.f;
                #pragma unroll
                for (int t = 0; t < 16; ++t) {
                    float4 qv = __ldg(q4 + t);
                    float2 a = __half22float2(k2[2 * t]);
                    float2 c = __half22float2(k2[2 * t + 1]);
                    acc += qv.x * a.x + qv.y * a.y + qv.z * c.x + qv.w * c.y;
                }
                s[jj] = acc;
            }
        }
        float m = -1e30f;
        #pragma unroll
        for (int jj = 0; jj < 7; ++jj)
            if (jj < cnt) { s[jj] *= 0.125f; m = fmaxf(m, s[jj]); }
        #pragma unroll
        for (int o = 16; o; o >>= 1) m = fmaxf(m, __shfl_xor_sync(0xffffffffu, m, o));
        float sum = 0.f;
        #pragma unroll
        for (int jj = 0; jj < 7; ++jj) {
            s[jj] = (jj < cnt) ? __expf(s[jj] - m) : 0.f;
            sum += s[jj];
        }
        #pragma unroll
        for (int o = 16; o; o >>= 1) sum += __shfl_xor_sync(0xffffffffu, sum, o);
        const float inv = 1.f / sum;
        #pragma unroll
        for (int jj = 0; jj < 7; ++jj)
            pw[lane + jj * 32] = s[jj] * inv;
        __syncwarp();

        float o0 = 0.f, o1 = 0.f;
        for (int j = 0; j < nk; ++j) {
            float pp = pw[j];
            o0 += pp * __half2float(Vs[j * KHQ + lane]);
            o1 += pp * __half2float(Vs[j * KHQ + lane + 32]);
        }
        __syncwarp();

        size_t base = ((size_t)(b * NT_ + qi)) * D_ + h * 64;
        out_hi[base + lane]      = __float2half_rn(o0);
        out_hi[base + lane + 32] = __float2half_rn(o1);
    }
}

// ---------------- CLS-only attention (query pass tail layer, fp32) ----------------
__global__ __launch_bounds__(256) void attn_cls_k(
    const float* __restrict__ qcls, const float* __restrict__ kvf,
    __half* __restrict__ out)
{
    extern __shared__ float skvf[];
    float* Ks = skvf;
    float* Vs = skvf + 64 * KSTR;
    float* Ps = skvf + 128 * KSTR;
    const int h = blockIdx.x, b = blockIdx.y;
    const int tid = threadIdx.x;

    const float* kb = kvf + (size_t)b * NT_ * 1536 + h * 64;
    const float* vb = kb + 768;
    for (int i = tid; i < 64 * PPAD; i += 256) {
        int j = i >> 6, d = i & 63;
        float kvv = 0.f, vvv = 0.f;
        if (j < NT_) {
            kvv = kb[(size_t)j * 1536 + d];
            vvv = vb[(size_t)j * 1536 + d];
        }
        Ks[d * KSTR + j] = kvv;
        Vs[d * KSTR + j] = vvv;
    }
    __syncthreads();
    if (tid >= 32) return;
    const int lane = tid;
    const int cnt = (NT_ - lane + 31) >> 5;
    const float* qrow = qcls + (size_t)b * D_ + h * 64;
    float qv[64];
    #pragma unroll
    for (int d = 0; d < 64; ++d) qv[d] = qrow[d];

    float s[7];
    #pragma unroll
    for (int jj = 0; jj < 7; ++jj) s[jj] = 0.f;
    #pragma unroll
    for (int d = 0; d < 64; ++d) {
        const float qd = qv[d];
        #pragma unroll
        for (int jj = 0; jj < 7; ++jj)
            if (jj < cnt) s[jj] += qd * Ks[d * KSTR + lane + jj * 32];
    }
    float m = -1e30f;
    #pragma unroll
    for (int jj = 0; jj < 7; ++jj)
        if (jj < cnt) { s[jj] *= 0.125f; m = fmaxf(m, s[jj]); }
    #pragma unroll
    for (int o = 16; o; o >>= 1) m = fmaxf(m, __shfl_xor_sync(0xffffffffu, m, o));
    float sum = 0.f;
    #pragma unroll
    for (int jj = 0; jj < 7; ++jj) {
        s[jj] = (jj < cnt) ? __expf(s[jj] - m) : 0.f;
        sum += s[jj];
    }
    #pragma unroll
    for (int o = 16; o; o >>= 1) sum += __shfl_xor_sync(0xffffffffu, sum, o);
    const float inv = 1.f / sum;
    #pragma unroll
    for (int jj = 0; jj < 7; ++jj)
        Ps[lane + jj * 32] = s[jj] * inv;
    __syncwarp();

    const float4* pw4 = (const float4*)Ps;
    const float4* v0p = (const float4*)(Vs + lane * KSTR);
    const float4* v1p = (const float4*)(Vs + (lane + 32) * KSTR);
    const int nk4q = (NT_ + 3) >> 2;
    float o0 = 0.f, o1 = 0.f;
    for (int j4 = 0; j4 < nk4q; ++j4) {
        float4 pp = pw4[j4];
        float4 a = v0p[j4];
        float4 c = v1p[j4];
        o0 += pp.x * a.x + pp.y * a.y + pp.z * a.z + pp.w * a.w;
        o1 += pp.x * c.x + pp.y * c.y + pp.z * c.z + pp.w * c.w;
    }
    out[(size_t)b * D_ + h * 64 + lane]      = __float2half_rn(o0);
    out[(size_t)b * D_ + h * 64 + lane + 32] = __float2half_rn(o1);
}

// ---------------- layernorm (block per row) -> fp16 hi(/lo) ----------------
__global__ __launch_bounds__(256) void ln_k(const float* __restrict__ x,
    const float* __restrict__ s, const float* __restrict__ b,
    __half* __restrict__ out_hi, __half* __restrict__ out_lo, long long ldx)
{
    const int row = blockIdx.x, tid = threadIdx.x;
    const float* xr = x + (size_t)row * ldx;
    float v[3], sum = 0.f, sq = 0.f;
    #pragma unroll
    for (int i = 0; i < 3; i++) { v[i] = xr[tid + i * 256]; sum += v[i]; sq += v[i] * v[i]; }
    __shared__ float rs[8], rq[8];
    #pragma unroll
    for (int o = 16; o; o >>= 1) {
        sum += __shfl_xor_sync(0xffffffffu, sum, o);
        sq  += __shfl_xor_sync(0xffffffffu, sq, o);
    }
    if ((tid & 31) == 0) { rs[tid >> 5] = sum; rq[tid >> 5] = sq; }
    __syncthreads();
    sum = 0.f; sq = 0.f;
    #pragma unroll
    for (int i = 0; i < 8; i++) { sum += rs[i]; sq += rq[i]; }
    const float mu = sum * (1.f / D_);
    const float var = sq * (1.f / D_) - mu * mu;
    const float rstd = rsqrtf(var + 1e-6f);
    #pragma unroll
    for (int i = 0; i < 3; i++) {
        int c = tid + i * 256;
        float y = (v[i] - mu) * rstd * s[c] + b[c];
        __half h, l;
        split_h(y, h, l);
        out_hi[(size_t)row * D_ + c] = h;
        if (out_lo) out_lo[(size_t)row * D_ + c] = l;
    }
}

// ---------------- small utility kernels ----------------
__global__ void conv_h4_k(const float4* __restrict__ in, __half2* __restrict__ o, size_t n4) {
    size_t i = (size_t)blockIdx.x * 256 + threadIdx.x;
    if (i < n4) {
        float4 v = in[i];
        o[2 * i]     = __floats2half2_rn(v.x, v.y);
        o[2 * i + 1] = __floats2half2_rn(v.z, v.w);
    }
}
__global__ void prep_k(const float* __restrict__ in, const float* __restrict__ pw,
                       __half* __restrict__ p_hi, __half* __restrict__ p_lo,
                       __half* __restrict__ w_hi) {
    size_t i = (size_t)blockIdx.x * 256 + threadIdx.x;
    const size_t NPT = (size_t)B_ * NP_ * D_;
    if (i < NPT) {
        int d = (int)(i % D_), r = (int)((i / D_) % NP_), b = (int)(i / ((size_t)D_ * NP_));
        int hp = r / 14, wp = r % 14;
        int c = d >> 8, ph = (d >> 4) & 15, pwc = d & 15;
        float v = in[(((size_t)b * 3 + c) * 224 + hp * 16 + ph) * 224 + wp * 16 + pwc];
        __half h, l;
        split_h(v, h, l);
        p_hi[i] = h; p_lo[i] = l;
    } else if (i < NPT + (size_t)D_ * D_) {
        size_t j = i - NPT;
        w_hi[j] = __float2half_rn(pw[j]);
    }
}
__global__ void assemble_k(const float* __restrict__ ptmp, const float* __restrict__ cls,
                           const float* __restrict__ pos, float* __restrict__ x0,
                           float* __restrict__ xq) {
    size_t i = (size_t)blockIdx.x * 256 + threadIdx.x;
    if (i >= (size_t)B_ * NT_ * D_) return;
    int d = (int)(i % D_), j = (int)((i / D_) % NT_), b = (int)(i / ((size_t)D_ * NT_));
    float v = (j == 0 ? cls[d] : ptmp[((size_t)b * NP_ + j - 1) * D_ + d]) + pos[(size_t)j * D_ + d];
    x0[i] = v; xq[i] = v;
}
__global__ void concat_k(const __half* __restrict__ h_hi, const __half* __restrict__ h_lo,
                         const float* __restrict__ gp, const float* __restrict__ ep,
                         const int* __restrict__ idx,
                         __half* __restrict__ xk_hi, __half* __restrict__ xk_lo,
                         __half* __restrict__ xv_hi, __half* __restrict__ xv_lo,
                         int nkl, int plen, int pi, int isE)
{
    size_t i = (size_t)blockIdx.x * 256 + threadIdx.x;
    if (i >= (size_t)B_ * nkl * D_) return;
    int d = (int)(i % D_);
    int row = (int)(i / D_);
    int b = row / nkl, j = row % nkl;
    if (j < NT_) {
        size_t src = ((size_t)(b * NT_ + j)) * D_ + d;
        __half wh = h_hi[src], wl = h_lo[src];
        xk_hi[i] = wh; xk_lo[i] = wl;
        xv_hi[i] = wh; xv_lo[i] = wl;
    } else {
        int jj = j - NT_;
        const float* base = isE ? (ep + (size_t)idx[b] * 120 * D_) : gp;
        float vk = base[((size_t)(2 * pi) * plen + jj) * D_ + d];
        float vv = base[((size_t)(2 * pi + 1) * plen + jj) * D_ + d];
        __half h, l;
        split_h(vk, h, l); xk_hi[i] = h; xk_lo[i] = l;
        split_h(vv, h, l); xv_hi[i] = h; xv_lo[i] = l;
    }
}
__global__ __launch_bounds__(256) void select_k(const float* __restrict__ x,
    const float* __restrict__ key, int* __restrict__ idx)
{
    const int b = blockIdx.x, tid = threadIdx.x;
    const float* q = x + (size_t)b * NT_ * D_;
    float pq = 0.f, pd[T_], pk[T_];
    #pragma unroll
    for (int t = 0; t < T_; t++) { pd[t] = 0.f; pk[t] = 0.f; }
    for (int i = 0; i < 3; i++) {
        int d = tid + i * 256;
        float qd = q[d];
        pq += qd * qd;
        #pragma unroll
        for (int t = 0; t < T_; t++) {
            float kv = key[(size_t)t * D_ + d];
            pd[t] += qd * kv; pk[t] += kv * kv;
        }
    }
    __shared__ float red[256];
    __shared__ float tot[21];
    for (int a = 0; a < 21; a++) {
        float v = (a == 0) ? pq : (a <= 10 ? pd[a - 1] : pk[a - 11]);
        red[tid] = v; __syncthreads();
        for (int st = 128; st > 0; st >>= 1) {
            if (tid < st) red[tid] += red[tid + st];
            __syncthreads();
        }
        if (tid == 0) tot[a] = red[0];
        __syncthreads();
    }
    if (tid == 0) {
        float qn = sqrtf(tot[0]) + 1e-8f;
        float best = -2e30f; int bi = 0;
        for (int t = 0; t < T_; t++) {
            float cosv = tot[1 + t] / (qn * (sqrtf(tot[11 + t]) + 1e-8f));
            if (cosv > best) { best = cosv; bi = t; }
        }
        idx[b] = bi;
    }
}
__global__ __launch_bounds__(256) void head_k(const float* __restrict__ x,
    const float* __restrict__ ns, const float* __restrict__ nb,
    const float* __restrict__ hw, const float* __restrict__ hb,
    const float* __restrict__ mp, const int* __restrict__ idx,
    float* __restrict__ out)
{
    const int b = blockIdx.x, tid = threadIdx.x;
    __shared__ float feat[D_];
    __shared__ float rs[8], rq[8];
    const float* xr = x + (size_t)b * NT_ * D_;
    float v[3], sum = 0.f, sq = 0.f;
    #pragma unroll
    for (int i = 0; i < 3; i++) { v[i] = xr[tid + i * 256]; sum += v[i]; sq += v[i] * v[i]; }
    #pragma unroll
    for (int o = 16; o; o >>= 1) {
        sum += __shfl_xor_sync(0xffffffffu, sum, o);
        sq  += __shfl_xor_sync(0xffffffffu, sq, o);
    }
    if ((tid & 31) == 0) { rs[tid >> 5] = sum; rq[tid >> 5] = sq; }
    __syncthreads();
    sum = 0.f; sq = 0.f;
    #pragma unroll
    for (int i = 0; i < 8; i++) { sum += rs[i]; sq += rq[i]; }
    const float mu = sum * (1.f / D_);
    const float var = sq * (1.f / D_) - mu * mu;
    const float rstd = rsqrtf(var + 1e-6f);
    #pragma unroll
    for (int i = 0; i < 3; i++) {
        int c = tid + i * 256;
        feat[c] = (v[i] - mu) * rstd * ns[c] + nb[c];
    }
    __syncthreads();
    if (tid < NC_) {
        float a = hb[tid];
        const float* wr = hw + (size_t)tid * D_;
        for (int d = 0; d < D_; d++) a += feat[d] * wr[d];
        float m = mp[(size_t)idx[b] * NC_ + tid];
        out[b * NC_ + tid] = a * 2.f / (1.f + expf(-m));
    }
}

// ---------------- host side ----------------
static inline void launch_gemm2(cudaStream_t st, int epi,
                                const __half* Ahi, const __half* Alo, const __half* Bw,
                                const float* bias, float* Cf,
                                __half* Cb_hi, __half* Cb_lo,
                                int M, int N, int K,
                                long long lda = -1, long long ldc = -1)
{
    if (lda < 0) lda = K;
    if (ldc < 0) ldc = N;
    dim3 grid(N / 128, (M + 127) / 128);
    switch (epi) {
        case 0:  gemm_k<2, 0><<<grid, 256, SMEM2, st>>>(Ahi, Alo, Bw, bias, Cf, Cb_hi, Cb_lo, M, N, K, lda, ldc); break;
        case 1:  gemm_k<2, 1><<<grid, 256, SMEM2, st>>>(Ahi, Alo, Bw, bias, Cf, Cb_hi, Cb_lo, M, N, K, lda, ldc); break;
        default: gemm_k<2, 2><<<grid, 256, SMEM2, st>>>(Ahi, Alo, Bw, bias, Cf, Cb_hi, Cb_lo, M, N, K, lda, ldc); break;
    }
}
static inline void launch_gemm1(cudaStream_t st, int epi,
                                const __half* A, const __half* Bw,
                                const float* bias, float* Cf, __half* Cb_hi,
                                int M, int N, int K,
                                long long lda = -1, long long ldc = -1)
{
    if (lda < 0) lda = K;
    if (ldc < 0) ldc = N;
    dim3 grid(N / 128, (M + 127) / 128);
    switch (epi) {
        case 0:  gemm_k<1, 0><<<grid, 256, SMEM1, st>>>(A, nullptr, Bw, bias, Cf, Cb_hi, nullptr, M, N, K, lda, ldc); break;
        case 1:  gemm_k<1, 1><<<grid, 256, SMEM1, st>>>(A, nullptr, Bw, bias, Cf, Cb_hi, nullptr, M, N, K, lda, ldc); break;
        default: gemm_k<1, 2><<<grid, 256, SMEM1, st>>>(A, nullptr, Bw, bias, Cf, Cb_hi, nullptr, M, N, K, lda, ldc); break;
    }
}

extern "C" void kernel_launch(void* const* d_in, const int* in_sizes, int n_in,
                              void* d_out, int out_size)
{
    (void)in_sizes; (void)n_in; (void)out_size;
    const float* inputs     = (const float*)d_in[0];
    const float* patch_w    = (const float*)d_in[1];
    const float* patch_b    = (const float*)d_in[2];
    const float* cls_token  = (const float*)d_in[3];
    const float* pos_embed  = (const float*)d_in[4];
    const float* ln1_s      = (const float*)d_in[5];
    const float* ln1_b      = (const float*)d_in[6];
    const float* qkv_w      = (const float*)d_in[7];
    const float* qkv_b      = (const float*)d_in[8];
    const float* proj_w     = (const float*)d_in[9];
    const float* proj_b     = (const float*)d_in[10];
    const float* ln2_s      = (const float*)d_in[11];
    const float* ln2_b      = (const float*)d_in[12];
    const float* fc1_w      = (const float*)d_in[13];
    const float* fc1_b      = (const float*)d_in[14];
    const float* fc2_w      = (const float*)d_in[15];
    const float* fc2_b      = (const float*)d_in[16];
    const float* norm_s     = (const float*)d_in[17];
    const float* norm_b     = (const float*)d_in[18];
    const float* head_w     = (const float*)d_in[19];
    const float* head_b     = (const float*)d_in[20];
    const float* key_emb    = (const float*)d_in[21];
    const float* mask_param = (const float*)d_in[22];
    const float* g_prompts  = (const float*)d_in[23];
    const float* e_prompts  = (const float*)d_in[24];
    float* out = (float*)d_out;

    void* p;
    cudaGetSymbolAddress(&p, g_xq);     float* xq     = (float*)p;
    cudaGetSymbolAddress(&p, g_x0);     float* x0     = (float*)p;
    cudaGetSymbolAddress(&p, g_ptmp);   float* ptmp   = (float*)p;
    cudaGetSymbolAddress(&p, g_qkvf);   float* qkvf   = (float*)p;
    cudaGetSymbolAddress(&p, g_qf);     float* qf     = (float*)p;
    cudaGetSymbolAddress(&p, g_kf);     float* kf     = (float*)p;
    cudaGetSymbolAddress(&p, g_vf);     float* vf     = (float*)p;
    cudaGetSymbolAddress(&p, g_idx);    int*   idx    = (int*)p;
    cudaGetSymbolAddress(&p, g_h_hi);   __half* h_hi  = (__half*)p;
    cudaGetSymbolAddress(&p, g_h_lo);   __half* h_lo  = (__half*)p;
    cudaGetSymbolAddress(&p, g_at_hi);  __half* at_hi = (__half*)p;
    cudaGetSymbolAddress(&p, g_at_lo);  __half* at_lo = (__half*)p;
    cudaGetSymbolAddress(&p, g_ff_hi);  __half* ff_hi = (__half*)p;
    cudaGetSymbolAddress(&p, g_ff_lo);  __half* ff_lo = (__half*)p;
    cudaGetSymbolAddress(&p, g_xk_hi);  __half* xk_hi = (__half*)p;
    cudaGetSymbolAddress(&p, g_xk_lo);  __half* xk_lo = (__half*)p;
    cudaGetSymbolAddress(&p, g_xv_hi);  __half* xv_hi = (__half*)p;
    cudaGetSymbolAddress(&p, g_xv_lo);  __half* xv_lo = (__half*)p;
    cudaGetSymbolAddress(&p, g_p_hi);   __half* p_hi  = (__half*)p;
    cudaGetSymbolAddress(&p, g_p_lo);   __half* p_lo  = (__half*)p;
    cudaGetSymbolAddress(&p, g_q2);     float* q2     = (float*)p;
    cudaGetSymbolAddress(&p, g_k2);     float* k2     = (float*)p;
    cudaGetSymbolAddress(&p, g_v2);     float* v2     = (float*)p;
    cudaGetSymbolAddress(&p, g_h2_hi);  __half* h2_hi = (__half*)p;
    cudaGetSymbolAddress(&p, g_h2_lo);  __half* h2_lo = (__half*)p;
    cudaGetSymbolAddress(&p, g_at2_hi); __half* at2_hi= (__half*)p;
    cudaGetSymbolAddress(&p, g_at2_lo); __half* at2_lo= (__half*)p;
    cudaGetSymbolAddress(&p, g_ff2_hi); __half* ff2_hi= (__half*)p;
    cudaGetSymbolAddress(&p, g_ff2_lo); __half* ff2_lo= (__half*)p;
    cudaGetSymbolAddress(&p, g_wpatch); __half* wpatch = (__half*)p;
    cudaGetSymbolAddress(&p, g_wqkv);   __half* wqkv   = (__half*)p;
    cudaGetSymbolAddress(&p, g_wproj);  __half* wproj  = (__half*)p;
    cudaGetSymbolAddress(&p, g_wfc1);   __half* wfc1   = (__half*)p;
    cudaGetSymbolAddress(&p, g_wfc2);   __half* wfc2   = (__half*)p;

    const int ATT_SMEM = (128 * KSTR + 8 * PPAD) * (int)sizeof(float);   // 123904
    cudaFuncSetAttribute(attn_k, cudaFuncAttributeMaxDynamicSharedMemorySize, ATT_SMEM);
    cudaFuncSetAttribute(attn_cls_k, cudaFuncAttributeMaxDynamicSharedMemorySize, ATT_SMEM);
    cudaFuncSetAttribute(attn_q_k, cudaFuncAttributeMaxDynamicSharedMemorySize, ATTQ_SMEM);
    cudaFuncSetAttribute(gemm_k<2, 0>, cudaFuncAttributeMaxDynamicSharedMemorySize, SMEM2);
    cudaFuncSetAttribute(gemm_k<2, 1>, cudaFuncAttributeMaxDynamicSharedMemorySize, SMEM2);
    cudaFuncSetAttribute(gemm_k<2, 2>, cudaFuncAttributeMaxDynamicSharedMemorySize, SMEM2);
    cudaFuncSetAttribute(gemm_k<1, 0>, cudaFuncAttributeMaxDynamicSharedMemorySize, SMEM1);
    cudaFuncSetAttribute(gemm_k<1, 1>, cudaFuncAttributeMaxDynamicSharedMemorySize, SMEM1);
    cudaFuncSetAttribute(gemm_k<1, 2>, cudaFuncAttributeMaxDynamicSharedMemorySize, SMEM1);

    // fork/join resources (created once, on the un-captured correctness call)
    static cudaStream_t s2 = nullptr;
    static cudaEvent_t evF = nullptr, evJ = nullptr;
    if (!s2) {
        cudaStreamCreateWithFlags(&s2, cudaStreamNonBlocking);
        cudaEventCreateWithFlags(&evF, cudaEventDisableTiming);
        cudaEventCreateWithFlags(&evJ, cudaEventDisableTiming);
    }
    cudaStream_t s0 = 0;

    auto conv = [](const float* in, __half* o, size_t n) {
        size_t n4 = n >> 2;
        conv_h4_k<<<(unsigned)((n4 + 255) / 256), 256>>>((const float4*)in, (__half2*)o, n4);
    };
    conv(qkv_w,  wqkv,  (size_t)L_ * 3 * D_ * D_);
    conv(proj_w, wproj, (size_t)L_ * D_ * D_);
    conv(fc1_w,  wfc1,  (size_t)L_ * FF_ * D_);
    conv(fc2_w,  wfc2,  (size_t)L_ * D_ * FF_);
    {
        size_t n = (size_t)B_ * NP_ * D_ + (size_t)D_ * D_;
        prep_k<<<(unsigned)((n + 255) / 256), 256>>>(inputs, patch_w, p_hi, p_lo, wpatch);
        launch_gemm2(s0, EPI_F32, p_hi, p_lo, wpatch, patch_b,
                     ptmp, nullptr, nullptr, B_ * NP_, D_, D_);
        size_t m = (size_t)B_ * NT_ * D_;
        assemble_k<<<(unsigned)((m + 255) / 256), 256>>>(ptmp, cls_token, pos_embed, x0, xq);
    }

    // ---- fork: prompted layers 0,1 (idx-independent) run on s2 concurrently ----
    cudaEventRecord(evF, s0);
    cudaStreamWaitEvent(s2, evF, 0);
    for (int l = 0; l < 2; ++l) {
        const int plen = 5, nkl = NT_ + plen, Mk = B_ * nkl;
        ln_k<<<M1, 256, 0, s2>>>(x0, ln1_s + (size_t)l * D_, ln1_b + (size_t)l * D_, h2_hi, h2_lo, D_);
        {
            size_t n = (size_t)Mk * D_;
            concat_k<<<(unsigned)((n + 255) / 256), 256, 0, s2>>>(
                h2_hi, h2_lo, g_prompts, e_prompts, idx,
                xk_hi, xk_lo, xv_hi, xv_lo, nkl, plen, l, 0);
        }
        const size_t wo = (size_t)l * 3 * D_ * D_;
        const float* bl = qkv_b + (size_t)l * 3 * D_;
        launch_gemm2(s2, EPI_F32, h2_hi, h2_lo, wqkv + wo, bl, q2, nullptr, nullptr, M1, D_, D_);
        launch_gemm2(s2, EPI_F32, xk_hi, xk_lo, wqkv + wo + (size_t)D_ * D_,
                     bl + D_, k2, nullptr, nullptr, Mk, D_, D_);
        launch_gemm2(s2, EPI_F32, xv_hi, xv_lo, wqkv + wo + (size_t)2 * D_ * D_,
                     bl + 2 * D_, v2, nullptr, nullptr, Mk, D_, D_);
        attn_k<<<dim3(H_, B_), 256, ATT_SMEM, s2>>>(
            q2, (long long)NT_ * D_, D_,
            k2, (long long)nkl * D_, D_,
            v2, (long long)nkl * D_, D_,
            at2_hi, at2_lo, nkl);
        launch_gemm2(s2, EPI_RES, at2_hi, at2_lo, wproj + (size_t)l * D_ * D_,
                     proj_b + (size_t)l * D_, x0, nullptr, nullptr, M1, D_, D_);
        ln_k<<<M1, 256, 0, s2>>>(x0, ln2_s + (size_t)l * D_, ln2_b + (size_t)l * D_, h2_hi, h2_lo, D_);
        launch_gemm2(s2, EPI_GELU, h2_hi, h2_lo, wfc1 + (size_t)l * FF_ * D_,
                     fc1_b + (size_t)l * FF_, nullptr, ff2_hi, ff2_lo, M1, FF_, D_);
        launch_gemm2(s2, EPI_RES, ff2_hi, ff2_lo, wfc2 + (size_t)l * D_ * FF_,
                     fc2_b + (size_t)l * D_, x0, nullptr, nullptr, M1, D_, FF_);
    }
    cudaEventRecord(evJ, s2);

    // ---- query pass on s0 (concurrent with s2) ----
    auto fast_block = [&](int l) {
        ln_k<<<M1, 256, 0, s0>>>(xq, ln1_s + (size_t)l * D_, ln1_b + (size_t)l * D_, h_hi, nullptr, D_);
        launch_gemm1(s0, EPI_F32, h_hi, wqkv + (size_t)l * 3 * D_ * D_,
                     qkv_b + (size_t)l * 3 * D_, qkvf, nullptr, M1, 3 * D_, D_);
        attn_q_k<<<dim3(H_, B_), 256, ATTQ_SMEM, s0>>>(
            qkvf,            (long long)NT_ * 3 * D_, 3 * D_,
            qkvf + D_,       (long long)NT_ * 3 * D_, 3 * D_,
            qkvf + 2 * D_,   (long long)NT_ * 3 * D_, 3 * D_,
            at_hi, NT_);
        launch_gemm1(s0, EPI_RES, at_hi, wproj + (size_t)l * D_ * D_,
                     proj_b + (size_t)l * D_, xq, nullptr, M1, D_, D_);
        ln_k<<<M1, 256, 0, s0>>>(xq, ln2_s + (size_t)l * D_, ln2_b + (size_t)l * D_, h_hi, nullptr, D_);
        launch_gemm1(s0, EPI_GELU, h_hi, wfc1 + (size_t)l * FF_ * D_,
                     fc1_b + (size_t)l * FF_, nullptr, ff_hi, M1, FF_, D_);
        launch_gemm1(s0, EPI_RES, ff_hi, wfc2 + (size_t)l * D_ * FF_,
                     fc2_b + (size_t)l * D_, xq, nullptr, M1, D_, FF_);
    };
    for (int l = 0; l < L_ - 1; ++l) fast_block(l);
    {
        const int l = L_ - 1;
        const long long LDX = (long long)NT_ * D_;
        ln_k<<<M1, 256, 0, s0>>>(xq, ln1_s + (size_t)l * D_, ln1_b + (size_t)l * D_, h_hi, nullptr, D_);
        launch_gemm1(s0, EPI_F32, h_hi, wqkv + (size_t)l * 3 * D_ * D_ + (size_t)D_ * D_,
                     qkv_b + (size_t)l * 3 * D_ + D_, qkvf, nullptr, M1, 2 * D_, D_);
        launch_gemm1(s0, EPI_F32, h_hi, wqkv + (size_t)l * 3 * D_ * D_,
                     qkv_b + (size_t)l * 3 * D_, qf, nullptr, B_, D_, D_, LDX, D_);
        attn_cls_k<<<dim3(H_, B_), 256, ATT_SMEM, s0>>>(qf, qkvf, at_hi);
        launch_gemm1(s0, EPI_RES, at_hi, wproj + (size_t)l * D_ * D_,
                     proj_b + (size_t)l * D_, xq, nullptr, B_, D_, D_, D_, LDX);
        ln_k<<<B_, 256, 0, s0>>>(xq, ln2_s + (size_t)l * D_, ln2_b + (size_t)l * D_, h_hi, nullptr, LDX);
        launch_gemm1(s0, EPI_GELU, h_hi, wfc1 + (size_t)l * FF_ * D_,
                     fc1_b + (size_t)l * FF_, nullptr, ff_hi, B_, FF_, D_);
        launch_gemm1(s0, EPI_RES, ff_hi, wfc2 + (size_t)l * D_ * FF_,
                     fc2_b + (size_t)l * D_, xq, nullptr, B_, D_, FF_, FF_, LDX);
    }
    select_k<<<B_, 256, 0, s0>>>(xq, key_emb, idx);

    // ---- join: s0 waits for prompted layers 0,1 ----
    cudaStreamWaitEvent(s0, evJ, 0);

    // ---- serial prompted pass, layers 2..11 on s0 ----
    auto std_block = [&](int l) {
        ln_k<<<M1, 256, 0, s0>>>(x0, ln1_s + (size_t)l * D_, ln1_b + (size_t)l * D_, h_hi, h_lo, D_);
        launch_gemm2(s0, EPI_F32, h_hi, h_lo, wqkv + (size_t)l * 3 * D_ * D_,
                     qkv_b + (size_t)l * 3 * D_, qkvf, nullptr, nullptr, M1, 3 * D_, D_);
        attn_k<<<dim3(H_, B_), 256, ATT_SMEM, s0>>>(
            qkvf,            (long long)NT_ * 3 * D_, 3 * D_,
            qkvf + D_,       (long long)NT_ * 3 * D_, 3 * D_,
            qkvf + 2 * D_,   (long long)NT_ * 3 * D_, 3 * D_,
            at_hi, at_lo, NT_);
        launch_gemm2(s0, EPI_RES, at_hi, at_lo, wproj + (size_t)l * D_ * D_,
                     proj_b + (size_t)l * D_, x0, nullptr, nullptr, M1, D_, D_);
        ln_k<<<M1, 256, 0, s0>>>(x0, ln2_s + (size_t)l * D_, ln2_b + (size_t)l * D_, h_hi, h_lo, D_);
        launch_gemm2(s0, EPI_GELU, h_hi, h_lo, wfc1 + (size_t)l * FF_ * D_,
                     fc1_b + (size_t)l * FF_, nullptr, ff_hi, ff_lo, M1, FF_, D_);
        launch_gemm2(s0, EPI_RES, ff_hi, ff_lo, wfc2 + (size_t)l * D_ * FF_,
                     fc2_b + (size_t)l * D_, x0, nullptr, nullptr, M1, D_, FF_);
    };
    for (int l = 2; l < L_; ++l) {
        const bool isEL = (l >= 2 && l < 5);
        if (!isEL) { std_block(l); continue; }
        const int plen = 20, pi = l - 2;
        const int nkl = NT_ + plen, Mk = B_ * nkl;

        ln_k<<<M1, 256, 0, s0>>>(x0, ln1_s + (size_t)l * D_, ln1_b + (size_t)l * D_, h_hi, h_lo, D_);
        {
            size_t n = (size_t)Mk * D_;
            concat_k<<<(unsigned)((n + 255) / 256), 256, 0, s0>>>(
                h_hi, h_lo, g_prompts, e_prompts, idx,
                xk_hi, xk_lo, xv_hi, xv_lo, nkl, plen, pi, 1);
        }
        const size_t wo = (size_t)l * 3 * D_ * D_;
        const float* bl = qkv_b + (size_t)l * 3 * D_;
        launch_gemm2(s0, EPI_F32, h_hi, h_lo, wqkv + wo, bl, qf, nullptr, nullptr, M1, D_, D_);
        launch_gemm2(s0, EPI_F32, xk_hi, xk_lo, wqkv + wo + (size_t)D_ * D_,
                     bl + D_, kf, nullptr, nullptr, Mk, D_, D_);
        launch_gemm2(s0, EPI_F32, xv_hi, xv_lo, wqkv + wo + (size_t)2 * D_ * D_,
                     bl + 2 * D_, vf, nullptr, nullptr, Mk, D_, D_);
        attn_k<<<dim3(H_, B_), 256, ATT_SMEM, s0>>>(
            qf, (long long)NT_ * D_, D_,
            kf, (long long)nkl * D_, D_,
            vf, (long long)nkl * D_, D_,
            at_hi, at_lo, nkl);
        launch_gemm2(s0, EPI_RES, at_hi, at_lo, wproj + (size_t)l * D_ * D_,
                     proj_b + (size_t)l * D_, x0, nullptr, nullptr, M1, D_, D_);
        ln_k<<<M1, 256, 0, s0>>>(x0, ln2_s + (size_t)l * D_, ln2_b + (size_t)l * D_, h_hi, h_lo, D_);
        launch_gemm2(s0, EPI_GELU, h_hi, h_lo, wfc1 + (size_t)l * FF_ * D_,
                     fc1_b + (size_t)l * FF_, nullptr, ff_hi, ff_lo, M1, FF_, D_);
        launch_gemm2(s0, EPI_RES, ff_hi, ff_lo, wfc2 + (size_t)l * D_ * FF_,
                     fc2_b + (size_t)l * D_, x0, nullptr, nullptr, M1, D_, FF_);
    }

    // 3) head
    head_k<<<B_, 256, 0, s0>>>(x0, norm_s, norm_b, head_w, head_b, mask_param, idx, out);
}

// round 17
// speedup vs baseline: 2.0903x; 1.2291x over previous
#include <cuda_runtime.h>
#include <cuda_fp16.h>
#include <cstdint>
#include <cstddef>

#define DI __device__ __forceinline__

// ---------------- problem dims ----------------
constexpr int L_ = 12, D_ = 768, H_ = 12, FF_ = 3072;
constexpr int B_ = 64, NP_ = 196, NT_ = 197, NC_ = 100, T_ = 10;
constexpr int M1 = B_ * NT_;        // 12608 token rows
constexpr int NKMAX = 217;          // 197 + 20 (e-prompt layers)
constexpr int MKMAX = B_ * NKMAX;   // 13888
constexpr int KSTR = 228;           // fp32 K smem row stride
constexpr int VSTR = 226;           // fp16 V smem row stride (odd word stride -> conflict-free)
constexpr int PPAD = 224;           // padded key count (mult of 32)
constexpr int KHQ = 68;             // query-pass fp16 K/V row stride (halves)

// ---------------- device scratch (static, no runtime alloc) ----------------
__device__ float g_xq  [(size_t)M1 * D_];       // query-pass stream
__device__ float g_x0  [(size_t)M1 * D_];       // prompted-pass stream
__device__ float g_ptmp[(size_t)B_ * NP_ * D_];
__device__ float g_qkvf[(size_t)M1 * 3 * D_];
__device__ float g_qf  [(size_t)M1 * D_];
__device__ float g_kf  [(size_t)MKMAX * D_];
__device__ float g_vf  [(size_t)MKMAX * D_];
__device__ int   g_idx [B_];
// fp16 activation buffers
__device__ __half g_h_hi [(size_t)M1 * D_];
__device__ __half g_h_lo [(size_t)M1 * D_];
__device__ __half g_at_hi[(size_t)M1 * D_];
__device__ __half g_ff_hi[(size_t)M1 * FF_];
__device__ __half g_xk_hi[(size_t)MKMAX * D_];
__device__ __half g_xk_lo[(size_t)MKMAX * D_];
__device__ __half g_xv_hi[(size_t)MKMAX * D_];
__device__ __half g_xv_lo[(size_t)MKMAX * D_];
__device__ __half g_p_hi [(size_t)B_ * NP_ * D_];
__device__ __half g_p_lo [(size_t)B_ * NP_ * D_];
// dedicated buffers for overlapped prompted layers 0-1
__device__ float  g_q2  [(size_t)M1 * D_];
__device__ float  g_k2  [(size_t)MKMAX * D_];
__device__ float  g_v2  [(size_t)MKMAX * D_];
__device__ __half g_h2_hi [(size_t)M1 * D_];
__device__ __half g_h2_lo [(size_t)M1 * D_];
__device__ __half g_at2_hi[(size_t)M1 * D_];
__device__ __half g_ff2_hi[(size_t)M1 * FF_];
// fp16 weights (hi only — B-side operands)
__device__ __half g_wpatch[(size_t)D_ * D_];
__device__ __half g_wqkv  [(size_t)L_ * 3 * D_ * D_];
__device__ __half g_wproj [(size_t)L_ * D_ * D_];
__device__ __half g_wfc1  [(size_t)L_ * FF_ * D_];
__device__ __half g_wfc2  [(size_t)L_ * D_ * FF_];

// ---------------- PTX helpers ----------------
DI uint32_t sptr(const void* p) { return (uint32_t)__cvta_generic_to_shared(p); }

DI void cp16(void* s, const void* g, bool pred) {
    asm volatile("cp.async.cg.shared.global [%0], [%1], 16, %2;\n"
                 :: "r"(sptr(s)), "l"(g), "r"(pred ? 16 : 0));
}
DI void cpcommit() { asm volatile("cp.async.commit_group;\n" ::); }
DI void cpwait0()  { asm volatile("cp.async.wait_group 0;\n" ::); }
DI void cpwait1()  { asm volatile("cp.async.wait_group 1;\n" ::); }

DI void ldm4(uint32_t* r, const void* p) {
    asm volatile("ldmatrix.sync.aligned.m8n8.x4.shared.b16 {%0,%1,%2,%3}, [%4];\n"
                 : "=r"(r[0]), "=r"(r[1]), "=r"(r[2]), "=r"(r[3])
                 : "r"(sptr(p)) : "memory");
}
DI void mma_f16(float* d, const uint32_t* a, const uint32_t* b) {
    asm volatile("mma.sync.aligned.m16n8k16.row.col.f32.f16.f16.f32 "
                 "{%0,%1,%2,%3}, {%4,%5,%6,%7}, {%8,%9}, {%0,%1,%2,%3};\n"
                 : "+f"(d[0]), "+f"(d[1]), "+f"(d[2]), "+f"(d[3])
                 : "r"(a[0]), "r"(a[1]), "r"(a[2]), "r"(a[3]),
                   "r"(b[0]), "r"(b[1]));
}
DI float gelu_f(float v) { return 0.5f * v * (1.f + erff(v * 0.70710678118654752f)); }
DI void split_h(float v, __half& hi, __half& lo) {
    hi = __float2half_rn(v);
    lo = __float2half_rn(v - __half2float(hi));
}

constexpr int EPI_F32 = 0, EPI_GELU = 1, EPI_RES = 2;
constexpr int AS = 40;
constexpr int TILE_ELE = 128 * AS;            // 5120 halves / tile
constexpr int SMEM2 = 3 * 3 * TILE_ELE * 2;   // 92160 B
constexpr int SMEM1 = 3 * 2 * TILE_ELE * 2;   // 61440 B

// ============ fp16 split TN GEMM: C[M,N] = A[M,K] * B[N,K]^T ============
// NPROD=2: A = Ah + Al (fp16 pair, exact), B = Bh (fp16)
// NPROD=1: C = Ah*Bh
template<int NPROD, int EPI>
__global__ __launch_bounds__(256, 2) void gemm_k(
    const __half* __restrict__ Ahi, const __half* __restrict__ Alo,
    const __half* __restrict__ Bw,
    const float* __restrict__ bias, float* __restrict__ Cf,
    __half* __restrict__ Cb_hi, __half* __restrict__ Cb_lo,
    int M, int N, int K, long long lda, long long ldc)
{
    constexpr int NT = (NPROD == 2) ? 3 : 2;
    extern __shared__ __half smem[];

    const int tid = threadIdx.x;
    const int m0 = blockIdx.y * 128, n0 = blockIdx.x * 128;
    const int wid = tid >> 5, lane = tid & 31;
    const int wm = wid >> 2, wn = wid & 3;

    float acc[4][4][4];
    #pragma unroll
    for (int a = 0; a < 4; a++)
        #pragma unroll
        for (int b = 0; b < 4; b++)
            #pragma unroll
            for (int c = 0; c < 4; c++) acc[a][b][c] = 0.f;

    const int nIt = K >> 5;

    auto load_stage = [&](int st, int k0) {
        __half* base = smem + st * NT * TILE_ELE;
        #pragma unroll
        for (int i = 0; i < 2; i++) {
            int idx = tid + i * 256;
            int r = idx >> 2, c = (idx & 3) << 3;
            int gr = m0 + r;
            bool p = gr < M;
            size_t aoff = (size_t)(p ? gr : 0) * lda + k0 + c;
            size_t boff = (size_t)(n0 + r) * K + k0 + c;
            cp16(base + r * AS + c, Ahi + aoff, p);
            if (NPROD == 2) cp16(base + TILE_ELE + r * AS + c, Alo + aoff, p);
            cp16(base + (NPROD == 2 ? 2 : 1) * TILE_ELE + r * AS + c, Bw + boff, true);
        }
        cpcommit();
    };

    load_stage(0, 0);
    load_stage(1, 32);
    cpwait1();
    __syncthreads();

    for (int it = 0; it < nIt; ++it) {
        const bool pre = (it + 2 < nIt);
        int stn = it + 2;
        if (pre) load_stage(stn - 3 * (stn / 3), stn << 5);
        const int buf = it - 3 * (it / 3);
        __half* sb = smem + buf * NT * TILE_ELE;
        __half* sAh = sb;
        __half* sAl = sb + TILE_ELE;
        __half* sBh = sb + (NPROD == 2 ? 2 : 1) * TILE_ELE;
        #pragma unroll
        for (int kk = 0; kk < 2; ++kk) {
            const int kcol = kk << 4;
            uint32_t bh[4][2], af[4][4];
            #pragma unroll
            for (int j = 0; j < 2; ++j) {
                int row = wn * 32 + j * 16 + (lane & 7) + ((lane >> 4) << 3);
                int col = kcol + (((lane >> 3) & 1) << 3);
                uint32_t t[4];
                ldm4(t, &sBh[row * AS + col]);
                bh[2 * j][0] = t[0]; bh[2 * j][1] = t[1];
                bh[2 * j + 1][0] = t[2]; bh[2 * j + 1][1] = t[3];
            }
            #pragma unroll
            for (int mt = 0; mt < 4; ++mt) {
                int row = wm * 64 + mt * 16 + (lane & 15);
                int col = kcol + ((lane >> 4) << 3);
                ldm4(af[mt], &sAh[row * AS + col]);
            }
            #pragma unroll
            for (int mt = 0; mt < 4; ++mt)
                #pragma unroll
                for (int nt = 0; nt < 4; ++nt)
                    mma_f16(acc[mt][nt], af[mt], bh[nt]);
            if (NPROD == 2) {
                #pragma unroll
                for (int mt = 0; mt < 4; ++mt) {
                    int row = wm * 64 + mt * 16 + (lane & 15);
                    int col = kcol + ((lane >> 4) << 3);
                    ldm4(af[mt], &sAl[row * AS + col]);
                }
                #pragma unroll
                for (int mt = 0; mt < 4; ++mt)
                    #pragma unroll
                    for (int nt = 0; nt < 4; ++nt)
                        mma_f16(acc[mt][nt], af[mt], bh[nt]);
            }
        }
        if (pre) cpwait1(); else cpwait0();
        __syncthreads();
    }

    const int g = lane >> 2, tg = lane & 3;
    #pragma unroll
    for (int mt = 0; mt < 4; ++mt) {
        #pragma unroll
        for (int nt = 0; nt < 4; ++nt) {
            const int col = n0 + wn * 32 + nt * 8 + tg * 2;
            #pragma unroll
            for (int hh = 0; hh < 2; ++hh) {
                const int r = m0 + wm * 64 + mt * 16 + g + hh * 8;
                if (r < M) {
                    float v0 = acc[mt][nt][2 * hh + 0] + bias[col];
                    float v1 = acc[mt][nt][2 * hh + 1] + bias[col + 1];
                    size_t off = (size_t)r * ldc + col;
                    if (EPI == EPI_F32) {
                        float2 o; o.x = v0; o.y = v1;
                        *reinterpret_cast<float2*>(Cf + off) = o;
                    } else if (EPI == EPI_GELU) {
                        float g0 = gelu_f(v0), g1 = gelu_f(v1);
                        __half2 oh = __floats2half2_rn(g0, g1);
                        *reinterpret_cast<__half2*>(Cb_hi + off) = oh;
                        if (NPROD == 2 && Cb_lo) {
                            __half h0, l0, h1, l1;
                            split_h(g0, h0, l0); split_h(g1, h1, l1);
                            __half2 ol; ol.x = l0; ol.y = l1;
                            *reinterpret_cast<__half2*>(Cb_lo + off) = ol;
                        }
                    } else {
                        float2 o = *reinterpret_cast<float2*>(Cf + off);
                        o.x += v0; o.y += v1;
                        *reinterpret_cast<float2*>(Cf + off) = o;
                    }
                }
            }
        }
    }
}

// ---------------- prompted-pass attention (K fp32, V fp16, 2 CTAs/SM) ----------------
constexpr int ATT_SMEM = 64 * KSTR * 4 + 64 * VSTR * 2 + 8 * PPAD * 4;   // 94464 B
__global__ __launch_bounds__(256, 2) void attn_k(
    const float* __restrict__ qp, long long qbs, int qrs,
    const float* __restrict__ kp, long long kbs, int krs,
    const float* __restrict__ vp, long long vbs, int vrs,
    __half* __restrict__ out_hi, int nk)
{
    extern __shared__ char smema[];
    float*  Ks = (float*)smema;                          // [64][KSTR]
    __half* Vs = (__half*)(smema + 64 * KSTR * 4);       // [64][VSTR]
    float*  Ps = (float*)(smema + 64 * KSTR * 4 + 64 * VSTR * 2);   // [8][PPAD]
    const int h = blockIdx.x, b = blockIdx.y;
    const int tid = threadIdx.x, lane = tid & 31, w = tid >> 5;

    const float* kb = kp + (long long)b * kbs + h * 64;
    const float* vb = vp + (long long)b * vbs + h * 64;
    for (int i = tid; i < 64 * PPAD; i += 256) {
        int j = i >> 6, d = i & 63;
        float kvv = 0.f, vvv = 0.f;
        if (j < nk) {
            kvv = kb[(long long)j * krs + d];
            vvv = vb[(long long)j * vrs + d];
        }
        Ks[d * KSTR + j] = kvv;
        Vs[d * VSTR + j] = __float2half_rn(vvv);
    }
    __syncthreads();

    const int cnt = (nk - lane + 31) >> 5;
    const int nk2q = (nk + 1) >> 1;
    float* pw = Ps + w * PPAD;
    const float2* pw2 = (const float2*)pw;
    const __half2* v0p = (const __half2*)(Vs + lane * VSTR);
    const __half2* v1p = (const __half2*)(Vs + (lane + 32) * VSTR);

    for (int qi = w; qi < NT_; qi += 8) {
        const float* qrow = qp + (long long)b * qbs + (long long)qi * qrs + h * 64;
        const float4* q4 = (const float4*)qrow;
        float qv[64];
        #pragma unroll
        for (int t = 0; t < 16; ++t) {
            float4 v = q4[t];
            qv[4 * t] = v.x; qv[4 * t + 1] = v.y; qv[4 * t + 2] = v.z; qv[4 * t + 3] = v.w;
        }

        float s[7];
        #pragma unroll
        for (int jj = 0; jj < 7; ++jj) s[jj] = 0.f;
        #pragma unroll
        for (int d = 0; d < 64; ++d) {
            const float qd = qv[d];
            #pragma unroll
            for (int jj = 0; jj < 7; ++jj)
                if (jj < cnt) s[jj] += qd * Ks[d * KSTR + lane + jj * 32];
        }
        float m = -1e30f;
        #pragma unroll
        for (int jj = 0; jj < 7; ++jj)
            if (jj < cnt) { s[jj] *= 0.125f; m = fmaxf(m, s[jj]); }
        #pragma unroll
        for (int o = 16; o; o >>= 1) m = fmaxf(m, __shfl_xor_sync(0xffffffffu, m, o));
        float sum = 0.f;
        #pragma unroll
        for (int jj = 0; jj < 7; ++jj) {
            s[jj] = (jj < cnt) ? __expf(s[jj] - m) : 0.f;
            sum += s[jj];
        }
        #pragma unroll
        for (int o = 16; o; o >>= 1) sum += __shfl_xor_sync(0xffffffffu, sum, o);
        const float inv = 1.f / sum;

        #pragma unroll
        for (int jj = 0; jj < 7; ++jj)
            pw[lane + jj * 32] = s[jj] * inv;
        __syncwarp();

        float o0 = 0.f, o1 = 0.f;
        for (int j2 = 0; j2 < nk2q; ++j2) {
            float2 pp = pw2[j2];
            float2 a = __half22float2(v0p[j2]);
            float2 c = __half22float2(v1p[j2]);
            o0 += pp.x * a.x + pp.y * a.y;
            o1 += pp.x * c.x + pp.y * c.y;
        }
        __syncwarp();

        size_t base = ((size_t)(b * NT_ + qi)) * D_ + h * 64;
        out_hi[base + lane]      = __float2half_rn(o0);
        out_hi[base + lane + 32] = __float2half_rn(o1);
    }
}

// ---------------- query-pass attention (fp16 K/V smem, 3 CTAs/SM) ----------------
constexpr int ATTQ_SMEM = 2 * (PPAD * KHQ * 2) + 8 * PPAD * 4;   // 68096 B
__global__ __launch_bounds__(256, 3) void attn_q_k(
    const float* __restrict__ qp, long long qbs, int qrs,
    const float* __restrict__ kp, long long kbs, int krs,
    const float* __restrict__ vp, long long vbs, int vrs,
    __half* __restrict__ out_hi, int nk)
{
    extern __shared__ char smemq[];
    __half* Ks = (__half*)smemq;                       // [PPAD][KHQ]
    __half* Vs = Ks + PPAD * KHQ;                      // [PPAD][KHQ]
    float*  Ps = (float*)(Vs + PPAD * KHQ);            // [8][PPAD]
    const int h = blockIdx.x, b = blockIdx.y;
    const int tid = threadIdx.x, lane = tid & 31, w = tid >> 5;

    const float* kb = kp + (long long)b * kbs + h * 64;
    const float* vb = vp + (long long)b * vbs + h * 64;
    for (int i = tid; i < PPAD * 64; i += 256) {
        int j = i >> 6, d = i & 63;
        float kvv = 0.f, vvv = 0.f;
        if (j < nk) {
            kvv = kb[(long long)j * krs + d];
            vvv = vb[(long long)j * vrs + d];
        }
        Ks[j * KHQ + d] = __float2half_rn(kvv);
        Vs[j * KHQ + d] = __float2half_rn(vvv);
    }
    __syncthreads();

    const int cnt = (nk - lane + 31) >> 5;
    float* pw = Ps + w * PPAD;

    for (int qi = w; qi < NT_; qi += 8) {
        const float4* q4 = (const float4*)(qp + (long long)b * qbs + (long long)qi * qrs + h * 64);

        float s[7];
        #pragma unroll
        for (int jj = 0; jj < 7; ++jj) s[jj] = 0.f;
        #pragma unroll
        for (int jj = 0; jj < 7; ++jj) {
            if (jj < cnt) {
                const __half2* k2 = (const __half2*)(Ks + (lane + jj * 32) * KHQ);
                float acc = 0.f;
                #pragma unroll
                for (int t = 0; t < 16; ++t) {
                    float4 qv = __ldg(q4 + t);
                    float2 a = __half22float2(k2[2 * t]);
                    float2 c = __half22float2(k2[2 * t + 1]);
                    acc += qv.x * a.x + qv.y * a.y + qv.z * c.x + qv.w * c.y;
                }
                s[jj] = acc;
            }
        }
        float m = -1e30f;
        #pragma unroll
        for (int jj = 0; jj < 7; ++jj)
            if (jj < cnt) { s[jj] *= 0.125f; m = fmaxf(m, s[jj]); }
        #pragma unroll
        for (int o = 16; o; o >>= 1) m = fmaxf(m, __shfl_xor_sync(0xffffffffu, m, o));
        float sum = 0.f;
        #pragma unroll
        for (int jj = 0; jj < 7; ++jj) {
            s[jj] = (jj < cnt) ? __expf(s[jj] - m) : 0.f;
            sum += s[jj];
        }
        #pragma unroll
        for (int o = 16; o; o >>= 1) sum += __shfl_xor_sync(0xffffffffu, sum, o);
        const float inv = 1.f / sum;
        #pragma unroll
        for (int jj = 0; jj < 7; ++jj)
            pw[lane + jj * 32] = s[jj] * inv;
        __syncwarp();

        float o0 = 0.f, o1 = 0.f;
        for (int j = 0; j < nk; ++j) {
            float pp = pw[j];
            o0 += pp * __half2float(Vs[j * KHQ + lane]);
            o1 += pp * __half2float(Vs[j * KHQ + lane + 32]);
        }
        __syncwarp();

        size_t base = ((size_t)(b * NT_ + qi)) * D_ + h * 64;
        out_hi[base + lane]      = __float2half_rn(o0);
        out_hi[base + lane + 32] = __float2half_rn(o1);
    }
}

// ---------------- CLS-only attention (query pass tail layer, fp32) ----------------
constexpr int ATTC_SMEM = (128 * KSTR + 8 * PPAD) * 4;   // 123904 B
__global__ __launch_bounds__(256) void attn_cls_k(
    const float* __restrict__ qcls, const float* __restrict__ kvf,
    __half* __restrict__ out)
{
    extern __shared__ float skvf[];
    float* Ks = skvf;
    float* Vs = skvf + 64 * KSTR;
    float* Ps = skvf + 128 * KSTR;
    const int h = blockIdx.x, b = blockIdx.y;
    const int tid = threadIdx.x;

    const float* kb = kvf + (size_t)b * NT_ * 1536 + h * 64;
    const float* vb = kb + 768;
    for (int i = tid; i < 64 * PPAD; i += 256) {
        int j = i >> 6, d = i & 63;
        float kvv = 0.f, vvv = 0.f;
        if (j < NT_) {
            kvv = kb[(size_t)j * 1536 + d];
            vvv = vb[(size_t)j * 1536 + d];
        }
        Ks[d * KSTR + j] = kvv;
        Vs[d * KSTR + j] = vvv;
    }
    __syncthreads();
    if (tid >= 32) return;
    const int lane = tid;
    const int cnt = (NT_ - lane + 31) >> 5;
    const float* qrow = qcls + (size_t)b * D_ + h * 64;
    float qv[64];
    #pragma unroll
    for (int d = 0; d < 64; ++d) qv[d] = qrow[d];

    float s[7];
    #pragma unroll
    for (int jj = 0; jj < 7; ++jj) s[jj] = 0.f;
    #pragma unroll
    for (int d = 0; d < 64; ++d) {
        const float qd = qv[d];
        #pragma unroll
        for (int jj = 0; jj < 7; ++jj)
            if (jj < cnt) s[jj] += qd * Ks[d * KSTR + lane + jj * 32];
    }
    float m = -1e30f;
    #pragma unroll
    for (int jj = 0; jj < 7; ++jj)
        if (jj < cnt) { s[jj] *= 0.125f; m = fmaxf(m, s[jj]); }
    #pragma unroll
    for (int o = 16; o; o >>= 1) m = fmaxf(m, __shfl_xor_sync(0xffffffffu, m, o));
    float sum = 0.f;
    #pragma unroll
    for (int jj = 0; jj < 7; ++jj) {
        s[jj] = (jj < cnt) ? __expf(s[jj] - m) : 0.f;
        sum += s[jj];
    }
    #pragma unroll
    for (int o = 16; o; o >>= 1) sum += __shfl_xor_sync(0xffffffffu, sum, o);
    const float inv = 1.f / sum;
    #pragma unroll
    for (int jj = 0; jj < 7; ++jj)
        Ps[lane + jj * 32] = s[jj] * inv;
    __syncwarp();

    const float4* pw4 = (const float4*)Ps;
    const float4* v0p = (const float4*)(Vs + lane * KSTR);
    const float4* v1p = (const float4*)(Vs + (lane + 32) * KSTR);
    const int nk4q = (NT_ + 3) >> 2;
    float o0 = 0.f, o1 = 0.f;
    for (int j4 = 0; j4 < nk4q; ++j4) {
        float4 pp = pw4[j4];
        float4 a = v0p[j4];
        float4 c = v1p[j4];
        o0 += pp.x * a.x + pp.y * a.y + pp.z * a.z + pp.w * a.w;
        o1 += pp.x * c.x + pp.y * c.y + pp.z * c.z + pp.w * c.w;
    }
    out[(size_t)b * D_ + h * 64 + lane]      = __float2half_rn(o0);
    out[(size_t)b * D_ + h * 64 + lane + 32] = __float2half_rn(o1);
}

// ---------------- layernorm (block per row) -> fp16 hi(/lo) ----------------
__global__ __launch_bounds__(256) void ln_k(const float* __restrict__ x,
    const float* __restrict__ s, const float* __restrict__ b,
    __half* __restrict__ out_hi, __half* __restrict__ out_lo, long long ldx)
{
    const int row = blockIdx.x, tid = threadIdx.x;
    const float* xr = x + (size_t)row * ldx;
    float v[3], sum = 0.f, sq = 0.f;
    #pragma unroll
    for (int i = 0; i < 3; i++) { v[i] = xr[tid + i * 256]; sum += v[i]; sq += v[i] * v[i]; }
    __shared__ float rs[8], rq[8];
    #pragma unroll
    for (int o = 16; o; o >>= 1) {
        sum += __shfl_xor_sync(0xffffffffu, sum, o);
        sq  += __shfl_xor_sync(0xffffffffu, sq, o);
    }
    if ((tid & 31) == 0) { rs[tid >> 5] = sum; rq[tid >> 5] = sq; }
    __syncthreads();
    sum = 0.f; sq = 0.f;
    #pragma unroll
    for (int i = 0; i < 8; i++) { sum += rs[i]; sq += rq[i]; }
    const float mu = sum * (1.f / D_);
    const float var = sq * (1.f / D_) - mu * mu;
    const float rstd = rsqrtf(var + 1e-6f);
    #pragma unroll
    for (int i = 0; i < 3; i++) {
        int c = tid + i * 256;
        float y = (v[i] - mu) * rstd * s[c] + b[c];
        __half h, l;
        split_h(y, h, l);
        out_hi[(size_t)row * D_ + c] = h;
        if (out_lo) out_lo[(size_t)row * D_ + c] = l;
    }
}

// ---------------- small utility kernels ----------------
__global__ void conv_h4_k(const float4* __restrict__ in, __half2* __restrict__ o, size_t n4) {
    size_t i = (size_t)blockIdx.x * 256 + threadIdx.x;
    if (i < n4) {
        float4 v = in[i];
        o[2 * i]     = __floats2half2_rn(v.x, v.y);
        o[2 * i + 1] = __floats2half2_rn(v.z, v.w);
    }
}
__global__ void prep_k(const float* __restrict__ in, const float* __restrict__ pw,
                       __half* __restrict__ p_hi, __half* __restrict__ p_lo,
                       __half* __restrict__ w_hi) {
    size_t i = (size_t)blockIdx.x * 256 + threadIdx.x;
    const size_t NPT = (size_t)B_ * NP_ * D_;
    if (i < NPT) {
        int d = (int)(i % D_), r = (int)((i / D_) % NP_), b = (int)(i / ((size_t)D_ * NP_));
        int hp = r / 14, wp = r % 14;
        int c = d >> 8, ph = (d >> 4) & 15, pwc = d & 15;
        float v = in[(((size_t)b * 3 + c) * 224 + hp * 16 + ph) * 224 + wp * 16 + pwc];
        __half h, l;
        split_h(v, h, l);
        p_hi[i] = h; p_lo[i] = l;
    } else if (i < NPT + (size_t)D_ * D_) {
        size_t j = i - NPT;
        w_hi[j] = __float2half_rn(pw[j]);
    }
}
__global__ void assemble_k(const float* __restrict__ ptmp, const float* __restrict__ cls,
                           const float* __restrict__ pos, float* __restrict__ x0,
                           float* __restrict__ xq) {
    size_t i = (size_t)blockIdx.x * 256 + threadIdx.x;
    if (i >= (size_t)B_ * NT_ * D_) return;
    int d = (int)(i % D_), j = (int)((i / D_) % NT_), b = (int)(i / ((size_t)D_ * NT_));
    float v = (j == 0 ? cls[d] : ptmp[((size_t)b * NP_ + j - 1) * D_ + d]) + pos[(size_t)j * D_ + d];
    x0[i] = v; xq[i] = v;
}
__global__ void concat_k(const __half* __restrict__ h_hi, const __half* __restrict__ h_lo,
                         const float* __restrict__ gp, const float* __restrict__ ep,
                         const int* __restrict__ idx,
                         __half* __restrict__ xk_hi, __half* __restrict__ xk_lo,
                         __half* __restrict__ xv_hi, __half* __restrict__ xv_lo,
                         int nkl, int plen, int pi, int isE)
{
    size_t i = (size_t)blockIdx.x * 256 + threadIdx.x;
    if (i >= (size_t)B_ * nkl * D_) return;
    int d = (int)(i % D_);
    int row = (int)(i / D_);
    int b = row / nkl, j = row % nkl;
    if (j < NT_) {
        size_t src = ((size_t)(b * NT_ + j)) * D_ + d;
        __half wh = h_hi[src], wl = h_lo[src];
        xk_hi[i] = wh; xk_lo[i] = wl;
        xv_hi[i] = wh; xv_lo[i] = wl;
    } else {
        int jj = j - NT_;
        const float* base = isE ? (ep + (size_t)idx[b] * 120 * D_) : gp;
        float vk = base[((size_t)(2 * pi) * plen + jj) * D_ + d];
        float vv = base[((size_t)(2 * pi + 1) * plen + jj) * D_ + d];
        __half h, l;
        split_h(vk, h, l); xk_hi[i] = h; xk_lo[i] = l;
        split_h(vv, h, l); xv_hi[i] = h; xv_lo[i] = l;
    }
}
__global__ __launch_bounds__(256) void select_k(const float* __restrict__ x,
    const float* __restrict__ key, int* __restrict__ idx)
{
    const int b = blockIdx.x, tid = threadIdx.x;
    const float* q = x + (size_t)b * NT_ * D_;
    float pq = 0.f, pd[T_], pk[T_];
    #pragma unroll
    for (int t = 0; t < T_; t++) { pd[t] = 0.f; pk[t] = 0.f; }
    for (int i = 0; i < 3; i++) {
        int d = tid + i * 256;
        float qd = q[d];
        pq += qd * qd;
        #pragma unroll
        for (int t = 0; t < T_; t++) {
            float kv = key[(size_t)t * D_ + d];
            pd[t] += qd * kv; pk[t] += kv * kv;
        }
    }
    __shared__ float red[256];
    __shared__ float tot[21];
    for (int a = 0; a < 21; a++) {
        float v = (a == 0) ? pq : (a <= 10 ? pd[a - 1] : pk[a - 11]);
        red[tid] = v; __syncthreads();
        for (int st = 128; st > 0; st >>= 1) {
            if (tid < st) red[tid] += red[tid + st];
            __syncthreads();
        }
        if (tid == 0) tot[a] = red[0];
        __syncthreads();
    }
    if (tid == 0) {
        float qn = sqrtf(tot[0]) + 1e-8f;
        float best = -2e30f; int bi = 0;
        for (int t = 0; t < T_; t++) {
            float cosv = tot[1 + t] / (qn * (sqrtf(tot[11 + t]) + 1e-8f));
            if (cosv > best) { best = cosv; bi = t; }
        }
        idx[b] = bi;
    }
}
__global__ __launch_bounds__(256) void head_k(const float* __restrict__ x,
    const float* __restrict__ ns, const float* __restrict__ nb,
    const float* __restrict__ hw, const float* __restrict__ hb,
    const float* __restrict__ mp, const int* __restrict__ idx,
    float* __restrict__ out)
{
    const int b = blockIdx.x, tid = threadIdx.x;
    __shared__ float feat[D_];
    __shared__ float rs[8], rq[8];
    const float* xr = x + (size_t)b * NT_ * D_;
    float v[3], sum = 0.f, sq = 0.f;
    #pragma unroll
    for (int i = 0; i < 3; i++) { v[i] = xr[tid + i * 256]; sum += v[i]; sq += v[i] * v[i]; }
    #pragma unroll
    for (int o = 16; o; o >>= 1) {
        sum += __shfl_xor_sync(0xffffffffu, sum, o);
        sq  += __shfl_xor_sync(0xffffffffu, sq, o);
    }
    if ((tid & 31) == 0) { rs[tid >> 5] = sum; rq[tid >> 5] = sq; }
    __syncthreads();
    sum = 0.f; sq = 0.f;
    #pragma unroll
    for (int i = 0; i < 8; i++) { sum += rs[i]; sq += rq[i]; }
    const float mu = sum * (1.f / D_);
    const float var = sq * (1.f / D_) - mu * mu;
    const float rstd = rsqrtf(var + 1e-6f);
    #pragma unroll
    for (int i = 0; i < 3; i++) {
        int c = tid + i * 256;
        feat[c] = (v[i] - mu) * rstd * ns[c] + nb[c];
    }
    __syncthreads();
    if (tid < NC_) {
        float a = hb[tid];
        const float* wr = hw + (size_t)tid * D_;
        for (int d = 0; d < D_; d++) a += feat[d] * wr[d];
        float m = mp[(size_t)idx[b] * NC_ + tid];
        out[b * NC_ + tid] = a * 2.f / (1.f + expf(-m));
    }
}

// ---------------- host side ----------------
static inline void launch_gemm2(cudaStream_t st, int epi,
                                const __half* Ahi, const __half* Alo, const __half* Bw,
                                const float* bias, float* Cf,
                                __half* Cb_hi, __half* Cb_lo,
                                int M, int N, int K,
                                long long lda = -1, long long ldc = -1)
{
    if (lda < 0) lda = K;
    if (ldc < 0) ldc = N;
    dim3 grid(N / 128, (M + 127) / 128);
    switch (epi) {
        case 0:  gemm_k<2, 0><<<grid, 256, SMEM2, st>>>(Ahi, Alo, Bw, bias, Cf, Cb_hi, Cb_lo, M, N, K, lda, ldc); break;
        case 1:  gemm_k<2, 1><<<grid, 256, SMEM2, st>>>(Ahi, Alo, Bw, bias, Cf, Cb_hi, Cb_lo, M, N, K, lda, ldc); break;
        default: gemm_k<2, 2><<<grid, 256, SMEM2, st>>>(Ahi, Alo, Bw, bias, Cf, Cb_hi, Cb_lo, M, N, K, lda, ldc); break;
    }
}
static inline void launch_gemm1(cudaStream_t st, int epi,
                                const __half* A, const __half* Bw,
                                const float* bias, float* Cf, __half* Cb_hi,
                                int M, int N, int K,
                                long long lda = -1, long long ldc = -1)
{
    if (lda < 0) lda = K;
    if (ldc < 0) ldc = N;
    dim3 grid(N / 128, (M + 127) / 128);
    switch (epi) {
        case 0:  gemm_k<1, 0><<<grid, 256, SMEM1, st>>>(A, nullptr, Bw, bias, Cf, Cb_hi, nullptr, M, N, K, lda, ldc); break;
        case 1:  gemm_k<1, 1><<<grid, 256, SMEM1, st>>>(A, nullptr, Bw, bias, Cf, Cb_hi, nullptr, M, N, K, lda, ldc); break;
        default: gemm_k<1, 2><<<grid, 256, SMEM1, st>>>(A, nullptr, Bw, bias, Cf, Cb_hi, nullptr, M, N, K, lda, ldc); break;
    }
}

extern "C" void kernel_launch(void* const* d_in, const int* in_sizes, int n_in,
                              void* d_out, int out_size)
{
    (void)in_sizes; (void)n_in; (void)out_size;
    const float* inputs     = (const float*)d_in[0];
    const float* patch_w    = (const float*)d_in[1];
    const float* patch_b    = (const float*)d_in[2];
    const float* cls_token  = (const float*)d_in[3];
    const float* pos_embed  = (const float*)d_in[4];
    const float* ln1_s      = (const float*)d_in[5];
    const float* ln1_b      = (const float*)d_in[6];
    const float* qkv_w      = (const float*)d_in[7];
    const float* qkv_b      = (const float*)d_in[8];
    const float* proj_w     = (const float*)d_in[9];
    const float* proj_b     = (const float*)d_in[10];
    const float* ln2_s      = (const float*)d_in[11];
    const float* ln2_b      = (const float*)d_in[12];
    const float* fc1_w      = (const float*)d_in[13];
    const float* fc1_b      = (const float*)d_in[14];
    const float* fc2_w      = (const float*)d_in[15];
    const float* fc2_b      = (const float*)d_in[16];
    const float* norm_s     = (const float*)d_in[17];
    const float* norm_b     = (const float*)d_in[18];
    const float* head_w     = (const float*)d_in[19];
    const float* head_b     = (const float*)d_in[20];
    const float* key_emb    = (const float*)d_in[21];
    const float* mask_param = (const float*)d_in[22];
    const float* g_prompts  = (const float*)d_in[23];
    const float* e_prompts  = (const float*)d_in[24];
    float* out = (float*)d_out;

    void* p;
    cudaGetSymbolAddress(&p, g_xq);     float* xq     = (float*)p;
    cudaGetSymbolAddress(&p, g_x0);     float* x0     = (float*)p;
    cudaGetSymbolAddress(&p, g_ptmp);   float* ptmp   = (float*)p;
    cudaGetSymbolAddress(&p, g_qkvf);   float* qkvf   = (float*)p;
    cudaGetSymbolAddress(&p, g_qf);     float* qf     = (float*)p;
    cudaGetSymbolAddress(&p, g_kf);     float* kf     = (float*)p;
    cudaGetSymbolAddress(&p, g_vf);     float* vf     = (float*)p;
    cudaGetSymbolAddress(&p, g_idx);    int*   idx    = (int*)p;
    cudaGetSymbolAddress(&p, g_h_hi);   __half* h_hi  = (__half*)p;
    cudaGetSymbolAddress(&p, g_h_lo);   __half* h_lo  = (__half*)p;
    cudaGetSymbolAddress(&p, g_at_hi);  __half* at_hi = (__half*)p;
    cudaGetSymbolAddress(&p, g_ff_hi);  __half* ff_hi = (__half*)p;
    cudaGetSymbolAddress(&p, g_xk_hi);  __half* xk_hi = (__half*)p;
    cudaGetSymbolAddress(&p, g_xk_lo);  __half* xk_lo = (__half*)p;
    cudaGetSymbolAddress(&p, g_xv_hi);  __half* xv_hi = (__half*)p;
    cudaGetSymbolAddress(&p, g_xv_lo);  __half* xv_lo = (__half*)p;
    cudaGetSymbolAddress(&p, g_p_hi);   __half* p_hi  = (__half*)p;
    cudaGetSymbolAddress(&p, g_p_lo);   __half* p_lo  = (__half*)p;
    cudaGetSymbolAddress(&p, g_q2);     float* q2     = (float*)p;
    cudaGetSymbolAddress(&p, g_k2);     float* k2     = (float*)p;
    cudaGetSymbolAddress(&p, g_v2);     float* v2     = (float*)p;
    cudaGetSymbolAddress(&p, g_h2_hi);  __half* h2_hi = (__half*)p;
    cudaGetSymbolAddress(&p, g_h2_lo);  __half* h2_lo = (__half*)p;
    cudaGetSymbolAddress(&p, g_at2_hi); __half* at2_hi= (__half*)p;
    cudaGetSymbolAddress(&p, g_ff2_hi); __half* ff2_hi= (__half*)p;
    cudaGetSymbolAddress(&p, g_wpatch); __half* wpatch = (__half*)p;
    cudaGetSymbolAddress(&p, g_wqkv);   __half* wqkv   = (__half*)p;
    cudaGetSymbolAddress(&p, g_wproj);  __half* wproj  = (__half*)p;
    cudaGetSymbolAddress(&p, g_wfc1);   __half* wfc1   = (__half*)p;
    cudaGetSymbolAddress(&p, g_wfc2);   __half* wfc2   = (__half*)p;

    cudaFuncSetAttribute(attn_k, cudaFuncAttributeMaxDynamicSharedMemorySize, ATT_SMEM);
    cudaFuncSetAttribute(attn_cls_k, cudaFuncAttributeMaxDynamicSharedMemorySize, ATTC_SMEM);
    cudaFuncSetAttribute(attn_q_k, cudaFuncAttributeMaxDynamicSharedMemorySize, ATTQ_SMEM);
    cudaFuncSetAttribute(gemm_k<2, 0>, cudaFuncAttributeMaxDynamicSharedMemorySize, SMEM2);
    cudaFuncSetAttribute(gemm_k<2, 1>, cudaFuncAttributeMaxDynamicSharedMemorySize, SMEM2);
    cudaFuncSetAttribute(gemm_k<2, 2>, cudaFuncAttributeMaxDynamicSharedMemorySize, SMEM2);
    cudaFuncSetAttribute(gemm_k<1, 0>, cudaFuncAttributeMaxDynamicSharedMemorySize, SMEM1);
    cudaFuncSetAttribute(gemm_k<1, 1>, cudaFuncAttributeMaxDynamicSharedMemorySize, SMEM1);
    cudaFuncSetAttribute(gemm_k<1, 2>, cudaFuncAttributeMaxDynamicSharedMemorySize, SMEM1);

    // fork/join resources (created once, on the un-captured correctness call)
    static cudaStream_t s2 = nullptr;
    static cudaEvent_t evF = nullptr, evJ = nullptr;
    if (!s2) {
        cudaStreamCreateWithFlags(&s2, cudaStreamNonBlocking);
        cudaEventCreateWithFlags(&evF, cudaEventDisableTiming);
        cudaEventCreateWithFlags(&evJ, cudaEventDisableTiming);
    }
    cudaStream_t s0 = 0;

    auto conv = [](const float* in, __half* o, size_t n) {
        size_t n4 = n >> 2;
        conv_h4_k<<<(unsigned)((n4 + 255) / 256), 256>>>((const float4*)in, (__half2*)o, n4);
    };
    conv(qkv_w,  wqkv,  (size_t)L_ * 3 * D_ * D_);
    conv(proj_w, wproj, (size_t)L_ * D_ * D_);
    conv(fc1_w,  wfc1,  (size_t)L_ * FF_ * D_);
    conv(fc2_w,  wfc2,  (size_t)L_ * D_ * FF_);
    {
        size_t n = (size_t)B_ * NP_ * D_ + (size_t)D_ * D_;
        prep_k<<<(unsigned)((n + 255) / 256), 256>>>(inputs, patch_w, p_hi, p_lo, wpatch);
        launch_gemm2(s0, EPI_F32, p_hi, p_lo, wpatch, patch_b,
                     ptmp, nullptr, nullptr, B_ * NP_, D_, D_);
        size_t m = (size_t)B_ * NT_ * D_;
        assemble_k<<<(unsigned)((m + 255) / 256), 256>>>(ptmp, cls_token, pos_embed, x0, xq);
    }

    // ---- fork: prompted layers 0,1 (idx-independent) on s2 ----
    cudaEventRecord(evF, s0);
    cudaStreamWaitEvent(s2, evF, 0);
    for (int l = 0; l < 2; ++l) {
        const int plen = 5, nkl = NT_ + plen, Mk = B_ * nkl;
        ln_k<<<M1, 256, 0, s2>>>(x0, ln1_s + (size_t)l * D_, ln1_b + (size_t)l * D_, h2_hi, h2_lo, D_);
        {
            size_t n = (size_t)Mk * D_;
            concat_k<<<(unsigned)((n + 255) / 256), 256, 0, s2>>>(
                h2_hi, h2_lo, g_prompts, e_prompts, idx,
                xk_hi, xk_lo, xv_hi, xv_lo, nkl, plen, l, 0);
        }
        const size_t wo = (size_t)l * 3 * D_ * D_;
        const float* bl = qkv_b + (size_t)l * 3 * D_;
        launch_gemm2(s2, EPI_F32, h2_hi, h2_lo, wqkv + wo, bl, q2, nullptr, nullptr, M1, D_, D_);
        launch_gemm2(s2, EPI_F32, xk_hi, xk_lo, wqkv + wo + (size_t)D_ * D_,
                     bl + D_, k2, nullptr, nullptr, Mk, D_, D_);
        launch_gemm2(s2, EPI_F32, xv_hi, xv_lo, wqkv + wo + (size_t)2 * D_ * D_,
                     bl + 2 * D_, v2, nullptr, nullptr, Mk, D_, D_);
        attn_k<<<dim3(H_, B_), 256, ATT_SMEM, s2>>>(
            q2, (long long)NT_ * D_, D_,
            k2, (long long)nkl * D_, D_,
            v2, (long long)nkl * D_, D_,
            at2_hi, nkl);
        launch_gemm1(s2, EPI_RES, at2_hi, wproj + (size_t)l * D_ * D_,
                     proj_b + (size_t)l * D_, x0, nullptr, M1, D_, D_);
        ln_k<<<M1, 256, 0, s2>>>(x0, ln2_s + (size_t)l * D_, ln2_b + (size_t)l * D_, h2_hi, h2_lo, D_);
        launch_gemm2(s2, EPI_GELU, h2_hi, h2_lo, wfc1 + (size_t)l * FF_ * D_,
                     fc1_b + (size_t)l * FF_, nullptr, ff2_hi, nullptr, M1, FF_, D_);
        launch_gemm1(s2, EPI_RES, ff2_hi, wfc2 + (size_t)l * D_ * FF_,
                     fc2_b + (size_t)l * D_, x0, nullptr, M1, D_, FF_);
    }
    cudaEventRecord(evJ, s2);

    // ---- query pass on s0 (concurrent with s2) ----
    auto fast_block = [&](int l) {
        ln_k<<<M1, 256, 0, s0>>>(xq, ln1_s + (size_t)l * D_, ln1_b + (size_t)l * D_, h_hi, nullptr, D_);
        launch_gemm1(s0, EPI_F32, h_hi, wqkv + (size_t)l * 3 * D_ * D_,
                     qkv_b + (size_t)l * 3 * D_, qkvf, nullptr, M1, 3 * D_, D_);
        attn_q_k<<<dim3(H_, B_), 256, ATTQ_SMEM, s0>>>(
            qkvf,            (long long)NT_ * 3 * D_, 3 * D_,
            qkvf + D_,       (long long)NT_ * 3 * D_, 3 * D_,
            qkvf + 2 * D_,   (long long)NT_ * 3 * D_, 3 * D_,
            at_hi, NT_);
        launch_gemm1(s0, EPI_RES, at_hi, wproj + (size_t)l * D_ * D_,
                     proj_b + (size_t)l * D_, xq, nullptr, M1, D_, D_);
        ln_k<<<M1, 256, 0, s0>>>(xq, ln2_s + (size_t)l * D_, ln2_b + (size_t)l * D_, h_hi, nullptr, D_);
        launch_gemm1(s0, EPI_GELU, h_hi, wfc1 + (size_t)l * FF_ * D_,
                     fc1_b + (size_t)l * FF_, nullptr, ff_hi, M1, FF_, D_);
        launch_gemm1(s0, EPI_RES, ff_hi, wfc2 + (size_t)l * D_ * FF_,
                     fc2_b + (size_t)l * D_, xq, nullptr, M1, D_, FF_);
    };
    for (int l = 0; l < L_ - 1; ++l) fast_block(l);
    {
        const int l = L_ - 1;
        const long long LDX = (long long)NT_ * D_;
        ln_k<<<M1, 256, 0, s0>>>(xq, ln1_s + (size_t)l * D_, ln1_b + (size_t)l * D_, h_hi, nullptr, D_);
        launch_gemm1(s0, EPI_F32, h_hi, wqkv + (size_t)l * 3 * D_ * D_ + (size_t)D_ * D_,
                     qkv_b + (size_t)l * 3 * D_ + D_, qkvf, nullptr, M1, 2 * D_, D_);
        launch_gemm1(s0, EPI_F32, h_hi, wqkv + (size_t)l * 3 * D_ * D_,
                     qkv_b + (size_t)l * 3 * D_, qf, nullptr, B_, D_, D_, LDX, D_);
        attn_cls_k<<<dim3(H_, B_), 256, ATTC_SMEM, s0>>>(qf, qkvf, at_hi);
        launch_gemm1(s0, EPI_RES, at_hi, wproj + (size_t)l * D_ * D_,
                     proj_b + (size_t)l * D_, xq, nullptr, B_, D_, D_, D_, LDX);
        ln_k<<<B_, 256, 0, s0>>>(xq, ln2_s + (size_t)l * D_, ln2_b + (size_t)l * D_, h_hi, nullptr, LDX);
        launch_gemm1(s0, EPI_GELU, h_hi, wfc1 + (size_t)l * FF_ * D_,
                     fc1_b + (size_t)l * FF_, nullptr, ff_hi, B_, FF_, D_);
        launch_gemm1(s0, EPI_RES, ff_hi, wfc2 + (size_t)l * D_ * FF_,
                     fc2_b + (size_t)l * D_, xq, nullptr, B_, D_, FF_, FF_, LDX);
    }
    select_k<<<B_, 256, 0, s0>>>(xq, key_emb, idx);

    // ---- join ----
    cudaStreamWaitEvent(s0, evJ, 0);

    // ---- serial prompted pass, layers 2..11 on s0 ----
    auto std_block = [&](int l) {
        ln_k<<<M1, 256, 0, s0>>>(x0, ln1_s + (size_t)l * D_, ln1_b + (size_t)l * D_, h_hi, h_lo, D_);
        launch_gemm2(s0, EPI_F32, h_hi, h_lo, wqkv + (size_t)l * 3 * D_ * D_,
                     qkv_b + (size_t)l * 3 * D_, qkvf, nullptr, nullptr, M1, 3 * D_, D_);
        attn_k<<<dim3(H_, B_), 256, ATT_SMEM, s0>>>(
            qkvf,            (long long)NT_ * 3 * D_, 3 * D_,
            qkvf + D_,       (long long)NT_ * 3 * D_, 3 * D_,
            qkvf + 2 * D_,   (long long)NT_ * 3 * D_, 3 * D_,
            at_hi, NT_);
        launch_gemm1(s0, EPI_RES, at_hi, wproj + (size_t)l * D_ * D_,
                     proj_b + (size_t)l * D_, x0, nullptr, M1, D_, D_);
        ln_k<<<M1, 256, 0, s0>>>(x0, ln2_s + (size_t)l * D_, ln2_b + (size_t)l * D_, h_hi, h_lo, D_);
        launch_gemm2(s0, EPI_GELU, h_hi, h_lo, wfc1 + (size_t)l * FF_ * D_,
                     fc1_b + (size_t)l * FF_, nullptr, ff_hi, nullptr, M1, FF_, D_);
        launch_gemm1(s0, EPI_RES, ff_hi, wfc2 + (size_t)l * D_ * FF_,
                     fc2_b + (size_t)l * D_, x0, nullptr, M1, D_, FF_);
    };
    for (int l = 2; l < L_; ++l) {
        const bool isEL = (l >= 2 && l < 5);
        if (!isEL) { std_block(l); continue; }
        const int plen = 20, pi = l - 2;
        const int nkl = NT_ + plen, Mk = B_ * nkl;

        ln_k<<<M1, 256, 0, s0>>>(x0, ln1_s + (size_t)l * D_, ln1_b + (size_t)l * D_, h_hi, h_lo, D_);
        {
            size_t n = (size_t)Mk * D_;
            concat_k<<<(unsigned)((n + 255) / 256), 256, 0, s0>>>(
                h_hi, h_lo, g_prompts, e_prompts, idx,
                xk_hi, xk_lo, xv_hi, xv_lo, nkl, plen, pi, 1);
        }
        const size_t wo = (size_t)l * 3 * D_ * D_;
        const float* bl = qkv_b + (size_t)l * 3 * D_;
        launch_gemm2(s0, EPI_F32, h_hi, h_lo, wqkv + wo, bl, qf, nullptr, nullptr, M1, D_, D_);
        launch_gemm2(s0, EPI_F32, xk_hi, xk_lo, wqkv + wo + (size_t)D_ * D_,
                     bl + D_, kf, nullptr, nullptr, Mk, D_, D_);
        launch_gemm2(s0, EPI_F32, xv_hi, xv_lo, wqkv + wo + (size_t)2 * D_ * D_,
                     bl + 2 * D_, vf, nullptr, nullptr, Mk, D_, D_);
        attn_k<<<dim3(H_, B_), 256, ATT_SMEM, s0>>>(
            qf, (long long)NT_ * D_, D_,
            kf, (long long)nkl * D_, D_,
            vf, (long long)nkl * D_, D_,
            at_hi, nkl);
        launch_gemm1(s0, EPI_RES, at_hi, wproj + (size_t)l * D_ * D_,
                     proj_b + (size_t)l * D_, x0, nullptr, M1, D_, D_);
        ln_k<<<M1, 256, 0, s0>>>(x0, ln2_s + (size_t)l * D_, ln2_b + (size_t)l * D_, h_hi, h_lo, D_);
        launch_gemm2(s0, EPI_GELU, h_hi, h_lo, wfc1 + (size_t)l * FF_ * D_,
                     fc1_b + (size_t)l * FF_, nullptr, ff_hi, nullptr, M1, FF_, D_);
        launch_gemm1(s0, EPI_RES, ff_hi, wfc2 + (size_t)l * D_ * FF_,
                     fc2_b + (size_t)l * D_, x0, nullptr, M1, D_, FF_);
    }

    // 3) head
    head_k<<<B_, 256, 0, s0>>>(x0, norm_s, norm_b, head_w, head_b, mask_param, idx, out);
}